// round 10
// baseline (speedup 1.0000x reference)
#include <cuda_runtime.h>
#include <math.h>
#include <stdint.h>

#define Bsz 2
#define Sl  2048
#define Dm  1024
#define Hn  16
#define HKn 4
#define HDn 64
#define DKn 64
#define DVn 64
#define NCH 32
#define MS  (Bsz*Sl)

__device__ float    g_q[Bsz*Sl*Hn*HDn];        // fp32 q (pre-rope)
__device__ float    g_k[Bsz*Sl*HKn*HDn];       // fp32 k (pre-rope)
__device__ float    g_attn[Bsz*Sl*Hn*HDn];
__device__ float    g_z[Bsz*Sl*DKn];
__device__ float    g_mem[Bsz*Sl*DVn];
__device__ uint32_t g_q2[Bsz*Sl*Hn*HDn];       // tf32, col-permuted, scaled
__device__ uint32_t g_k2[Bsz*Sl*HKn*HDn];      // tf32, col-permuted
__device__ uint32_t g_v2[Bsz*HKn*(Sl/2)*128];  // tf32, sigma-permuted row pairs

__device__ __forceinline__ uint32_t f2tf(float x) {
    uint32_t u; asm("cvt.rna.tf32.f32 %0, %1;" : "=r"(u) : "f"(x)); return u;
}
__device__ __forceinline__ float ex2(float x) {
    float y; asm("ex2.approx.f32 %0, %1;" : "=f"(y) : "f"(x)); return y;
}
__device__ __forceinline__ int colperm(int d) {   // per-8 group: 0,4,1,5,2,6,3,7
    return (d & ~7) | ((d & 3) << 1) | ((d >> 2) & 1);
}
__device__ __forceinline__ int mpair(int m) {     // per-16 group: pair (i, i+8) adjacent
    return (m & ~15) | ((m & 7) << 1) | ((m >> 3) & 1);
}
__device__ __forceinline__ unsigned su32(const void* p) {
    unsigned a;
    asm("{.reg .u64 t; cvta.to.shared.u64 t, %1; cvt.u32.u64 %0, t;}" : "=r"(a) : "l"(p));
    return a;
}
#define CP16(dst, src) asm volatile("cp.async.ca.shared.global [%0], [%1], 16;" :: "r"(dst), "l"(src))
#define CPCOMMIT()     asm volatile("cp.async.commit_group;")
#define CPWAITALL()    asm volatile("cp.async.wait_group 0;")

// mma.sync m16n8k8 tf32
__device__ __forceinline__ void mma8(float d[4], const uint32_t a[4], const uint32_t b[2]) {
    asm volatile(
        "mma.sync.aligned.m16n8k8.row.col.f32.tf32.tf32.f32 "
        "{%0,%1,%2,%3}, {%4,%5,%6,%7}, {%8,%9}, {%0,%1,%2,%3};"
        : "+f"(d[0]), "+f"(d[1]), "+f"(d[2]), "+f"(d[3])
        : "r"(a[0]), "r"(a[1]), "r"(a[2]), "r"(a[3]), "r"(b[0]), "r"(b[1]));
}

// ===========================================================================
// TF32 GEMM core (proj/dual): BM=128, BN=64, BK=16, 256 thr, double-buffered.
// A smem m-pair-permuted (stride 144) so A-fragment loads are LDS.64.
// ===========================================================================
#define AS_STR 144
#define BS_STR 72

__device__ __forceinline__ void g_load(const float* __restrict__ A,
                                       const float* __restrict__ B,
                                       int K, int N, int row0, int col0, int k0,
                                       int tid, float4 ar[2], float4& br) {
    #pragma unroll
    for (int i = 0; i < 2; i++) {
        int vec = tid + i * 256;
        int m = vec >> 2, kq = vec & 3;
        ar[i] = *(const float4*)&A[(size_t)(row0 + m) * K + k0 + kq * 4];
    }
    int kk = tid >> 4, nq = tid & 15;
    br = *(const float4*)&B[(size_t)(k0 + kk) * N + col0 + nq * 4];
}

__device__ __forceinline__ void g_sts(uint32_t* As, uint32_t* Bs, int tid,
                                      const float4 ar[2], const float4& br) {
    #pragma unroll
    for (int i = 0; i < 2; i++) {
        int vec = tid + i * 256;
        int m = vec >> 2, kq = vec & 3;
        int mp = mpair(m);
        As[(kq * 4 + 0) * AS_STR + mp] = f2tf(ar[i].x);
        As[(kq * 4 + 1) * AS_STR + mp] = f2tf(ar[i].y);
        As[(kq * 4 + 2) * AS_STR + mp] = f2tf(ar[i].z);
        As[(kq * 4 + 3) * AS_STR + mp] = f2tf(ar[i].w);
    }
    int kk = tid >> 4, nq = tid & 15;
    uint4 t;
    t.x = f2tf(br.x); t.y = f2tf(br.y); t.z = f2tf(br.z); t.w = f2tf(br.w);
    *(uint4*)&Bs[kk * BS_STR + nq * 4] = t;
}

__device__ __forceinline__ void g_mma(const uint32_t* As, const uint32_t* Bs,
                                      int lane, int wm, int wn, float d[2][4][4]) {
    int g = lane >> 2, c4 = lane & 3;
    #pragma unroll
    for (int ks = 0; ks < 16; ks += 8) {
        int kc = ks + c4;
        uint32_t a[2][4], b[4][2];
        #pragma unroll
        for (int mt = 0; mt < 2; mt++) {
            int off = wm * 32 + mt * 16 + 2 * g;   // m-pairs (r, r+8) adjacent
            uint2 u0 = *(const uint2*)&As[kc * AS_STR + off];
            uint2 u1 = *(const uint2*)&As[(kc + 4) * AS_STR + off];
            a[mt][0] = u0.x; a[mt][1] = u0.y; a[mt][2] = u1.x; a[mt][3] = u1.y;
        }
        #pragma unroll
        for (int nt = 0; nt < 4; nt++) {
            int n = wn * 32 + nt * 8 + g;
            b[nt][0] = Bs[kc * BS_STR + n];
            b[nt][1] = Bs[(kc + 4) * BS_STR + n];
        }
        #pragma unroll
        for (int mt = 0; mt < 2; mt++)
            #pragma unroll
            for (int nt = 0; nt < 4; nt++)
                mma8(d[mt][nt], a[mt], b[nt]);
    }
}

__device__ __forceinline__ void g_epilogue(float d[2][4][4], float* __restrict__ C,
                                           int N, int row0, int col0,
                                           int lane, int wm, int wn) {
    #pragma unroll
    for (int mt = 0; mt < 2; mt++) {
        #pragma unroll
        for (int nt = 0; nt < 4; nt++) {
            int r = row0 + wm * 32 + mt * 16 + (lane >> 2);
            int cc = col0 + wn * 32 + nt * 8 + 2 * (lane & 3);
            *(float2*)&C[(size_t)r * N + cc]       = make_float2(d[mt][nt][0], d[mt][nt][1]);
            *(float2*)&C[(size_t)(r + 8) * N + cc] = make_float2(d[mt][nt][2], d[mt][nt][3]);
        }
    }
}

// V store into sigma-paired tf32 layout:
// V'[(b,kh)][ (s>>3)*4 + ((s>>1)&3) ][ 2d + (s&1) ]
// pairs original rows (2i, 2i+1) -> B-frag rows (k', k'+4) under sigma.
__device__ __forceinline__ void v2store(uint32_t* __restrict__ v2, int r, int cc, float val) {
    int s = r & (Sl - 1), b = r >> 11;
    int kh = cc >> 6, d = cc & 63;
    size_t idx = ((size_t)(b * HKn + kh) * (Sl / 2) + (s >> 3) * 4 + ((s >> 1) & 3)) * 128
               + 2 * d + (s & 1);
    v2[idx] = f2tf(val);
}

// ---------------------------------------------------------------------------
// Fused projection GEMM: x @ {Wq|Wk|Wv|Wmemin}. grid=(25,32), block=256.
// ---------------------------------------------------------------------------
__global__ __launch_bounds__(256)
void proj_kernel(const float* __restrict__ x,
                 const float* __restrict__ Wq, const float* __restrict__ Wk,
                 const float* __restrict__ Wv, const float* __restrict__ Wz,
                 float* __restrict__ q, float* __restrict__ kout,
                 uint32_t* __restrict__ v2, float* __restrict__ z) {
    __shared__ uint32_t As[2][16 * AS_STR];
    __shared__ uint32_t Bs[2][16 * BS_STR];
    int tid = threadIdx.x;
    int lane = tid & 31, warp = tid >> 5;
    int wm = warp >> 1, wn = warp & 1;
    int ct = blockIdx.x;
    int row0 = blockIdx.y * 128;
    const float* B; float* C; int N, col0; bool isV = false;
    if (ct < 16)      { B = Wq; C = q;    N = 1024; col0 = ct * 64; }
    else if (ct < 20) { B = Wk; C = kout; N = 256;  col0 = (ct - 16) * 64; }
    else if (ct < 24) { B = Wv; C = nullptr; N = 256; col0 = (ct - 20) * 64; isV = true; }
    else              { B = Wz; C = z;    N = 64;   col0 = 0; }

    float d[2][4][4] = {};
    float4 ar[2]; float4 br;
    g_load(x, B, 1024, N, row0, col0, 0, tid, ar, br);
    g_sts(As[0], Bs[0], tid, ar, br);
    __syncthreads();
    for (int k0 = 0; k0 < 1024; k0 += 16) {
        int cur = (k0 >> 4) & 1;
        if (k0 + 16 < 1024) g_load(x, B, 1024, N, row0, col0, k0 + 16, tid, ar, br);
        g_mma(As[cur], Bs[cur], lane, wm, wn, d);
        if (k0 + 16 < 1024) g_sts(As[cur ^ 1], Bs[cur ^ 1], tid, ar, br);
        __syncthreads();
    }
    if (!isV) {
        g_epilogue(d, C, N, row0, col0, lane, wm, wn);
    } else {
        #pragma unroll
        for (int mt = 0; mt < 2; mt++) {
            #pragma unroll
            for (int nt = 0; nt < 4; nt++) {
                int r = row0 + wm * 32 + mt * 16 + (lane >> 2);
                int cc = col0 + wn * 32 + nt * 8 + 2 * (lane & 3);
                v2store(v2, r,     cc,     d[mt][nt][0]);
                v2store(v2, r,     cc + 1, d[mt][nt][1]);
                v2store(v2, r + 8, cc,     d[mt][nt][2]);
                v2store(v2, r + 8, cc + 1, d[mt][nt][3]);
            }
        }
    }
}

// ---------------------------------------------------------------------------
// Dual GEMM: C = A1@B1 + A2@B2. grid=(16,32), block=256.
// ---------------------------------------------------------------------------
__global__ __launch_bounds__(256)
void dual_gemm_kernel(const float* __restrict__ A1, const float* __restrict__ B1, int K1,
                      const float* __restrict__ A2, const float* __restrict__ B2, int K2,
                      float* __restrict__ C, int N) {
    __shared__ uint32_t As[2][16 * AS_STR];
    __shared__ uint32_t Bs[2][16 * BS_STR];
    int tid = threadIdx.x;
    int lane = tid & 31, warp = tid >> 5;
    int wm = warp >> 1, wn = warp & 1;
    int row0 = blockIdx.y * 128, col0 = blockIdx.x * 64;
    float d[2][4][4] = {};
    float4 ar[2]; float4 br;
    #pragma unroll
    for (int ph = 0; ph < 2; ph++) {
        const float* A = ph ? A2 : A1;
        const float* B = ph ? B2 : B1;
        int K = ph ? K2 : K1;
        g_load(A, B, K, N, row0, col0, 0, tid, ar, br);
        g_sts(As[0], Bs[0], tid, ar, br);
        __syncthreads();
        for (int k0 = 0; k0 < K; k0 += 16) {
            int cur = (k0 >> 4) & 1;
            if (k0 + 16 < K) g_load(A, B, K, N, row0, col0, k0 + 16, tid, ar, br);
            g_mma(As[cur], Bs[cur], lane, wm, wn, d);
            if (k0 + 16 < K) g_sts(As[cur ^ 1], Bs[cur ^ 1], tid, ar, br);
            __syncthreads();
        }
    }
    g_epilogue(d, C, N, row0, col0, lane, wm, wn);
}

// ---------------------------------------------------------------------------
// RoPE + tf32 convert + column permute. Q pre-scaled into log2 domain.
// ---------------------------------------------------------------------------
#define QSCALE 0.18033688f   // 0.125 * log2(e)

__global__ void rope_kernel(const float* __restrict__ qp, const float* __restrict__ kp,
                            uint32_t* __restrict__ q2, uint32_t* __restrict__ k2) {
    int idx = blockIdx.x * blockDim.x + threadIdx.x;
    const int qtot = Bsz * Sl * Hn * 32;
    const int ktot = Bsz * Sl * HKn * 32;
    const float* src; uint32_t* dst; int nheads; bool isq;
    if (idx < qtot) { src = qp; dst = q2; nheads = Hn; isq = true; }
    else { idx -= qtot; if (idx >= ktot) return; src = kp; dst = k2; nheads = HKn; isq = false; }
    int j = idx & 31;
    int h = (idx >> 5) % nheads;
    int s = ((idx >> 5) / nheads) % Sl;
    int b = idx / (32 * nheads * Sl);
    float inv = powf(500000.0f, -(float)(2 * j) / 64.0f);
    float ang = (float)s * inv;
    float c, sn;
    __sincosf(ang, &sn, &c);
    size_t base = ((size_t)(b * Sl + s) * nheads + h) * 64;
    float u1 = src[base + j], u2 = src[base + j + 32];
    float r1 = u1 * c - u2 * sn;
    float r2 = u2 * c + u1 * sn;
    if (isq) { r1 *= QSCALE; r2 *= QSCALE; }
    dst[base + colperm(j)]      = f2tf(r1);
    dst[base + colperm(j + 32)] = f2tf(r2);
}

// ---------------------------------------------------------------------------
// TF32 flash attention v4: 128 threads (4 warps), warp tile = 32 q-rows,
// full 64-col kv tile. NEW: V rows sigma-permuted in global so the QK
// C-fragment is the PV A-fragment by pure register reorder — zero shfl.
// ---------------------------------------------------------------------------
#define QST 72
#define KST 72
#define VST 144
#define ATTN_WORDS (128*QST + 2*64*KST + 2*32*VST)
#define ATTN_BYTES (ATTN_WORDS * 4)

__global__ __launch_bounds__(128, 2)
void attn_kernel(const uint32_t* __restrict__ q2, const uint32_t* __restrict__ k2,
                 const uint32_t* __restrict__ v2, float* __restrict__ o) {
    extern __shared__ uint32_t smu[];
    uint32_t* qs = smu;                 // [r:128][d':64] stride 72
    uint32_t* ks = qs + 128 * QST;      // 2 x [c:64][d':64] stride 72
    uint32_t* vs = ks + 2 * 64 * KST;   // 2 x [row':32][2d+slot:128] stride 144

    int qt = (int)gridDim.x - 1 - (int)blockIdx.x;   // longest tiles first
    int bh = blockIdx.y;
    int b = bh >> 4, h = bh & 15, kh = h >> 2;
    int tid = threadIdx.x;
    int lane = tid & 31, w = tid >> 5;
    int g = lane >> 2, c4 = lane & 3;
    int row_base = w * 32 + g;          // warp covers q-rows [w*32, w*32+32)

    size_t qbase = ((size_t)(b * Sl + qt * 128) * Hn + h) * 64;
    size_t kvbase = ((size_t)(b * Sl) * HKn + kh) * 64;
    size_t v2base0 = (size_t)(b * HKn + kh) * (Sl / 2) * 128;
    int ktmax = 2 * qt + 1;

    // ---- prologue: cp.async Q tile + K0 + V0 ----
    {
        unsigned qd = su32(qs);
        #pragma unroll
        for (int i = 0; i < 16; i++) {
            int vec = tid + i * 128;             // 128 rows x 16 chunks
            int r = vec >> 4, ch = vec & 15;
            CP16(qd + (unsigned)((r * QST + ch * 4) * 4),
                 &q2[qbase + (size_t)r * Hn * 64 + ch * 4]);
        }
        unsigned kd = su32(ks), vd = su32(vs);
        #pragma unroll
        for (int i = 0; i < 8; i++) {
            int vec = tid + i * 128;
            int c = vec >> 4, dq = vec & 15;
            CP16(kd + (unsigned)((c * KST + dq * 4) * 4),
                 &k2[kvbase + (size_t)c * HKn * 64 + dq * 4]);
            int row = vec >> 5, ch = vec & 31;
            CP16(vd + (unsigned)((row * VST + ch * 4) * 4),
                 &v2[v2base0 + (size_t)row * 128 + ch * 4]);
        }
        CPCOMMIT();
    }

    float m[2][2], l[2][2];
    #pragma unroll
    for (int mt = 0; mt < 2; mt++) {
        m[mt][0] = -1e30f; m[mt][1] = -1e30f;
        l[mt][0] = 0.f;    l[mt][1] = 0.f;
    }
    float accO[2][8][4] = {};
    CPWAITALL();
    __syncthreads();

    for (int kt = 0; kt <= ktmax; kt++) {
        const uint32_t* kb = ks + (kt & 1) * 64 * KST;
        const uint32_t* vb = vs + (kt & 1) * 32 * VST;

        if (kt < ktmax) {
            unsigned kd = su32(ks + ((kt + 1) & 1) * 64 * KST);
            unsigned vd = su32(vs + ((kt + 1) & 1) * 32 * VST);
            size_t kbase = kvbase + (size_t)(kt + 1) * 64 * HKn * 64;
            size_t vbase = v2base0 + (size_t)(kt + 1) * 32 * 128;
            #pragma unroll
            for (int i = 0; i < 8; i++) {
                int vec = tid + i * 128;
                int c = vec >> 4, dq = vec & 15;
                CP16(kd + (unsigned)((c * KST + dq * 4) * 4),
                     &k2[kbase + (size_t)c * HKn * 64 + dq * 4]);
                int row = vec >> 5, ch = vec & 31;
                CP16(vd + (unsigned)((row * VST + ch * 4) * 4),
                     &v2[vbase + (size_t)row * 128 + ch * 4]);
            }
            CPCOMMIT();
        }

        // ---- QK^T: 32 q-rows x 64 kv-cols per warp ----
        float sc[2][8][4] = {};
        #pragma unroll
        for (int t8 = 0; t8 < 8; t8++) {
            int pc = t8 * 8 + 2 * c4;     // permuted: (kc, kc+4) adjacent
            uint32_t a[2][4];
            #pragma unroll
            for (int mt = 0; mt < 2; mt++) {
                uint2 ua0 = *(const uint2*)&qs[(row_base + mt * 16) * QST + pc];
                uint2 ua1 = *(const uint2*)&qs[(row_base + mt * 16 + 8) * QST + pc];
                a[mt][0] = ua0.x; a[mt][1] = ua1.x; a[mt][2] = ua0.y; a[mt][3] = ua1.y;
            }
            #pragma unroll
            for (int nt = 0; nt < 8; nt++) {
                int n = nt * 8 + g;
                uint2 ub = *(const uint2*)&kb[n * KST + pc];
                uint32_t bb[2] = { ub.x, ub.y };
                mma8(sc[0][nt], a[0], bb);
                mma8(sc[1][nt], a[1], bb);
            }
        }

        // ---- causal mask ----
        if (kt >= 2 * qt) {
            #pragma unroll
            for (int mt = 0; mt < 2; mt++) {
                int rg0 = qt * 128 + row_base + mt * 16, rg1 = rg0 + 8;
                #pragma unroll
                for (int nt = 0; nt < 8; nt++) {
                    int cg = kt * 64 + nt * 8 + 2 * c4;
                    if (cg > rg0)     sc[mt][nt][0] = -1e30f;
                    if (cg + 1 > rg0) sc[mt][nt][1] = -1e30f;
                    if (cg > rg1)     sc[mt][nt][2] = -1e30f;
                    if (cg + 1 > rg1) sc[mt][nt][3] = -1e30f;
                }
            }
        }

        // ---- online softmax (log2 domain, bare EX2) ----
        #pragma unroll
        for (int mt = 0; mt < 2; mt++) {
            float mx0 = m[mt][0], mx1 = m[mt][1];
            #pragma unroll
            for (int nt = 0; nt < 8; nt++) {
                mx0 = fmaxf(mx0, fmaxf(sc[mt][nt][0], sc[mt][nt][1]));
                mx1 = fmaxf(mx1, fmaxf(sc[mt][nt][2], sc[mt][nt][3]));
            }
            mx0 = fmaxf(mx0, __shfl_xor_sync(0xffffffffu, mx0, 1));
            mx0 = fmaxf(mx0, __shfl_xor_sync(0xffffffffu, mx0, 2));
            mx1 = fmaxf(mx1, __shfl_xor_sync(0xffffffffu, mx1, 1));
            mx1 = fmaxf(mx1, __shfl_xor_sync(0xffffffffu, mx1, 2));
            float f0 = ex2(m[mt][0] - mx0), f1 = ex2(m[mt][1] - mx1);
            m[mt][0] = mx0; m[mt][1] = mx1;
            float sum0 = 0.f, sum1 = 0.f;
            #pragma unroll
            for (int nt = 0; nt < 8; nt++) {
                sc[mt][nt][0] = ex2(sc[mt][nt][0] - mx0); sum0 += sc[mt][nt][0];
                sc[mt][nt][1] = ex2(sc[mt][nt][1] - mx0); sum0 += sc[mt][nt][1];
                sc[mt][nt][2] = ex2(sc[mt][nt][2] - mx1); sum1 += sc[mt][nt][2];
                sc[mt][nt][3] = ex2(sc[mt][nt][3] - mx1); sum1 += sc[mt][nt][3];
            }
            sum0 += __shfl_xor_sync(0xffffffffu, sum0, 1);
            sum0 += __shfl_xor_sync(0xffffffffu, sum0, 2);
            sum1 += __shfl_xor_sync(0xffffffffu, sum1, 1);
            sum1 += __shfl_xor_sync(0xffffffffu, sum1, 2);
            l[mt][0] = l[mt][0] * f0 + sum0;
            l[mt][1] = l[mt][1] * f1 + sum1;
            #pragma unroll
            for (int nt = 0; nt < 8; nt++) {
                accO[mt][nt][0] *= f0; accO[mt][nt][1] *= f0;
                accO[mt][nt][2] *= f1; accO[mt][nt][3] *= f1;
            }
        }

        // ---- P @ V: C-fragment IS the A-fragment under sigma (no shfl) ----
        #pragma unroll
        for (int t = 0; t < 8; t++) {
            uint32_t a[2][4];
            #pragma unroll
            for (int mt = 0; mt < 2; mt++) {
                a[mt][0] = f2tf(sc[mt][t][0]);   // (row g,   k'=c4)   = P[g][2c4]
                a[mt][1] = f2tf(sc[mt][t][2]);   // (row g+8, k'=c4)   = P[g+8][2c4]
                a[mt][2] = f2tf(sc[mt][t][1]);   // (row g,   k'=c4+4) = P[g][2c4+1]
                a[mt][3] = f2tf(sc[mt][t][3]);   // (row g+8, k'=c4+4) = P[g+8][2c4+1]
            }
            int vrow = t * 4 + c4;   // V' row pair = original rows (8t+2c4, 8t+2c4+1)
            #pragma unroll
            for (int nt = 0; nt < 8; nt++) {
                int dcol = nt * 8 + g;
                uint2 ub = *(const uint2*)&vb[vrow * VST + 2 * dcol];
                uint32_t bb[2] = { ub.x, ub.y };
                mma8(accO[0][nt], a[0], bb);
                mma8(accO[1][nt], a[1], bb);
            }
        }

        if (kt < ktmax) CPWAITALL();
        __syncthreads();
    }

    // ---- epilogue ----
    #pragma unroll
    for (int mt = 0; mt < 2; mt++) {
        float il0 = 1.f / l[mt][0], il1 = 1.f / l[mt][1];
        size_t ob0 = ((size_t)(b * Sl + qt * 128 + row_base + mt * 16) * Hn + h) * 64;
        size_t ob1 = ((size_t)(b * Sl + qt * 128 + row_base + mt * 16 + 8) * Hn + h) * 64;
        #pragma unroll
        for (int nt = 0; nt < 8; nt++) {
            int dcol = nt * 8 + 2 * c4;
            *(float2*)&o[ob0 + dcol] = make_float2(accO[mt][nt][0] * il0, accO[mt][nt][1] * il0);
            *(float2*)&o[ob1 + dcol] = make_float2(accO[mt][nt][2] * il1, accO[mt][nt][3] * il1);
        }
    }
}

// ---------------------------------------------------------------------------
// Chunked delta-rule memory scan (side stream).
// ---------------------------------------------------------------------------
__global__ __launch_bounds__(256)
void memscan_kernel(const float* __restrict__ z,
                    const float* __restrict__ M_init,
                    const float* __restrict__ w_eta, const float* __restrict__ b_eta,
                    const float* __restrict__ w_alpha, const float* __restrict__ b_alpha,
                    const float* __restrict__ w_gate, const float* __restrict__ b_gate,
                    float* __restrict__ mem_out) {
    __shared__ float Ms[64][65];
    __shared__ float chs[64][65];
    __shared__ float red2[16][64];
    __shared__ float se[64], sa[64], sg[64], nrm[64];
    __shared__ float kmean[64], vt[64], diffv[64];
    __shared__ float swe[64], swa[64], swg[64];
    __shared__ float redw[8];
    __shared__ float sc_eta, sc_alpha, sc_gate, sc_scale;

    int b = blockIdx.x;
    int tid = threadIdx.x;
    int tx = tid & 15, ty = tid >> 4;
    int lane = tid & 31, warp = tid >> 5;
    int tok = tid >> 2, part = tid & 3;
    float be = b_eta[0], ba = b_alpha[0], bg = b_gate[0];

    if (tid < 64) { swe[tid] = w_eta[tid]; swa[tid] = w_alpha[tid]; swg[tid] = w_gate[tid]; }
    #pragma unroll
    for (int i = 0; i < 16; i++) {
        int idx = tid + i * 256;
        Ms[idx >> 6][idx & 63] = M_init[idx];
    }
    __syncthreads();

    for (int c = 0; c < NCH; c++) {
        #pragma unroll
        for (int i = 0; i < 16; i++) {
            int idx = tid + i * 256;
            chs[idx >> 6][idx & 63] = z[((size_t)b * Sl + c * 64 + (idx >> 6)) * 64 + (idx & 63)];
        }
        __syncthreads();

        float o4[4][4] = {};
        #pragma unroll
        for (int d = 0; d < 64; d++) {
            float a0 = chs[ty*4+0][d], a1 = chs[ty*4+1][d];
            float a2 = chs[ty*4+2][d], a3 = chs[ty*4+3][d];
            float m0 = Ms[tx*4+0][d], m1 = Ms[tx*4+1][d];
            float m2 = Ms[tx*4+2][d], m3 = Ms[tx*4+3][d];
            o4[0][0] += a0*m0; o4[0][1] += a0*m1; o4[0][2] += a0*m2; o4[0][3] += a0*m3;
            o4[1][0] += a1*m0; o4[1][1] += a1*m1; o4[1][2] += a1*m2; o4[1][3] += a1*m3;
            o4[2][0] += a2*m0; o4[2][1] += a2*m1; o4[2][2] += a2*m2; o4[2][3] += a2*m3;
            o4[3][0] += a3*m0; o4[3][1] += a3*m1; o4[3][2] += a3*m2; o4[3][3] += a3*m3;
        }
        #pragma unroll
        for (int i = 0; i < 4; i++)
            #pragma unroll
            for (int j = 0; j < 4; j++)
                mem_out[((size_t)b * Sl + c * 64 + ty * 4 + i) * 64 + tx * 4 + j] = o4[i][j];
        #pragma unroll
        for (int j = 0; j < 4; j++)
            red2[ty][tx * 4 + j] = o4[0][j] + o4[1][j] + o4[2][j] + o4[3][j];
        __syncthreads();

        {
            float de = 0.f, da = 0.f, dg = 0.f, nn = 0.f;
            int d0 = part * 16;
            #pragma unroll
            for (int dd = 0; dd < 16; dd++) {
                float xv = chs[tok][d0 + dd];
                de = fmaf(xv, swe[d0 + dd], de);
                da = fmaf(xv, swa[d0 + dd], da);
                dg = fmaf(xv, swg[d0 + dd], dg);
                nn = fmaf(xv, xv, nn);
            }
            de += __shfl_xor_sync(0xffffffffu, de, 1); de += __shfl_xor_sync(0xffffffffu, de, 2);
            da += __shfl_xor_sync(0xffffffffu, da, 1); da += __shfl_xor_sync(0xffffffffu, da, 2);
            dg += __shfl_xor_sync(0xffffffffu, dg, 1); dg += __shfl_xor_sync(0xffffffffu, dg, 2);
            nn += __shfl_xor_sync(0xffffffffu, nn, 1); nn += __shfl_xor_sync(0xffffffffu, nn, 2);
            if (part == 0) {
                se[tok] = 0.2f / (1.f + __expf(-(de + be)));
                sa[tok] = 0.5f + 0.5f / (1.f + __expf(-(da + ba)));
                sg[tok] = 1.f / (1.f + __expf(-(dg + bg)));
                nrm[tok] = fmaxf(sqrtf(nn), 1e-6f);
            }
        }
        __syncthreads();

        {
            float s = 0.f, s2 = 0.f;
            #pragma unroll
            for (int t = 0; t < 16; t++) s += chs[part * 16 + t][tok] / nrm[part * 16 + t];
            #pragma unroll
            for (int yy = 0; yy < 4; yy++) s2 += red2[part * 4 + yy][tok];
            s  += __shfl_xor_sync(0xffffffffu, s, 1);  s  += __shfl_xor_sync(0xffffffffu, s, 2);
            s2 += __shfl_xor_sync(0xffffffffu, s2, 1); s2 += __shfl_xor_sync(0xffffffffu, s2, 2);
            if (part == 0) { kmean[tok] = s * (1.f / 64.f); vt[tok] = s2 * (1.f / 64.f); }
        }
        __syncthreads();

        if (tid < 32) {
            float e = se[tid] + se[tid + 32];
            float a = sa[tid] + sa[tid + 32];
            float gg = sg[tid] + sg[tid + 32];
            #pragma unroll
            for (int st = 16; st; st >>= 1) {
                e  += __shfl_xor_sync(0xffffffffu, e, st);
                a  += __shfl_xor_sync(0xffffffffu, a, st);
                gg += __shfl_xor_sync(0xffffffffu, gg, st);
            }
            if (tid == 0) {
                sc_eta = e * (1.f / 64.f);
                sc_alpha = a * (1.f / 64.f);
                sc_gate = gg * (1.f / 64.f);
            }
        }
        {
            float s = 0.f;
            int d0 = part * 16;
            #pragma unroll
            for (int dd = 0; dd < 16; dd++)
                s = fmaf(Ms[tok][d0 + dd], kmean[d0 + dd], s);
            s += __shfl_xor_sync(0xffffffffu, s, 1);
            s += __shfl_xor_sync(0xffffffffu, s, 2);
            if (part == 0) diffv[tok] = vt[tok] - s;
        }
        __syncthreads();

        float eg = sc_eta * sc_gate, al = sc_alpha;
        float ss2 = 0.f;
        #pragma unroll
        for (int i = 0; i < 16; i++) {
            int idx = tid + i * 256;
            int vv = idx >> 6, d = idx & 63;
            float mn = al * Ms[vv][d] + eg * diffv[vv] * kmean[d];
            Ms[vv][d] = mn;
            ss2 = fmaf(mn, mn, ss2);
        }
        #pragma unroll
        for (int st = 16; st; st >>= 1) ss2 += __shfl_xor_sync(0xffffffffu, ss2, st);
        if (lane == 0) redw[warp] = ss2;
        __syncthreads();
        if (tid == 0) {
            float fro = sqrtf(redw[0] + redw[1] + redw[2] + redw[3] +
                              redw[4] + redw[5] + redw[6] + redw[7]);
            sc_scale = fminf(1.f, 30.f / fmaxf(fro, 1e-6f));
        }
        __syncthreads();
        #pragma unroll
        for (int i = 0; i < 16; i++) {
            int idx = tid + i * 256;
            Ms[idx >> 6][idx & 63] *= sc_scale;
        }
        __syncthreads();
    }
}

// ---------------------------------------------------------------------------
extern "C" void kernel_launch(void* const* d_in, const int* in_sizes, int n_in,
                              void* d_out, int out_size) {
    const float* x       = (const float*)d_in[0];
    const float* Wq      = (const float*)d_in[1];
    const float* Wk      = (const float*)d_in[2];
    const float* Wv      = (const float*)d_in[3];
    const float* Wo      = (const float*)d_in[4];
    const float* Wmemin  = (const float*)d_in[5];
    const float* Wmemout = (const float*)d_in[6];
    const float* M_init  = (const float*)d_in[7];
    const float* w_eta   = (const float*)d_in[8];
    const float* b_eta   = (const float*)d_in[9];
    const float* w_alpha = (const float*)d_in[10];
    const float* b_alpha = (const float*)d_in[11];
    const float* w_gate  = (const float*)d_in[12];
    const float* b_gate  = (const float*)d_in[13];
    float* out = (float*)d_out;

    float *q, *k, *attn, *z, *mem;
    uint32_t *q2, *k2, *v2;
    cudaGetSymbolAddress((void**)&q, g_q);
    cudaGetSymbolAddress((void**)&k, g_k);
    cudaGetSymbolAddress((void**)&attn, g_attn);
    cudaGetSymbolAddress((void**)&z, g_z);
    cudaGetSymbolAddress((void**)&mem, g_mem);
    cudaGetSymbolAddress((void**)&q2, g_q2);
    cudaGetSymbolAddress((void**)&k2, g_k2);
    cudaGetSymbolAddress((void**)&v2, g_v2);

    static cudaStream_t s2 = nullptr;
    static cudaEvent_t evZ = nullptr, evM = nullptr;
    static int inited = 0;
    if (!inited) {
        cudaStreamCreateWithFlags(&s2, cudaStreamNonBlocking);
        cudaEventCreateWithFlags(&evZ, cudaEventDisableTiming);
        cudaEventCreateWithFlags(&evM, cudaEventDisableTiming);
        cudaFuncSetAttribute(attn_kernel,
                             cudaFuncAttributeMaxDynamicSharedMemorySize, ATTN_BYTES);
        inited = 1;
    }

    // Fused projections (q, k fp32; v tf32 sigma-paired; z fp32)
    proj_kernel<<<dim3(25, 32), 256>>>(x, Wq, Wk, Wv, Wmemin, q, k, v2, z);

    // Fork serial memscan onto side stream (depends on z)
    cudaEventRecord(evZ, 0);
    cudaStreamWaitEvent(s2, evZ, 0);
    memscan_kernel<<<Bsz, 256, 0, s2>>>(z, M_init, w_eta, b_eta, w_alpha, b_alpha,
                                        w_gate, b_gate, mem);
    cudaEventRecord(evM, s2);

    // RoPE + tf32 convert + permute (q scaled)
    {
        int total = Bsz * Sl * (Hn + HKn) * 32;
        rope_kernel<<<(total + 255) / 256, 256>>>(q, k, q2, k2);
    }

    // Attention
    attn_kernel<<<dim3(Sl/128, Bsz*Hn), 128, ATTN_BYTES>>>(q2, k2, v2, attn);

    // Join memscan, then fused output GEMM
    cudaStreamWaitEvent((cudaStream_t)0, evM, 0);
    dual_gemm_kernel<<<dim3(16, 32), 256>>>(attn, Wo, Hn*HDn,
                                            mem, Wmemout, DVn, out, Dm);
}

// round 11
// speedup vs baseline: 1.0834x; 1.0834x over previous
#include <cuda_runtime.h>
#include <math.h>
#include <stdint.h>

#define Bsz 2
#define Sl  2048
#define Dm  1024
#define Hn  16
#define HKn 4
#define HDn 64
#define DKn 64
#define DVn 64
#define NCH 32
#define MS  (Bsz*Sl)

__device__ float    g_q[Bsz*Sl*Hn*HDn];        // fp32 q (pre-rope)
__device__ float    g_k[Bsz*Sl*HKn*HDn];       // fp32 k (pre-rope)
__device__ float    g_attn[Bsz*Sl*Hn*HDn];
__device__ float    g_z[Bsz*Sl*DKn];
__device__ float    g_mem[Bsz*Sl*DVn];
__device__ uint32_t g_q2[Bsz*Sl*Hn*HDn];       // tf32, col-permuted, scaled
__device__ uint32_t g_k2[Bsz*Sl*HKn*HDn];      // tf32, col-permuted
__device__ uint32_t g_v2[Bsz*HKn*(Sl/2)*128];  // tf32, sigma-permuted row pairs

__device__ __forceinline__ uint32_t f2tf(float x) {
    uint32_t u; asm("cvt.rna.tf32.f32 %0, %1;" : "=r"(u) : "f"(x)); return u;
}
__device__ __forceinline__ float ex2(float x) {
    float y; asm("ex2.approx.f32 %0, %1;" : "=f"(y) : "f"(x)); return y;
}
__device__ __forceinline__ int colperm(int d) {   // per-8 group: 0,4,1,5,2,6,3,7
    return (d & ~7) | ((d & 3) << 1) | ((d >> 2) & 1);
}
__device__ __forceinline__ unsigned su32(const void* p) {
    unsigned a;
    asm("{.reg .u64 t; cvta.to.shared.u64 t, %1; cvt.u32.u64 %0, t;}" : "=r"(a) : "l"(p));
    return a;
}
#define CP16(dst, src) asm volatile("cp.async.ca.shared.global [%0], [%1], 16;" :: "r"(dst), "l"(src))
#define CPCOMMIT()     asm volatile("cp.async.commit_group;")
#define CPWAITALL()    asm volatile("cp.async.wait_group 0;")

// mma.sync m16n8k8 tf32
__device__ __forceinline__ void mma8(float d[4], const uint32_t a[4], const uint32_t b[2]) {
    asm volatile(
        "mma.sync.aligned.m16n8k8.row.col.f32.tf32.tf32.f32 "
        "{%0,%1,%2,%3}, {%4,%5,%6,%7}, {%8,%9}, {%0,%1,%2,%3};"
        : "+f"(d[0]), "+f"(d[1]), "+f"(d[2]), "+f"(d[3])
        : "r"(a[0]), "r"(a[1]), "r"(a[2]), "r"(a[3]), "r"(b[0]), "r"(b[1]));
}

// ===========================================================================
// TF32 GEMM core (proj/dual): BM=128, BN=64, BK=16, 256 thr, double-buffered.
// (R9-proven form: AS_STR=136, scalar A-fragment loads, conflict-free.)
// ===========================================================================
#define AS_STR 136
#define BS_STR 72

__device__ __forceinline__ void g_load(const float* __restrict__ A,
                                       const float* __restrict__ B,
                                       int K, int N, int row0, int col0, int k0,
                                       int tid, float4 ar[2], float4& br) {
    #pragma unroll
    for (int i = 0; i < 2; i++) {
        int vec = tid + i * 256;
        int m = vec >> 2, kq = vec & 3;
        ar[i] = *(const float4*)&A[(size_t)(row0 + m) * K + k0 + kq * 4];
    }
    int kk = tid >> 4, nq = tid & 15;
    br = *(const float4*)&B[(size_t)(k0 + kk) * N + col0 + nq * 4];
}

__device__ __forceinline__ void g_sts(uint32_t* As, uint32_t* Bs, int tid,
                                      const float4 ar[2], const float4& br) {
    #pragma unroll
    for (int i = 0; i < 2; i++) {
        int vec = tid + i * 256;
        int m = vec >> 2, kq = vec & 3;
        As[(kq * 4 + 0) * AS_STR + m] = f2tf(ar[i].x);
        As[(kq * 4 + 1) * AS_STR + m] = f2tf(ar[i].y);
        As[(kq * 4 + 2) * AS_STR + m] = f2tf(ar[i].z);
        As[(kq * 4 + 3) * AS_STR + m] = f2tf(ar[i].w);
    }
    int kk = tid >> 4, nq = tid & 15;
    uint4 t;
    t.x = f2tf(br.x); t.y = f2tf(br.y); t.z = f2tf(br.z); t.w = f2tf(br.w);
    *(uint4*)&Bs[kk * BS_STR + nq * 4] = t;
}

__device__ __forceinline__ void g_mma(const uint32_t* As, const uint32_t* Bs,
                                      int lane, int wm, int wn, float d[2][4][4]) {
    #pragma unroll
    for (int ks = 0; ks < 16; ks += 8) {
        int kc = ks + (lane & 3);
        uint32_t a[2][4], b[4][2];
        #pragma unroll
        for (int mt = 0; mt < 2; mt++) {
            int r = wm * 32 + mt * 16 + (lane >> 2);
            a[mt][0] = As[kc * AS_STR + r];
            a[mt][1] = As[kc * AS_STR + r + 8];
            a[mt][2] = As[(kc + 4) * AS_STR + r];
            a[mt][3] = As[(kc + 4) * AS_STR + r + 8];
        }
        #pragma unroll
        for (int nt = 0; nt < 4; nt++) {
            int n = wn * 32 + nt * 8 + (lane >> 2);
            b[nt][0] = Bs[kc * BS_STR + n];
            b[nt][1] = Bs[(kc + 4) * BS_STR + n];
        }
        #pragma unroll
        for (int mt = 0; mt < 2; mt++)
            #pragma unroll
            for (int nt = 0; nt < 4; nt++)
                mma8(d[mt][nt], a[mt], b[nt]);
    }
}

__device__ __forceinline__ void g_epilogue(float d[2][4][4], float* __restrict__ C,
                                           int N, int row0, int col0,
                                           int lane, int wm, int wn) {
    #pragma unroll
    for (int mt = 0; mt < 2; mt++) {
        #pragma unroll
        for (int nt = 0; nt < 4; nt++) {
            int r = row0 + wm * 32 + mt * 16 + (lane >> 2);
            int cc = col0 + wn * 32 + nt * 8 + 2 * (lane & 3);
            *(float2*)&C[(size_t)r * N + cc]       = make_float2(d[mt][nt][0], d[mt][nt][1]);
            *(float2*)&C[(size_t)(r + 8) * N + cc] = make_float2(d[mt][nt][2], d[mt][nt][3]);
        }
    }
}

// V store into sigma-paired tf32 layout:
// V'[(b,kh)][ (s>>3)*4 + ((s>>1)&3) ][ 2d + (s&1) ]
// pairs original rows (2i, 2i+1) -> B-frag rows (k', k'+4) under sigma.
__device__ __forceinline__ void v2store(uint32_t* __restrict__ v2, int r, int cc, float val) {
    int s = r & (Sl - 1), b = r >> 11;
    int kh = cc >> 6, d = cc & 63;
    size_t idx = ((size_t)(b * HKn + kh) * (Sl / 2) + (s >> 3) * 4 + ((s >> 1) & 3)) * 128
               + 2 * d + (s & 1);
    v2[idx] = f2tf(val);
}

// ---------------------------------------------------------------------------
// Fused projection GEMM: x @ {Wq|Wk|Wv|Wmemin}. grid=(25,32), block=256.
// ---------------------------------------------------------------------------
__global__ __launch_bounds__(256)
void proj_kernel(const float* __restrict__ x,
                 const float* __restrict__ Wq, const float* __restrict__ Wk,
                 const float* __restrict__ Wv, const float* __restrict__ Wz,
                 float* __restrict__ q, float* __restrict__ kout,
                 uint32_t* __restrict__ v2, float* __restrict__ z) {
    __shared__ uint32_t As[2][16 * AS_STR];
    __shared__ uint32_t Bs[2][16 * BS_STR];
    int tid = threadIdx.x;
    int lane = tid & 31, warp = tid >> 5;
    int wm = warp >> 1, wn = warp & 1;
    int ct = blockIdx.x;
    int row0 = blockIdx.y * 128;
    const float* B; float* C; int N, col0; bool isV = false;
    if (ct < 16)      { B = Wq; C = q;    N = 1024; col0 = ct * 64; }
    else if (ct < 20) { B = Wk; C = kout; N = 256;  col0 = (ct - 16) * 64; }
    else if (ct < 24) { B = Wv; C = nullptr; N = 256; col0 = (ct - 20) * 64; isV = true; }
    else              { B = Wz; C = z;    N = 64;   col0 = 0; }

    float d[2][4][4] = {};
    float4 ar[2]; float4 br;
    g_load(x, B, 1024, N, row0, col0, 0, tid, ar, br);
    g_sts(As[0], Bs[0], tid, ar, br);
    __syncthreads();
    for (int k0 = 0; k0 < 1024; k0 += 16) {
        int cur = (k0 >> 4) & 1;
        if (k0 + 16 < 1024) g_load(x, B, 1024, N, row0, col0, k0 + 16, tid, ar, br);
        g_mma(As[cur], Bs[cur], lane, wm, wn, d);
        if (k0 + 16 < 1024) g_sts(As[cur ^ 1], Bs[cur ^ 1], tid, ar, br);
        __syncthreads();
    }
    if (!isV) {
        g_epilogue(d, C, N, row0, col0, lane, wm, wn);
    } else {
        #pragma unroll
        for (int mt = 0; mt < 2; mt++) {
            #pragma unroll
            for (int nt = 0; nt < 4; nt++) {
                int r = row0 + wm * 32 + mt * 16 + (lane >> 2);
                int cc = col0 + wn * 32 + nt * 8 + 2 * (lane & 3);
                v2store(v2, r,     cc,     d[mt][nt][0]);
                v2store(v2, r,     cc + 1, d[mt][nt][1]);
                v2store(v2, r + 8, cc,     d[mt][nt][2]);
                v2store(v2, r + 8, cc + 1, d[mt][nt][3]);
            }
        }
    }
}

// ---------------------------------------------------------------------------
// Dual GEMM: C = A1@B1 + A2@B2. grid=(16,32), block=256.
// ---------------------------------------------------------------------------
__global__ __launch_bounds__(256)
void dual_gemm_kernel(const float* __restrict__ A1, const float* __restrict__ B1, int K1,
                      const float* __restrict__ A2, const float* __restrict__ B2, int K2,
                      float* __restrict__ C, int N) {
    __shared__ uint32_t As[2][16 * AS_STR];
    __shared__ uint32_t Bs[2][16 * BS_STR];
    int tid = threadIdx.x;
    int lane = tid & 31, warp = tid >> 5;
    int wm = warp >> 1, wn = warp & 1;
    int row0 = blockIdx.y * 128, col0 = blockIdx.x * 64;
    float d[2][4][4] = {};
    float4 ar[2]; float4 br;
    #pragma unroll
    for (int ph = 0; ph < 2; ph++) {
        const float* A = ph ? A2 : A1;
        const float* B = ph ? B2 : B1;
        int K = ph ? K2 : K1;
        g_load(A, B, K, N, row0, col0, 0, tid, ar, br);
        g_sts(As[0], Bs[0], tid, ar, br);
        __syncthreads();
        for (int k0 = 0; k0 < K; k0 += 16) {
            int cur = (k0 >> 4) & 1;
            if (k0 + 16 < K) g_load(A, B, K, N, row0, col0, k0 + 16, tid, ar, br);
            g_mma(As[cur], Bs[cur], lane, wm, wn, d);
            if (k0 + 16 < K) g_sts(As[cur ^ 1], Bs[cur ^ 1], tid, ar, br);
            __syncthreads();
        }
    }
    g_epilogue(d, C, N, row0, col0, lane, wm, wn);
}

// ---------------------------------------------------------------------------
// RoPE + tf32 convert + column permute. Q pre-scaled into log2 domain.
// ---------------------------------------------------------------------------
#define QSCALE 0.18033688f   // 0.125 * log2(e)

__global__ void rope_kernel(const float* __restrict__ qp, const float* __restrict__ kp,
                            uint32_t* __restrict__ q2, uint32_t* __restrict__ k2) {
    int idx = blockIdx.x * blockDim.x + threadIdx.x;
    const int qtot = Bsz * Sl * Hn * 32;
    const int ktot = Bsz * Sl * HKn * 32;
    const float* src; uint32_t* dst; int nheads; bool isq;
    if (idx < qtot) { src = qp; dst = q2; nheads = Hn; isq = true; }
    else { idx -= qtot; if (idx >= ktot) return; src = kp; dst = k2; nheads = HKn; isq = false; }
    int j = idx & 31;
    int h = (idx >> 5) % nheads;
    int s = ((idx >> 5) / nheads) % Sl;
    int b = idx / (32 * nheads * Sl);
    float inv = powf(500000.0f, -(float)(2 * j) / 64.0f);
    float ang = (float)s * inv;
    float c, sn;
    __sincosf(ang, &sn, &c);
    size_t base = ((size_t)(b * Sl + s) * nheads + h) * 64;
    float u1 = src[base + j], u2 = src[base + j + 32];
    float r1 = u1 * c - u2 * sn;
    float r2 = u2 * c + u1 * sn;
    if (isq) { r1 *= QSCALE; r2 *= QSCALE; }
    dst[base + colperm(j)]      = f2tf(r1);
    dst[base + colperm(j + 32)] = f2tf(r2);
}

// ---------------------------------------------------------------------------
// TF32 flash attention v4 (kept from R10): 128 threads (4 warps), warp tile
// 32 q-rows, full 64-col kv tile. V sigma-permuted in global so the QK
// C-fragment is the PV A-fragment by pure register reorder — zero shfl.
// ---------------------------------------------------------------------------
#define QST 72
#define KST 72
#define VST 144
#define ATTN_WORDS (128*QST + 2*64*KST + 2*32*VST)
#define ATTN_BYTES (ATTN_WORDS * 4)

__global__ __launch_bounds__(128, 2)
void attn_kernel(const uint32_t* __restrict__ q2, const uint32_t* __restrict__ k2,
                 const uint32_t* __restrict__ v2, float* __restrict__ o) {
    extern __shared__ uint32_t smu[];
    uint32_t* qs = smu;                 // [r:128][d':64] stride 72
    uint32_t* ks = qs + 128 * QST;      // 2 x [c:64][d':64] stride 72
    uint32_t* vs = ks + 2 * 64 * KST;   // 2 x [row':32][2d+slot:128] stride 144

    int qt = (int)gridDim.x - 1 - (int)blockIdx.x;   // longest tiles first
    int bh = blockIdx.y;
    int b = bh >> 4, h = bh & 15, kh = h >> 2;
    int tid = threadIdx.x;
    int lane = tid & 31, w = tid >> 5;
    int g = lane >> 2, c4 = lane & 3;
    int row_base = w * 32 + g;          // warp covers q-rows [w*32, w*32+32)

    size_t qbase = ((size_t)(b * Sl + qt * 128) * Hn + h) * 64;
    size_t kvbase = ((size_t)(b * Sl) * HKn + kh) * 64;
    size_t v2base0 = (size_t)(b * HKn + kh) * (Sl / 2) * 128;
    int ktmax = 2 * qt + 1;

    // ---- prologue: cp.async Q tile + K0 + V0 ----
    {
        unsigned qd = su32(qs);
        #pragma unroll
        for (int i = 0; i < 16; i++) {
            int vec = tid + i * 128;             // 128 rows x 16 chunks
            int r = vec >> 4, ch = vec & 15;
            CP16(qd + (unsigned)((r * QST + ch * 4) * 4),
                 &q2[qbase + (size_t)r * Hn * 64 + ch * 4]);
        }
        unsigned kd = su32(ks), vd = su32(vs);
        #pragma unroll
        for (int i = 0; i < 8; i++) {
            int vec = tid + i * 128;
            int c = vec >> 4, dq = vec & 15;
            CP16(kd + (unsigned)((c * KST + dq * 4) * 4),
                 &k2[kvbase + (size_t)c * HKn * 64 + dq * 4]);
            int row = vec >> 5, ch = vec & 31;
            CP16(vd + (unsigned)((row * VST + ch * 4) * 4),
                 &v2[v2base0 + (size_t)row * 128 + ch * 4]);
        }
        CPCOMMIT();
    }

    float m[2][2], l[2][2];
    #pragma unroll
    for (int mt = 0; mt < 2; mt++) {
        m[mt][0] = -1e30f; m[mt][1] = -1e30f;
        l[mt][0] = 0.f;    l[mt][1] = 0.f;
    }
    float accO[2][8][4] = {};
    CPWAITALL();
    __syncthreads();

    for (int kt = 0; kt <= ktmax; kt++) {
        const uint32_t* kb = ks + (kt & 1) * 64 * KST;
        const uint32_t* vb = vs + (kt & 1) * 32 * VST;

        if (kt < ktmax) {
            unsigned kd = su32(ks + ((kt + 1) & 1) * 64 * KST);
            unsigned vd = su32(vs + ((kt + 1) & 1) * 32 * VST);
            size_t kbase = kvbase + (size_t)(kt + 1) * 64 * HKn * 64;
            size_t vbase = v2base0 + (size_t)(kt + 1) * 32 * 128;
            #pragma unroll
            for (int i = 0; i < 8; i++) {
                int vec = tid + i * 128;
                int c = vec >> 4, dq = vec & 15;
                CP16(kd + (unsigned)((c * KST + dq * 4) * 4),
                     &k2[kbase + (size_t)c * HKn * 64 + dq * 4]);
                int row = vec >> 5, ch = vec & 31;
                CP16(vd + (unsigned)((row * VST + ch * 4) * 4),
                     &v2[vbase + (size_t)row * 128 + ch * 4]);
            }
            CPCOMMIT();
        }

        // ---- QK^T: 32 q-rows x 64 kv-cols per warp ----
        float sc[2][8][4] = {};
        #pragma unroll
        for (int t8 = 0; t8 < 8; t8++) {
            int pc = t8 * 8 + 2 * c4;     // permuted: (kc, kc+4) adjacent
            uint32_t a[2][4];
            #pragma unroll
            for (int mt = 0; mt < 2; mt++) {
                uint2 ua0 = *(const uint2*)&qs[(row_base + mt * 16) * QST + pc];
                uint2 ua1 = *(const uint2*)&qs[(row_base + mt * 16 + 8) * QST + pc];
                a[mt][0] = ua0.x; a[mt][1] = ua1.x; a[mt][2] = ua0.y; a[mt][3] = ua1.y;
            }
            #pragma unroll
            for (int nt = 0; nt < 8; nt++) {
                int n = nt * 8 + g;
                uint2 ub = *(const uint2*)&kb[n * KST + pc];
                uint32_t bb[2] = { ub.x, ub.y };
                mma8(sc[0][nt], a[0], bb);
                mma8(sc[1][nt], a[1], bb);
            }
        }

        // ---- causal mask ----
        if (kt >= 2 * qt) {
            #pragma unroll
            for (int mt = 0; mt < 2; mt++) {
                int rg0 = qt * 128 + row_base + mt * 16, rg1 = rg0 + 8;
                #pragma unroll
                for (int nt = 0; nt < 8; nt++) {
                    int cg = kt * 64 + nt * 8 + 2 * c4;
                    if (cg > rg0)     sc[mt][nt][0] = -1e30f;
                    if (cg + 1 > rg0) sc[mt][nt][1] = -1e30f;
                    if (cg > rg1)     sc[mt][nt][2] = -1e30f;
                    if (cg + 1 > rg1) sc[mt][nt][3] = -1e30f;
                }
            }
        }

        // ---- online softmax (log2 domain, bare EX2) ----
        #pragma unroll
        for (int mt = 0; mt < 2; mt++) {
            float mx0 = m[mt][0], mx1 = m[mt][1];
            #pragma unroll
            for (int nt = 0; nt < 8; nt++) {
                mx0 = fmaxf(mx0, fmaxf(sc[mt][nt][0], sc[mt][nt][1]));
                mx1 = fmaxf(mx1, fmaxf(sc[mt][nt][2], sc[mt][nt][3]));
            }
            mx0 = fmaxf(mx0, __shfl_xor_sync(0xffffffffu, mx0, 1));
            mx0 = fmaxf(mx0, __shfl_xor_sync(0xffffffffu, mx0, 2));
            mx1 = fmaxf(mx1, __shfl_xor_sync(0xffffffffu, mx1, 1));
            mx1 = fmaxf(mx1, __shfl_xor_sync(0xffffffffu, mx1, 2));
            float f0 = ex2(m[mt][0] - mx0), f1 = ex2(m[mt][1] - mx1);
            m[mt][0] = mx0; m[mt][1] = mx1;
            float sum0 = 0.f, sum1 = 0.f;
            #pragma unroll
            for (int nt = 0; nt < 8; nt++) {
                sc[mt][nt][0] = ex2(sc[mt][nt][0] - mx0); sum0 += sc[mt][nt][0];
                sc[mt][nt][1] = ex2(sc[mt][nt][1] - mx0); sum0 += sc[mt][nt][1];
                sc[mt][nt][2] = ex2(sc[mt][nt][2] - mx1); sum1 += sc[mt][nt][2];
                sc[mt][nt][3] = ex2(sc[mt][nt][3] - mx1); sum1 += sc[mt][nt][3];
            }
            sum0 += __shfl_xor_sync(0xffffffffu, sum0, 1);
            sum0 += __shfl_xor_sync(0xffffffffu, sum0, 2);
            sum1 += __shfl_xor_sync(0xffffffffu, sum1, 1);
            sum1 += __shfl_xor_sync(0xffffffffu, sum1, 2);
            l[mt][0] = l[mt][0] * f0 + sum0;
            l[mt][1] = l[mt][1] * f1 + sum1;
            #pragma unroll
            for (int nt = 0; nt < 8; nt++) {
                accO[mt][nt][0] *= f0; accO[mt][nt][1] *= f0;
                accO[mt][nt][2] *= f1; accO[mt][nt][3] *= f1;
            }
        }

        // ---- P @ V: C-fragment IS the A-fragment under sigma (no shfl) ----
        #pragma unroll
        for (int t = 0; t < 8; t++) {
            uint32_t a[2][4];
            #pragma unroll
            for (int mt = 0; mt < 2; mt++) {
                a[mt][0] = f2tf(sc[mt][t][0]);   // (row g,   k'=c4)   = P[g][2c4]
                a[mt][1] = f2tf(sc[mt][t][2]);   // (row g+8, k'=c4)   = P[g+8][2c4]
                a[mt][2] = f2tf(sc[mt][t][1]);   // (row g,   k'=c4+4) = P[g][2c4+1]
                a[mt][3] = f2tf(sc[mt][t][3]);   // (row g+8, k'=c4+4) = P[g+8][2c4+1]
            }
            int vrow = t * 4 + c4;   // V' row pair = original rows (8t+2c4, 8t+2c4+1)
            #pragma unroll
            for (int nt = 0; nt < 8; nt++) {
                int dcol = nt * 8 + g;
                uint2 ub = *(const uint2*)&vb[vrow * VST + 2 * dcol];
                uint32_t bb[2] = { ub.x, ub.y };
                mma8(accO[0][nt], a[0], bb);
                mma8(accO[1][nt], a[1], bb);
            }
        }

        if (kt < ktmax) CPWAITALL();
        __syncthreads();
    }

    // ---- epilogue ----
    #pragma unroll
    for (int mt = 0; mt < 2; mt++) {
        float il0 = 1.f / l[mt][0], il1 = 1.f / l[mt][1];
        size_t ob0 = ((size_t)(b * Sl + qt * 128 + row_base + mt * 16) * Hn + h) * 64;
        size_t ob1 = ((size_t)(b * Sl + qt * 128 + row_base + mt * 16 + 8) * Hn + h) * 64;
        #pragma unroll
        for (int nt = 0; nt < 8; nt++) {
            int dcol = nt * 8 + 2 * c4;
            *(float2*)&o[ob0 + dcol] = make_float2(accO[mt][nt][0] * il0, accO[mt][nt][1] * il0);
            *(float2*)&o[ob1 + dcol] = make_float2(accO[mt][nt][2] * il1, accO[mt][nt][3] * il1);
        }
    }
}

// ---------------------------------------------------------------------------
// Chunked delta-rule memory scan (side stream).
// ---------------------------------------------------------------------------
__global__ __launch_bounds__(256)
void memscan_kernel(const float* __restrict__ z,
                    const float* __restrict__ M_init,
                    const float* __restrict__ w_eta, const float* __restrict__ b_eta,
                    const float* __restrict__ w_alpha, const float* __restrict__ b_alpha,
                    const float* __restrict__ w_gate, const float* __restrict__ b_gate,
                    float* __restrict__ mem_out) {
    __shared__ float Ms[64][65];
    __shared__ float chs[64][65];
    __shared__ float red2[16][64];
    __shared__ float se[64], sa[64], sg[64], nrm[64];
    __shared__ float kmean[64], vt[64], diffv[64];
    __shared__ float swe[64], swa[64], swg[64];
    __shared__ float redw[8];
    __shared__ float sc_eta, sc_alpha, sc_gate, sc_scale;

    int b = blockIdx.x;
    int tid = threadIdx.x;
    int tx = tid & 15, ty = tid >> 4;
    int lane = tid & 31, warp = tid >> 5;
    int tok = tid >> 2, part = tid & 3;
    float be = b_eta[0], ba = b_alpha[0], bg = b_gate[0];

    if (tid < 64) { swe[tid] = w_eta[tid]; swa[tid] = w_alpha[tid]; swg[tid] = w_gate[tid]; }
    #pragma unroll
    for (int i = 0; i < 16; i++) {
        int idx = tid + i * 256;
        Ms[idx >> 6][idx & 63] = M_init[idx];
    }
    __syncthreads();

    for (int c = 0; c < NCH; c++) {
        #pragma unroll
        for (int i = 0; i < 16; i++) {
            int idx = tid + i * 256;
            chs[idx >> 6][idx & 63] = z[((size_t)b * Sl + c * 64 + (idx >> 6)) * 64 + (idx & 63)];
        }
        __syncthreads();

        float o4[4][4] = {};
        #pragma unroll
        for (int d = 0; d < 64; d++) {
            float a0 = chs[ty*4+0][d], a1 = chs[ty*4+1][d];
            float a2 = chs[ty*4+2][d], a3 = chs[ty*4+3][d];
            float m0 = Ms[tx*4+0][d], m1 = Ms[tx*4+1][d];
            float m2 = Ms[tx*4+2][d], m3 = Ms[tx*4+3][d];
            o4[0][0] += a0*m0; o4[0][1] += a0*m1; o4[0][2] += a0*m2; o4[0][3] += a0*m3;
            o4[1][0] += a1*m0; o4[1][1] += a1*m1; o4[1][2] += a1*m2; o4[1][3] += a1*m3;
            o4[2][0] += a2*m0; o4[2][1] += a2*m1; o4[2][2] += a2*m2; o4[2][3] += a2*m3;
            o4[3][0] += a3*m0; o4[3][1] += a3*m1; o4[3][2] += a3*m2; o4[3][3] += a3*m3;
        }
        #pragma unroll
        for (int i = 0; i < 4; i++)
            #pragma unroll
            for (int j = 0; j < 4; j++)
                mem_out[((size_t)b * Sl + c * 64 + ty * 4 + i) * 64 + tx * 4 + j] = o4[i][j];
        #pragma unroll
        for (int j = 0; j < 4; j++)
            red2[ty][tx * 4 + j] = o4[0][j] + o4[1][j] + o4[2][j] + o4[3][j];
        __syncthreads();

        {
            float de = 0.f, da = 0.f, dg = 0.f, nn = 0.f;
            int d0 = part * 16;
            #pragma unroll
            for (int dd = 0; dd < 16; dd++) {
                float xv = chs[tok][d0 + dd];
                de = fmaf(xv, swe[d0 + dd], de);
                da = fmaf(xv, swa[d0 + dd], da);
                dg = fmaf(xv, swg[d0 + dd], dg);
                nn = fmaf(xv, xv, nn);
            }
            de += __shfl_xor_sync(0xffffffffu, de, 1); de += __shfl_xor_sync(0xffffffffu, de, 2);
            da += __shfl_xor_sync(0xffffffffu, da, 1); da += __shfl_xor_sync(0xffffffffu, da, 2);
            dg += __shfl_xor_sync(0xffffffffu, dg, 1); dg += __shfl_xor_sync(0xffffffffu, dg, 2);
            nn += __shfl_xor_sync(0xffffffffu, nn, 1); nn += __shfl_xor_sync(0xffffffffu, nn, 2);
            if (part == 0) {
                se[tok] = 0.2f / (1.f + __expf(-(de + be)));
                sa[tok] = 0.5f + 0.5f / (1.f + __expf(-(da + ba)));
                sg[tok] = 1.f / (1.f + __expf(-(dg + bg)));
                nrm[tok] = fmaxf(sqrtf(nn), 1e-6f);
            }
        }
        __syncthreads();

        {
            float s = 0.f, s2 = 0.f;
            #pragma unroll
            for (int t = 0; t < 16; t++) s += chs[part * 16 + t][tok] / nrm[part * 16 + t];
            #pragma unroll
            for (int yy = 0; yy < 4; yy++) s2 += red2[part * 4 + yy][tok];
            s  += __shfl_xor_sync(0xffffffffu, s, 1);  s  += __shfl_xor_sync(0xffffffffu, s, 2);
            s2 += __shfl_xor_sync(0xffffffffu, s2, 1); s2 += __shfl_xor_sync(0xffffffffu, s2, 2);
            if (part == 0) { kmean[tok] = s * (1.f / 64.f); vt[tok] = s2 * (1.f / 64.f); }
        }
        __syncthreads();

        if (tid < 32) {
            float e = se[tid] + se[tid + 32];
            float a = sa[tid] + sa[tid + 32];
            float gg = sg[tid] + sg[tid + 32];
            #pragma unroll
            for (int st = 16; st; st >>= 1) {
                e  += __shfl_xor_sync(0xffffffffu, e, st);
                a  += __shfl_xor_sync(0xffffffffu, a, st);
                gg += __shfl_xor_sync(0xffffffffu, gg, st);
            }
            if (tid == 0) {
                sc_eta = e * (1.f / 64.f);
                sc_alpha = a * (1.f / 64.f);
                sc_gate = gg * (1.f / 64.f);
            }
        }
        {
            float s = 0.f;
            int d0 = part * 16;
            #pragma unroll
            for (int dd = 0; dd < 16; dd++)
                s = fmaf(Ms[tok][d0 + dd], kmean[d0 + dd], s);
            s += __shfl_xor_sync(0xffffffffu, s, 1);
            s += __shfl_xor_sync(0xffffffffu, s, 2);
            if (part == 0) diffv[tok] = vt[tok] - s;
        }
        __syncthreads();

        float eg = sc_eta * sc_gate, al = sc_alpha;
        float ss2 = 0.f;
        #pragma unroll
        for (int i = 0; i < 16; i++) {
            int idx = tid + i * 256;
            int vv = idx >> 6, d = idx & 63;
            float mn = al * Ms[vv][d] + eg * diffv[vv] * kmean[d];
            Ms[vv][d] = mn;
            ss2 = fmaf(mn, mn, ss2);
        }
        #pragma unroll
        for (int st = 16; st; st >>= 1) ss2 += __shfl_xor_sync(0xffffffffu, ss2, st);
        if (lane == 0) redw[warp] = ss2;
        __syncthreads();
        if (tid == 0) {
            float fro = sqrtf(redw[0] + redw[1] + redw[2] + redw[3] +
                              redw[4] + redw[5] + redw[6] + redw[7]);
            sc_scale = fminf(1.f, 30.f / fmaxf(fro, 1e-6f));
        }
        __syncthreads();
        #pragma unroll
        for (int i = 0; i < 16; i++) {
            int idx = tid + i * 256;
            Ms[idx >> 6][idx & 63] *= sc_scale;
        }
        __syncthreads();
    }
}

// ---------------------------------------------------------------------------
extern "C" void kernel_launch(void* const* d_in, const int* in_sizes, int n_in,
                              void* d_out, int out_size) {
    const float* x       = (const float*)d_in[0];
    const float* Wq      = (const float*)d_in[1];
    const float* Wk      = (const float*)d_in[2];
    const float* Wv      = (const float*)d_in[3];
    const float* Wo      = (const float*)d_in[4];
    const float* Wmemin  = (const float*)d_in[5];
    const float* Wmemout = (const float*)d_in[6];
    const float* M_init  = (const float*)d_in[7];
    const float* w_eta   = (const float*)d_in[8];
    const float* b_eta   = (const float*)d_in[9];
    const float* w_alpha = (const float*)d_in[10];
    const float* b_alpha = (const float*)d_in[11];
    const float* w_gate  = (const float*)d_in[12];
    const float* b_gate  = (const float*)d_in[13];
    float* out = (float*)d_out;

    float *q, *k, *attn, *z, *mem;
    uint32_t *q2, *k2, *v2;
    cudaGetSymbolAddress((void**)&q, g_q);
    cudaGetSymbolAddress((void**)&k, g_k);
    cudaGetSymbolAddress((void**)&attn, g_attn);
    cudaGetSymbolAddress((void**)&z, g_z);
    cudaGetSymbolAddress((void**)&mem, g_mem);
    cudaGetSymbolAddress((void**)&q2, g_q2);
    cudaGetSymbolAddress((void**)&k2, g_k2);
    cudaGetSymbolAddress((void**)&v2, g_v2);

    static cudaStream_t s2 = nullptr;
    static cudaEvent_t evZ = nullptr, evM = nullptr;
    static int inited = 0;
    if (!inited) {
        cudaStreamCreateWithFlags(&s2, cudaStreamNonBlocking);
        cudaEventCreateWithFlags(&evZ, cudaEventDisableTiming);
        cudaEventCreateWithFlags(&evM, cudaEventDisableTiming);
        cudaFuncSetAttribute(attn_kernel,
                             cudaFuncAttributeMaxDynamicSharedMemorySize, ATTN_BYTES);
        inited = 1;
    }

    // Fused projections (q, k fp32; v tf32 sigma-paired; z fp32)
    proj_kernel<<<dim3(25, 32), 256>>>(x, Wq, Wk, Wv, Wmemin, q, k, v2, z);

    // Fork serial memscan onto side stream (depends on z)
    cudaEventRecord(evZ, 0);
    cudaStreamWaitEvent(s2, evZ, 0);
    memscan_kernel<<<Bsz, 256, 0, s2>>>(z, M_init, w_eta, b_eta, w_alpha, b_alpha,
                                        w_gate, b_gate, mem);
    cudaEventRecord(evM, s2);

    // RoPE + tf32 convert + permute (q scaled)
    {
        int total = Bsz * Sl * (Hn + HKn) * 32;
        rope_kernel<<<(total + 255) / 256, 256>>>(q, k, q2, k2);
    }

    // Attention
    attn_kernel<<<dim3(Sl/128, Bsz*Hn), 128, ATTN_BYTES>>>(q2, k2, v2, attn);

    // Join memscan, then fused output GEMM
    cudaStreamWaitEvent((cudaStream_t)0, evM, 0);
    dual_gemm_kernel<<<dim3(16, 32), 256>>>(attn, Wo, Hn*HDn,
                                            mem, Wmemout, DVn, out, Dm);
}

// round 12
// speedup vs baseline: 1.0842x; 1.0008x over previous
#include <cuda_runtime.h>
#include <math.h>
#include <stdint.h>

#define Bsz 2
#define Sl  2048
#define Dm  1024
#define Hn  16
#define HKn 4
#define HDn 64
#define DKn 64
#define DVn 64
#define NCH 32
#define MS  (Bsz*Sl)

__device__ float    g_q[Bsz*Sl*Hn*HDn];        // fp32 q (pre-rope)
__device__ float    g_k[Bsz*Sl*HKn*HDn];       // fp32 k (pre-rope)
__device__ float    g_attn[Bsz*Sl*Hn*HDn];
__device__ float    g_z[Bsz*Sl*DKn];
__device__ float    g_mem[Bsz*Sl*DVn];
__device__ uint32_t g_q2[Bsz*Sl*Hn*HDn];       // tf32, col-permuted, scaled
__device__ uint32_t g_k2[Bsz*Sl*HKn*HDn];      // tf32, col-permuted
__device__ uint32_t g_v2[Bsz*HKn*(Sl/2)*128];  // tf32, sigma-permuted row pairs

__device__ __forceinline__ uint32_t f2tf(float x) {
    uint32_t u; asm("cvt.rna.tf32.f32 %0, %1;" : "=r"(u) : "f"(x)); return u;
}
__device__ __forceinline__ float ex2(float x) {
    float y; asm("ex2.approx.f32 %0, %1;" : "=f"(y) : "f"(x)); return y;
}
__device__ __forceinline__ int colperm(int d) {   // per-8 group: 0,4,1,5,2,6,3,7
    return (d & ~7) | ((d & 3) << 1) | ((d >> 2) & 1);
}
__device__ __forceinline__ unsigned su32(const void* p) {
    unsigned a;
    asm("{.reg .u64 t; cvta.to.shared.u64 t, %1; cvt.u32.u64 %0, t;}" : "=r"(a) : "l"(p));
    return a;
}
#define CP16(dst, src) asm volatile("cp.async.ca.shared.global [%0], [%1], 16;" :: "r"(dst), "l"(src))
#define CPCOMMIT()     asm volatile("cp.async.commit_group;")
#define CPWAITALL()    asm volatile("cp.async.wait_group 0;")

// mma.sync m16n8k8 tf32
__device__ __forceinline__ void mma8(float d[4], const uint32_t a[4], const uint32_t b[2]) {
    asm volatile(
        "mma.sync.aligned.m16n8k8.row.col.f32.tf32.tf32.f32 "
        "{%0,%1,%2,%3}, {%4,%5,%6,%7}, {%8,%9}, {%0,%1,%2,%3};"
        : "+f"(d[0]), "+f"(d[1]), "+f"(d[2]), "+f"(d[3])
        : "r"(a[0]), "r"(a[1]), "r"(a[2]), "r"(a[3]), "r"(b[0]), "r"(b[1]));
}

// ===========================================================================
// TF32 GEMM core (proj/dual): BM=128, BN=64, BK=16, 256 thr, double-buffered.
// (R9-proven form: AS_STR=136, scalar A-fragment loads, conflict-free.)
// ===========================================================================
#define AS_STR 136
#define BS_STR 72

__device__ __forceinline__ void g_load(const float* __restrict__ A,
                                       const float* __restrict__ B,
                                       int K, int N, int row0, int col0, int k0,
                                       int tid, float4 ar[2], float4& br) {
    #pragma unroll
    for (int i = 0; i < 2; i++) {
        int vec = tid + i * 256;
        int m = vec >> 2, kq = vec & 3;
        ar[i] = *(const float4*)&A[(size_t)(row0 + m) * K + k0 + kq * 4];
    }
    int kk = tid >> 4, nq = tid & 15;
    br = *(const float4*)&B[(size_t)(k0 + kk) * N + col0 + nq * 4];
}

__device__ __forceinline__ void g_sts(uint32_t* As, uint32_t* Bs, int tid,
                                      const float4 ar[2], const float4& br) {
    #pragma unroll
    for (int i = 0; i < 2; i++) {
        int vec = tid + i * 256;
        int m = vec >> 2, kq = vec & 3;
        As[(kq * 4 + 0) * AS_STR + m] = f2tf(ar[i].x);
        As[(kq * 4 + 1) * AS_STR + m] = f2tf(ar[i].y);
        As[(kq * 4 + 2) * AS_STR + m] = f2tf(ar[i].z);
        As[(kq * 4 + 3) * AS_STR + m] = f2tf(ar[i].w);
    }
    int kk = tid >> 4, nq = tid & 15;
    uint4 t;
    t.x = f2tf(br.x); t.y = f2tf(br.y); t.z = f2tf(br.z); t.w = f2tf(br.w);
    *(uint4*)&Bs[kk * BS_STR + nq * 4] = t;
}

__device__ __forceinline__ void g_mma(const uint32_t* As, const uint32_t* Bs,
                                      int lane, int wm, int wn, float d[2][4][4]) {
    #pragma unroll
    for (int ks = 0; ks < 16; ks += 8) {
        int kc = ks + (lane & 3);
        uint32_t a[2][4], b[4][2];
        #pragma unroll
        for (int mt = 0; mt < 2; mt++) {
            int r = wm * 32 + mt * 16 + (lane >> 2);
            a[mt][0] = As[kc * AS_STR + r];
            a[mt][1] = As[kc * AS_STR + r + 8];
            a[mt][2] = As[(kc + 4) * AS_STR + r];
            a[mt][3] = As[(kc + 4) * AS_STR + r + 8];
        }
        #pragma unroll
        for (int nt = 0; nt < 4; nt++) {
            int n = wn * 32 + nt * 8 + (lane >> 2);
            b[nt][0] = Bs[kc * BS_STR + n];
            b[nt][1] = Bs[(kc + 4) * BS_STR + n];
        }
        #pragma unroll
        for (int mt = 0; mt < 2; mt++)
            #pragma unroll
            for (int nt = 0; nt < 4; nt++)
                mma8(d[mt][nt], a[mt], b[nt]);
    }
}

__device__ __forceinline__ void g_epilogue(float d[2][4][4], float* __restrict__ C,
                                           int N, int row0, int col0,
                                           int lane, int wm, int wn) {
    #pragma unroll
    for (int mt = 0; mt < 2; mt++) {
        #pragma unroll
        for (int nt = 0; nt < 4; nt++) {
            int r = row0 + wm * 32 + mt * 16 + (lane >> 2);
            int cc = col0 + wn * 32 + nt * 8 + 2 * (lane & 3);
            *(float2*)&C[(size_t)r * N + cc]       = make_float2(d[mt][nt][0], d[mt][nt][1]);
            *(float2*)&C[(size_t)(r + 8) * N + cc] = make_float2(d[mt][nt][2], d[mt][nt][3]);
        }
    }
}

// V store into sigma-paired tf32 layout:
// V'[(b,kh)][ (s>>3)*4 + ((s>>1)&3) ][ 2d + (s&1) ]
__device__ __forceinline__ void v2store(uint32_t* __restrict__ v2, int r, int cc, float val) {
    int s = r & (Sl - 1), b = r >> 11;
    int kh = cc >> 6, d = cc & 63;
    size_t idx = ((size_t)(b * HKn + kh) * (Sl / 2) + (s >> 3) * 4 + ((s >> 1) & 3)) * 128
               + 2 * d + (s & 1);
    v2[idx] = f2tf(val);
}

// ---------------------------------------------------------------------------
// Fused projection GEMM: x @ {Wq|Wk|Wv|Wmemin}. grid=(25,32), block=256.
// ---------------------------------------------------------------------------
__global__ __launch_bounds__(256)
void proj_kernel(const float* __restrict__ x,
                 const float* __restrict__ Wq, const float* __restrict__ Wk,
                 const float* __restrict__ Wv, const float* __restrict__ Wz,
                 float* __restrict__ q, float* __restrict__ kout,
                 uint32_t* __restrict__ v2, float* __restrict__ z) {
    __shared__ uint32_t As[2][16 * AS_STR];
    __shared__ uint32_t Bs[2][16 * BS_STR];
    int tid = threadIdx.x;
    int lane = tid & 31, warp = tid >> 5;
    int wm = warp >> 1, wn = warp & 1;
    int ct = blockIdx.x;
    int row0 = blockIdx.y * 128;
    const float* B; float* C; int N, col0; bool isV = false;
    if (ct < 16)      { B = Wq; C = q;    N = 1024; col0 = ct * 64; }
    else if (ct < 20) { B = Wk; C = kout; N = 256;  col0 = (ct - 16) * 64; }
    else if (ct < 24) { B = Wv; C = nullptr; N = 256; col0 = (ct - 20) * 64; isV = true; }
    else              { B = Wz; C = z;    N = 64;   col0 = 0; }

    float d[2][4][4] = {};
    float4 ar[2]; float4 br;
    g_load(x, B, 1024, N, row0, col0, 0, tid, ar, br);
    g_sts(As[0], Bs[0], tid, ar, br);
    __syncthreads();
    for (int k0 = 0; k0 < 1024; k0 += 16) {
        int cur = (k0 >> 4) & 1;
        if (k0 + 16 < 1024) g_load(x, B, 1024, N, row0, col0, k0 + 16, tid, ar, br);
        g_mma(As[cur], Bs[cur], lane, wm, wn, d);
        if (k0 + 16 < 1024) g_sts(As[cur ^ 1], Bs[cur ^ 1], tid, ar, br);
        __syncthreads();
    }
    if (!isV) {
        g_epilogue(d, C, N, row0, col0, lane, wm, wn);
    } else {
        #pragma unroll
        for (int mt = 0; mt < 2; mt++) {
            #pragma unroll
            for (int nt = 0; nt < 4; nt++) {
                int r = row0 + wm * 32 + mt * 16 + (lane >> 2);
                int cc = col0 + wn * 32 + nt * 8 + 2 * (lane & 3);
                v2store(v2, r,     cc,     d[mt][nt][0]);
                v2store(v2, r,     cc + 1, d[mt][nt][1]);
                v2store(v2, r + 8, cc,     d[mt][nt][2]);
                v2store(v2, r + 8, cc + 1, d[mt][nt][3]);
            }
        }
    }
}

// ---------------------------------------------------------------------------
// Dual GEMM: C = A1@B1 + A2@B2. grid=(16,32), block=256.
// ---------------------------------------------------------------------------
__global__ __launch_bounds__(256)
void dual_gemm_kernel(const float* __restrict__ A1, const float* __restrict__ B1, int K1,
                      const float* __restrict__ A2, const float* __restrict__ B2, int K2,
                      float* __restrict__ C, int N) {
    __shared__ uint32_t As[2][16 * AS_STR];
    __shared__ uint32_t Bs[2][16 * BS_STR];
    int tid = threadIdx.x;
    int lane = tid & 31, warp = tid >> 5;
    int wm = warp >> 1, wn = warp & 1;
    int row0 = blockIdx.y * 128, col0 = blockIdx.x * 64;
    float d[2][4][4] = {};
    float4 ar[2]; float4 br;
    #pragma unroll
    for (int ph = 0; ph < 2; ph++) {
        const float* A = ph ? A2 : A1;
        const float* B = ph ? B2 : B1;
        int K = ph ? K2 : K1;
        g_load(A, B, K, N, row0, col0, 0, tid, ar, br);
        g_sts(As[0], Bs[0], tid, ar, br);
        __syncthreads();
        for (int k0 = 0; k0 < K; k0 += 16) {
            int cur = (k0 >> 4) & 1;
            if (k0 + 16 < K) g_load(A, B, K, N, row0, col0, k0 + 16, tid, ar, br);
            g_mma(As[cur], Bs[cur], lane, wm, wn, d);
            if (k0 + 16 < K) g_sts(As[cur ^ 1], Bs[cur ^ 1], tid, ar, br);
            __syncthreads();
        }
    }
    g_epilogue(d, C, N, row0, col0, lane, wm, wn);
}

// ---------------------------------------------------------------------------
// RoPE + tf32 convert + column permute. Q pre-scaled into log2 domain.
// ---------------------------------------------------------------------------
#define QSCALE 0.18033688f   // 0.125 * log2(e)

__global__ void rope_kernel(const float* __restrict__ qp, const float* __restrict__ kp,
                            uint32_t* __restrict__ q2, uint32_t* __restrict__ k2) {
    int idx = blockIdx.x * blockDim.x + threadIdx.x;
    const int qtot = Bsz * Sl * Hn * 32;
    const int ktot = Bsz * Sl * HKn * 32;
    const float* src; uint32_t* dst; int nheads; bool isq;
    if (idx < qtot) { src = qp; dst = q2; nheads = Hn; isq = true; }
    else { idx -= qtot; if (idx >= ktot) return; src = kp; dst = k2; nheads = HKn; isq = false; }
    int j = idx & 31;
    int h = (idx >> 5) % nheads;
    int s = ((idx >> 5) / nheads) % Sl;
    int b = idx / (32 * nheads * Sl);
    float inv = powf(500000.0f, -(float)(2 * j) / 64.0f);
    float ang = (float)s * inv;
    float c, sn;
    __sincosf(ang, &sn, &c);
    size_t base = ((size_t)(b * Sl + s) * nheads + h) * 64;
    float u1 = src[base + j], u2 = src[base + j + 32];
    float r1 = u1 * c - u2 * sn;
    float r2 = u2 * c + u1 * sn;
    if (isq) { r1 *= QSCALE; r2 *= QSCALE; }
    dst[base + colperm(j)]      = f2tf(r1);
    dst[base + colperm(j + 32)] = f2tf(r2);
}

// ---------------------------------------------------------------------------
// TF32 flash attention v5: no-max softmax (scores provably bounded << 127 in
// log2 domain; masked entries flush to 0 under ex2.approx). Per-thread l is a
// pure partial sum, reduced once in the epilogue. V sigma-permuted so QK
// C-frag == PV A-frag (no shfl). 128 threads, 2 CTAs/SM.
// ---------------------------------------------------------------------------
#define QST 72
#define KST 72
#define VST 144
#define ATTN_WORDS (128*QST + 2*64*KST + 2*32*VST)
#define ATTN_BYTES (ATTN_WORDS * 4)

__global__ __launch_bounds__(128, 2)
void attn_kernel(const uint32_t* __restrict__ q2, const uint32_t* __restrict__ k2,
                 const uint32_t* __restrict__ v2, float* __restrict__ o) {
    extern __shared__ uint32_t smu[];
    uint32_t* qs = smu;                 // [r:128][d':64] stride 72
    uint32_t* ks = qs + 128 * QST;      // 2 x [c:64][d':64] stride 72
    uint32_t* vs = ks + 2 * 64 * KST;   // 2 x [row':32][2d+slot:128] stride 144

    int qt = (int)gridDim.x - 1 - (int)blockIdx.x;   // longest tiles first
    int bh = blockIdx.y;
    int b = bh >> 4, h = bh & 15, kh = h >> 2;
    int tid = threadIdx.x;
    int lane = tid & 31, w = tid >> 5;
    int g = lane >> 2, c4 = lane & 3;
    int row_base = w * 32 + g;

    size_t qbase = ((size_t)(b * Sl + qt * 128) * Hn + h) * 64;
    size_t kvbase = ((size_t)(b * Sl) * HKn + kh) * 64;
    size_t v2base0 = (size_t)(b * HKn + kh) * (Sl / 2) * 128;
    int ktmax = 2 * qt + 1;

    // ---- prologue: cp.async Q tile + K0 + V0 ----
    {
        unsigned qd = su32(qs);
        #pragma unroll
        for (int i = 0; i < 16; i++) {
            int vec = tid + i * 128;
            int r = vec >> 4, ch = vec & 15;
            CP16(qd + (unsigned)((r * QST + ch * 4) * 4),
                 &q2[qbase + (size_t)r * Hn * 64 + ch * 4]);
        }
        unsigned kd = su32(ks), vd = su32(vs);
        #pragma unroll
        for (int i = 0; i < 8; i++) {
            int vec = tid + i * 128;
            int c = vec >> 4, dq = vec & 15;
            CP16(kd + (unsigned)((c * KST + dq * 4) * 4),
                 &k2[kvbase + (size_t)c * HKn * 64 + dq * 4]);
            int row = vec >> 5, ch = vec & 31;
            CP16(vd + (unsigned)((row * VST + ch * 4) * 4),
                 &v2[v2base0 + (size_t)row * 128 + ch * 4]);
        }
        CPCOMMIT();
    }

    float l[2][2] = {};
    float accO[2][8][4] = {};
    CPWAITALL();
    __syncthreads();

    for (int kt = 0; kt <= ktmax; kt++) {
        const uint32_t* kb = ks + (kt & 1) * 64 * KST;
        const uint32_t* vb = vs + (kt & 1) * 32 * VST;

        if (kt < ktmax) {
            unsigned kd = su32(ks + ((kt + 1) & 1) * 64 * KST);
            unsigned vd = su32(vs + ((kt + 1) & 1) * 32 * VST);
            size_t kbase = kvbase + (size_t)(kt + 1) * 64 * HKn * 64;
            size_t vbase = v2base0 + (size_t)(kt + 1) * 32 * 128;
            #pragma unroll
            for (int i = 0; i < 8; i++) {
                int vec = tid + i * 128;
                int c = vec >> 4, dq = vec & 15;
                CP16(kd + (unsigned)((c * KST + dq * 4) * 4),
                     &k2[kbase + (size_t)c * HKn * 64 + dq * 4]);
                int row = vec >> 5, ch = vec & 31;
                CP16(vd + (unsigned)((row * VST + ch * 4) * 4),
                     &v2[vbase + (size_t)row * 128 + ch * 4]);
            }
            CPCOMMIT();
        }

        // ---- QK^T: 32 q-rows x 64 kv-cols per warp ----
        float sc[2][8][4] = {};
        #pragma unroll
        for (int t8 = 0; t8 < 8; t8++) {
            int pc = t8 * 8 + 2 * c4;
            uint32_t a[2][4];
            #pragma unroll
            for (int mt = 0; mt < 2; mt++) {
                uint2 ua0 = *(const uint2*)&qs[(row_base + mt * 16) * QST + pc];
                uint2 ua1 = *(const uint2*)&qs[(row_base + mt * 16 + 8) * QST + pc];
                a[mt][0] = ua0.x; a[mt][1] = ua1.x; a[mt][2] = ua0.y; a[mt][3] = ua1.y;
            }
            #pragma unroll
            for (int nt = 0; nt < 8; nt++) {
                int n = nt * 8 + g;
                uint2 ub = *(const uint2*)&kb[n * KST + pc];
                uint32_t bb[2] = { ub.x, ub.y };
                mma8(sc[0][nt], a[0], bb);
                mma8(sc[1][nt], a[1], bb);
            }
        }

        // ---- causal mask ----
        if (kt >= 2 * qt) {
            #pragma unroll
            for (int mt = 0; mt < 2; mt++) {
                int rg0 = qt * 128 + row_base + mt * 16, rg1 = rg0 + 8;
                #pragma unroll
                for (int nt = 0; nt < 8; nt++) {
                    int cg = kt * 64 + nt * 8 + 2 * c4;
                    if (cg > rg0)     sc[mt][nt][0] = -1e30f;
                    if (cg + 1 > rg0) sc[mt][nt][1] = -1e30f;
                    if (cg > rg1)     sc[mt][nt][2] = -1e30f;
                    if (cg + 1 > rg1) sc[mt][nt][3] = -1e30f;
                }
            }
        }

        // ---- softmax numerator (log2 domain, no max subtraction) ----
        #pragma unroll
        for (int mt = 0; mt < 2; mt++) {
            #pragma unroll
            for (int nt = 0; nt < 8; nt++) {
                sc[mt][nt][0] = ex2(sc[mt][nt][0]); l[mt][0] += sc[mt][nt][0];
                sc[mt][nt][1] = ex2(sc[mt][nt][1]); l[mt][0] += sc[mt][nt][1];
                sc[mt][nt][2] = ex2(sc[mt][nt][2]); l[mt][1] += sc[mt][nt][2];
                sc[mt][nt][3] = ex2(sc[mt][nt][3]); l[mt][1] += sc[mt][nt][3];
            }
        }

        // ---- P @ V: C-fragment IS the A-fragment under sigma ----
        #pragma unroll
        for (int t = 0; t < 8; t++) {
            uint32_t a[2][4];
            #pragma unroll
            for (int mt = 0; mt < 2; mt++) {
                a[mt][0] = f2tf(sc[mt][t][0]);
                a[mt][1] = f2tf(sc[mt][t][2]);
                a[mt][2] = f2tf(sc[mt][t][1]);
                a[mt][3] = f2tf(sc[mt][t][3]);
            }
            int vrow = t * 4 + c4;
            #pragma unroll
            for (int nt = 0; nt < 8; nt++) {
                int dcol = nt * 8 + g;
                uint2 ub = *(const uint2*)&vb[vrow * VST + 2 * dcol];
                uint32_t bb[2] = { ub.x, ub.y };
                mma8(accO[0][nt], a[0], bb);
                mma8(accO[1][nt], a[1], bb);
            }
        }

        if (kt < ktmax) CPWAITALL();
        __syncthreads();
    }

    // ---- epilogue: reduce l across the 4-lane row group, then scale ----
    #pragma unroll
    for (int mt = 0; mt < 2; mt++) {
        #pragma unroll
        for (int half = 0; half < 2; half++) {
            l[mt][half] += __shfl_xor_sync(0xffffffffu, l[mt][half], 1);
            l[mt][half] += __shfl_xor_sync(0xffffffffu, l[mt][half], 2);
        }
        float il0 = 1.f / l[mt][0], il1 = 1.f / l[mt][1];
        size_t ob0 = ((size_t)(b * Sl + qt * 128 + row_base + mt * 16) * Hn + h) * 64;
        size_t ob1 = ((size_t)(b * Sl + qt * 128 + row_base + mt * 16 + 8) * Hn + h) * 64;
        #pragma unroll
        for (int nt = 0; nt < 8; nt++) {
            int dcol = nt * 8 + 2 * c4;
            *(float2*)&o[ob0 + dcol] = make_float2(accO[mt][nt][0] * il0, accO[mt][nt][1] * il0);
            *(float2*)&o[ob1 + dcol] = make_float2(accO[mt][nt][2] * il1, accO[mt][nt][3] * il1);
        }
    }
}

// ---------------------------------------------------------------------------
// Chunked delta-rule memory scan (side stream).
// ---------------------------------------------------------------------------
__global__ __launch_bounds__(256)
void memscan_kernel(const float* __restrict__ z,
                    const float* __restrict__ M_init,
                    const float* __restrict__ w_eta, const float* __restrict__ b_eta,
                    const float* __restrict__ w_alpha, const float* __restrict__ b_alpha,
                    const float* __restrict__ w_gate, const float* __restrict__ b_gate,
                    float* __restrict__ mem_out) {
    __shared__ float Ms[64][65];
    __shared__ float chs[64][65];
    __shared__ float red2[16][64];
    __shared__ float se[64], sa[64], sg[64], nrm[64];
    __shared__ float kmean[64], vt[64], diffv[64];
    __shared__ float swe[64], swa[64], swg[64];
    __shared__ float redw[8];
    __shared__ float sc_eta, sc_alpha, sc_gate, sc_scale;

    int b = blockIdx.x;
    int tid = threadIdx.x;
    int tx = tid & 15, ty = tid >> 4;
    int lane = tid & 31, warp = tid >> 5;
    int tok = tid >> 2, part = tid & 3;
    float be = b_eta[0], ba = b_alpha[0], bg = b_gate[0];

    if (tid < 64) { swe[tid] = w_eta[tid]; swa[tid] = w_alpha[tid]; swg[tid] = w_gate[tid]; }
    #pragma unroll
    for (int i = 0; i < 16; i++) {
        int idx = tid + i * 256;
        Ms[idx >> 6][idx & 63] = M_init[idx];
    }
    __syncthreads();

    for (int c = 0; c < NCH; c++) {
        #pragma unroll
        for (int i = 0; i < 16; i++) {
            int idx = tid + i * 256;
            chs[idx >> 6][idx & 63] = z[((size_t)b * Sl + c * 64 + (idx >> 6)) * 64 + (idx & 63)];
        }
        __syncthreads();

        float o4[4][4] = {};
        #pragma unroll
        for (int d = 0; d < 64; d++) {
            float a0 = chs[ty*4+0][d], a1 = chs[ty*4+1][d];
            float a2 = chs[ty*4+2][d], a3 = chs[ty*4+3][d];
            float m0 = Ms[tx*4+0][d], m1 = Ms[tx*4+1][d];
            float m2 = Ms[tx*4+2][d], m3 = Ms[tx*4+3][d];
            o4[0][0] += a0*m0; o4[0][1] += a0*m1; o4[0][2] += a0*m2; o4[0][3] += a0*m3;
            o4[1][0] += a1*m0; o4[1][1] += a1*m1; o4[1][2] += a1*m2; o4[1][3] += a1*m3;
            o4[2][0] += a2*m0; o4[2][1] += a2*m1; o4[2][2] += a2*m2; o4[2][3] += a2*m3;
            o4[3][0] += a3*m0; o4[3][1] += a3*m1; o4[3][2] += a3*m2; o4[3][3] += a3*m3;
        }
        #pragma unroll
        for (int i = 0; i < 4; i++)
            #pragma unroll
            for (int j = 0; j < 4; j++)
                mem_out[((size_t)b * Sl + c * 64 + ty * 4 + i) * 64 + tx * 4 + j] = o4[i][j];
        #pragma unroll
        for (int j = 0; j < 4; j++)
            red2[ty][tx * 4 + j] = o4[0][j] + o4[1][j] + o4[2][j] + o4[3][j];
        __syncthreads();

        {
            float de = 0.f, da = 0.f, dg = 0.f, nn = 0.f;
            int d0 = part * 16;
            #pragma unroll
            for (int dd = 0; dd < 16; dd++) {
                float xv = chs[tok][d0 + dd];
                de = fmaf(xv, swe[d0 + dd], de);
                da = fmaf(xv, swa[d0 + dd], da);
                dg = fmaf(xv, swg[d0 + dd], dg);
                nn = fmaf(xv, xv, nn);
            }
            de += __shfl_xor_sync(0xffffffffu, de, 1); de += __shfl_xor_sync(0xffffffffu, de, 2);
            da += __shfl_xor_sync(0xffffffffu, da, 1); da += __shfl_xor_sync(0xffffffffu, da, 2);
            dg += __shfl_xor_sync(0xffffffffu, dg, 1); dg += __shfl_xor_sync(0xffffffffu, dg, 2);
            nn += __shfl_xor_sync(0xffffffffu, nn, 1); nn += __shfl_xor_sync(0xffffffffu, nn, 2);
            if (part == 0) {
                se[tok] = 0.2f / (1.f + __expf(-(de + be)));
                sa[tok] = 0.5f + 0.5f / (1.f + __expf(-(da + ba)));
                sg[tok] = 1.f / (1.f + __expf(-(dg + bg)));
                nrm[tok] = fmaxf(sqrtf(nn), 1e-6f);
            }
        }
        __syncthreads();

        {
            float s = 0.f, s2 = 0.f;
            #pragma unroll
            for (int t = 0; t < 16; t++) s += chs[part * 16 + t][tok] / nrm[part * 16 + t];
            #pragma unroll
            for (int yy = 0; yy < 4; yy++) s2 += red2[part * 4 + yy][tok];
            s  += __shfl_xor_sync(0xffffffffu, s, 1);  s  += __shfl_xor_sync(0xffffffffu, s, 2);
            s2 += __shfl_xor_sync(0xffffffffu, s2, 1); s2 += __shfl_xor_sync(0xffffffffu, s2, 2);
            if (part == 0) { kmean[tok] = s * (1.f / 64.f); vt[tok] = s2 * (1.f / 64.f); }
        }
        __syncthreads();

        if (tid < 32) {
            float e = se[tid] + se[tid + 32];
            float a = sa[tid] + sa[tid + 32];
            float gg = sg[tid] + sg[tid + 32];
            #pragma unroll
            for (int st = 16; st; st >>= 1) {
                e  += __shfl_xor_sync(0xffffffffu, e, st);
                a  += __shfl_xor_sync(0xffffffffu, a, st);
                gg += __shfl_xor_sync(0xffffffffu, gg, st);
            }
            if (tid == 0) {
                sc_eta = e * (1.f / 64.f);
                sc_alpha = a * (1.f / 64.f);
                sc_gate = gg * (1.f / 64.f);
            }
        }
        {
            float s = 0.f;
            int d0 = part * 16;
            #pragma unroll
            for (int dd = 0; dd < 16; dd++)
                s = fmaf(Ms[tok][d0 + dd], kmean[d0 + dd], s);
            s += __shfl_xor_sync(0xffffffffu, s, 1);
            s += __shfl_xor_sync(0xffffffffu, s, 2);
            if (part == 0) diffv[tok] = vt[tok] - s;
        }
        __syncthreads();

        float eg = sc_eta * sc_gate, al = sc_alpha;
        float ss2 = 0.f;
        #pragma unroll
        for (int i = 0; i < 16; i++) {
            int idx = tid + i * 256;
            int vv = idx >> 6, d = idx & 63;
            float mn = al * Ms[vv][d] + eg * diffv[vv] * kmean[d];
            Ms[vv][d] = mn;
            ss2 = fmaf(mn, mn, ss2);
        }
        #pragma unroll
        for (int st = 16; st; st >>= 1) ss2 += __shfl_xor_sync(0xffffffffu, ss2, st);
        if (lane == 0) redw[warp] = ss2;
        __syncthreads();
        if (tid == 0) {
            float fro = sqrtf(redw[0] + redw[1] + redw[2] + redw[3] +
                              redw[4] + redw[5] + redw[6] + redw[7]);
            sc_scale = fminf(1.f, 30.f / fmaxf(fro, 1e-6f));
        }
        __syncthreads();
        #pragma unroll
        for (int i = 0; i < 16; i++) {
            int idx = tid + i * 256;
            Ms[idx >> 6][idx & 63] *= sc_scale;
        }
        __syncthreads();
    }
}

// ---------------------------------------------------------------------------
extern "C" void kernel_launch(void* const* d_in, const int* in_sizes, int n_in,
                              void* d_out, int out_size) {
    const float* x       = (const float*)d_in[0];
    const float* Wq      = (const float*)d_in[1];
    const float* Wk      = (const float*)d_in[2];
    const float* Wv      = (const float*)d_in[3];
    const float* Wo      = (const float*)d_in[4];
    const float* Wmemin  = (const float*)d_in[5];
    const float* Wmemout = (const float*)d_in[6];
    const float* M_init  = (const float*)d_in[7];
    const float* w_eta   = (const float*)d_in[8];
    const float* b_eta   = (const float*)d_in[9];
    const float* w_alpha = (const float*)d_in[10];
    const float* b_alpha = (const float*)d_in[11];
    const float* w_gate  = (const float*)d_in[12];
    const float* b_gate  = (const float*)d_in[13];
    float* out = (float*)d_out;

    float *q, *k, *attn, *z, *mem;
    uint32_t *q2, *k2, *v2;
    cudaGetSymbolAddress((void**)&q, g_q);
    cudaGetSymbolAddress((void**)&k, g_k);
    cudaGetSymbolAddress((void**)&attn, g_attn);
    cudaGetSymbolAddress((void**)&z, g_z);
    cudaGetSymbolAddress((void**)&mem, g_mem);
    cudaGetSymbolAddress((void**)&q2, g_q2);
    cudaGetSymbolAddress((void**)&k2, g_k2);
    cudaGetSymbolAddress((void**)&v2, g_v2);

    static cudaStream_t s2 = nullptr;
    static cudaEvent_t evZ = nullptr, evM = nullptr;
    static int inited = 0;
    if (!inited) {
        cudaStreamCreateWithFlags(&s2, cudaStreamNonBlocking);
        cudaEventCreateWithFlags(&evZ, cudaEventDisableTiming);
        cudaEventCreateWithFlags(&evM, cudaEventDisableTiming);
        cudaFuncSetAttribute(attn_kernel,
                             cudaFuncAttributeMaxDynamicSharedMemorySize, ATTN_BYTES);
        inited = 1;
    }

    // Fused projections (q, k fp32; v tf32 sigma-paired; z fp32)
    proj_kernel<<<dim3(25, 32), 256>>>(x, Wq, Wk, Wv, Wmemin, q, k, v2, z);

    // Fork serial memscan onto side stream (depends on z)
    cudaEventRecord(evZ, 0);
    cudaStreamWaitEvent(s2, evZ, 0);
    memscan_kernel<<<Bsz, 256, 0, s2>>>(z, M_init, w_eta, b_eta, w_alpha, b_alpha,
                                        w_gate, b_gate, mem);
    cudaEventRecord(evM, s2);

    // RoPE + tf32 convert + permute (q scaled)
    {
        int total = Bsz * Sl * (Hn + HKn) * 32;
        rope_kernel<<<(total + 255) / 256, 256>>>(q, k, q2, k2);
    }

    // Attention
    attn_kernel<<<dim3(Sl/128, Bsz*Hn), 128, ATTN_BYTES>>>(q2, k2, v2, attn);

    // Join memscan, then fused output GEMM
    cudaStreamWaitEvent((cudaStream_t)0, evM, 0);
    dual_gemm_kernel<<<dim3(16, 32), 256>>>(attn, Wo, Hn*HDn,
                                            mem, Wmemout, DVn, out, Dm);
}

// round 13
// speedup vs baseline: 1.2967x; 1.1960x over previous
#include <cuda_runtime.h>
#include <math.h>
#include <stdint.h>

#define Bsz 2
#define Sl  2048
#define Dm  1024
#define Hn  16
#define HKn 4
#define HDn 64
#define DKn 64
#define DVn 64
#define NCH 32
#define MS  (Bsz*Sl)

__device__ float    g_q[Bsz*Sl*Hn*HDn];        // fp32 q (pre-rope)
__device__ float    g_k[Bsz*Sl*HKn*HDn];       // fp32 k (pre-rope)
__device__ float    g_attn[Bsz*Sl*Hn*HDn];
__device__ float    g_z[Bsz*Sl*DKn];
__device__ float    g_mem[Bsz*Sl*DVn];
__device__ uint32_t g_q2[Bsz*Sl*Hn*HDn];       // tf32, col-permuted, scaled
__device__ uint32_t g_k2[Bsz*Sl*HKn*HDn];      // tf32, col-permuted
__device__ uint32_t g_v2[Bsz*HKn*(Sl/2)*128];  // tf32, sigma-permuted row pairs

__device__ __forceinline__ uint32_t f2tf(float x) {
    uint32_t u; asm("cvt.rna.tf32.f32 %0, %1;" : "=r"(u) : "f"(x)); return u;
}
__device__ __forceinline__ float ex2(float x) {
    float y; asm("ex2.approx.f32 %0, %1;" : "=f"(y) : "f"(x)); return y;
}
__device__ __forceinline__ int colperm(int d) {   // per-8 group: 0,4,1,5,2,6,3,7
    return (d & ~7) | ((d & 3) << 1) | ((d >> 2) & 1);
}
__device__ __forceinline__ unsigned su32(const void* p) {
    unsigned a;
    asm("{.reg .u64 t; cvta.to.shared.u64 t, %1; cvt.u32.u64 %0, t;}" : "=r"(a) : "l"(p));
    return a;
}
#define CP16(dst, src) asm volatile("cp.async.ca.shared.global [%0], [%1], 16;" :: "r"(dst), "l"(src))
#define CPCOMMIT()     asm volatile("cp.async.commit_group;")
#define CPWAITALL()    asm volatile("cp.async.wait_group 0;")

// mma.sync m16n8k8 tf32
__device__ __forceinline__ void mma8(float d[4], const uint32_t a[4], const uint32_t b[2]) {
    asm volatile(
        "mma.sync.aligned.m16n8k8.row.col.f32.tf32.tf32.f32 "
        "{%0,%1,%2,%3}, {%4,%5,%6,%7}, {%8,%9}, {%0,%1,%2,%3};"
        : "+f"(d[0]), "+f"(d[1]), "+f"(d[2]), "+f"(d[3])
        : "r"(a[0]), "r"(a[1]), "r"(a[2]), "r"(a[3]), "r"(b[0]), "r"(b[1]));
}

// ===========================================================================
// TF32 GEMM core v2: BM=128, BN=128, BK=16, 256 thr (8 warps, 4x2),
// warp tile 32x64. Double-buffered smem, 1 sync per BK step.
// Strides 136 (== 8 mod 32): A frag banks 8*c4+g, B frag 8*c4+g+const — clean.
// ===========================================================================
#define AS_STR 136
#define BS_STR 136

__device__ __forceinline__ void g_load(const float* __restrict__ A,
                                       const float* __restrict__ B,
                                       int K, int N, int row0, int col0, int k0,
                                       int tid, float4 ar[2], float4 br[2]) {
    #pragma unroll
    for (int i = 0; i < 2; i++) {
        int vec = tid + i * 256;
        int m = vec >> 2, kq = vec & 3;
        ar[i] = *(const float4*)&A[(size_t)(row0 + m) * K + k0 + kq * 4];
    }
    #pragma unroll
    for (int i = 0; i < 2; i++) {
        int vec = tid + i * 256;
        int kk = vec >> 5, nq = vec & 31;
        int col = col0 + nq * 4;
        br[i] = (col < N) ? *(const float4*)&B[(size_t)(k0 + kk) * N + col]
                          : make_float4(0.f, 0.f, 0.f, 0.f);
    }
}

__device__ __forceinline__ void g_sts(uint32_t* As, uint32_t* Bs, int tid,
                                      const float4 ar[2], const float4 br[2]) {
    #pragma unroll
    for (int i = 0; i < 2; i++) {
        int vec = tid + i * 256;
        int m = vec >> 2, kq = vec & 3;
        As[(kq * 4 + 0) * AS_STR + m] = f2tf(ar[i].x);
        As[(kq * 4 + 1) * AS_STR + m] = f2tf(ar[i].y);
        As[(kq * 4 + 2) * AS_STR + m] = f2tf(ar[i].z);
        As[(kq * 4 + 3) * AS_STR + m] = f2tf(ar[i].w);
    }
    #pragma unroll
    for (int i = 0; i < 2; i++) {
        int vec = tid + i * 256;
        int kk = vec >> 5, nq = vec & 31;
        uint4 t;
        t.x = f2tf(br[i].x); t.y = f2tf(br[i].y);
        t.z = f2tf(br[i].z); t.w = f2tf(br[i].w);
        *(uint4*)&Bs[kk * BS_STR + nq * 4] = t;
    }
}

__device__ __forceinline__ void g_mma(const uint32_t* As, const uint32_t* Bs,
                                      int lane, int wm, int wn, float d[2][8][4]) {
    #pragma unroll
    for (int ks = 0; ks < 16; ks += 8) {
        int kc = ks + (lane & 3);
        uint32_t a[2][4], b[8][2];
        #pragma unroll
        for (int mt = 0; mt < 2; mt++) {
            int r = wm * 32 + mt * 16 + (lane >> 2);
            a[mt][0] = As[kc * AS_STR + r];
            a[mt][1] = As[kc * AS_STR + r + 8];
            a[mt][2] = As[(kc + 4) * AS_STR + r];
            a[mt][3] = As[(kc + 4) * AS_STR + r + 8];
        }
        #pragma unroll
        for (int nt = 0; nt < 8; nt++) {
            int n = wn * 64 + nt * 8 + (lane >> 2);
            b[nt][0] = Bs[kc * BS_STR + n];
            b[nt][1] = Bs[(kc + 4) * BS_STR + n];
        }
        #pragma unroll
        for (int mt = 0; mt < 2; mt++)
            #pragma unroll
            for (int nt = 0; nt < 8; nt++)
                mma8(d[mt][nt], a[mt], b[nt]);
    }
}

__device__ __forceinline__ void g_epilogue(float d[2][8][4], float* __restrict__ C,
                                           int N, int row0, int col0,
                                           int lane, int wm, int wn) {
    #pragma unroll
    for (int mt = 0; mt < 2; mt++) {
        #pragma unroll
        for (int nt = 0; nt < 8; nt++) {
            int r = row0 + wm * 32 + mt * 16 + (lane >> 2);
            int cc = col0 + wn * 64 + nt * 8 + 2 * (lane & 3);
            if (cc < N) {
                *(float2*)&C[(size_t)r * N + cc]       = make_float2(d[mt][nt][0], d[mt][nt][1]);
                *(float2*)&C[(size_t)(r + 8) * N + cc] = make_float2(d[mt][nt][2], d[mt][nt][3]);
            }
        }
    }
}

// V store into sigma-paired tf32 layout:
// V'[(b,kh)][ (s>>3)*4 + ((s>>1)&3) ][ 2d + (s&1) ]
__device__ __forceinline__ void v2store(uint32_t* __restrict__ v2, int r, int cc, float val) {
    int s = r & (Sl - 1), b = r >> 11;
    int kh = cc >> 6, d = cc & 63;
    size_t idx = ((size_t)(b * HKn + kh) * (Sl / 2) + (s >> 3) * 4 + ((s >> 1) & 3)) * 128
               + 2 * d + (s & 1);
    v2[idx] = f2tf(val);
}

// ---------------------------------------------------------------------------
// Fused projection GEMM: x @ {Wq|Wk|Wv|Wmemin}. grid=(13,32), block=256.
// Col tiles: 0..7 Wq(1024), 8..9 Wk(256), 10..11 Wv(256), 12 Wz(64, guarded).
// ---------------------------------------------------------------------------
__global__ __launch_bounds__(256, 2)
void proj_kernel(const float* __restrict__ x,
                 const float* __restrict__ Wq, const float* __restrict__ Wk,
                 const float* __restrict__ Wv, const float* __restrict__ Wz,
                 float* __restrict__ q, float* __restrict__ kout,
                 uint32_t* __restrict__ v2, float* __restrict__ z) {
    __shared__ uint32_t As[2][16 * AS_STR];
    __shared__ uint32_t Bs[2][16 * BS_STR];
    int tid = threadIdx.x;
    int lane = tid & 31, warp = tid >> 5;
    int wm = warp >> 1, wn = warp & 1;
    int ct = blockIdx.x;
    int row0 = blockIdx.y * 128;
    const float* B; float* C; int N, col0; bool isV = false;
    if (ct < 8)       { B = Wq; C = q;    N = 1024; col0 = ct * 128; }
    else if (ct < 10) { B = Wk; C = kout; N = 256;  col0 = (ct - 8) * 128; }
    else if (ct < 12) { B = Wv; C = nullptr; N = 256; col0 = (ct - 10) * 128; isV = true; }
    else              { B = Wz; C = z;    N = 64;   col0 = 0; }

    float d[2][8][4] = {};
    float4 ar[2], br[2];
    g_load(x, B, 1024, N, row0, col0, 0, tid, ar, br);
    g_sts(As[0], Bs[0], tid, ar, br);
    __syncthreads();
    for (int k0 = 0; k0 < 1024; k0 += 16) {
        int cur = (k0 >> 4) & 1;
        if (k0 + 16 < 1024) g_load(x, B, 1024, N, row0, col0, k0 + 16, tid, ar, br);
        g_mma(As[cur], Bs[cur], lane, wm, wn, d);
        if (k0 + 16 < 1024) g_sts(As[cur ^ 1], Bs[cur ^ 1], tid, ar, br);
        __syncthreads();
    }
    if (!isV) {
        g_epilogue(d, C, N, row0, col0, lane, wm, wn);
    } else {
        #pragma unroll
        for (int mt = 0; mt < 2; mt++) {
            #pragma unroll
            for (int nt = 0; nt < 8; nt++) {
                int r = row0 + wm * 32 + mt * 16 + (lane >> 2);
                int cc = col0 + wn * 64 + nt * 8 + 2 * (lane & 3);
                v2store(v2, r,     cc,     d[mt][nt][0]);
                v2store(v2, r,     cc + 1, d[mt][nt][1]);
                v2store(v2, r + 8, cc,     d[mt][nt][2]);
                v2store(v2, r + 8, cc + 1, d[mt][nt][3]);
            }
        }
    }
}

// ---------------------------------------------------------------------------
// Dual GEMM: C = A1@B1 + A2@B2. grid=(8,32), block=256.
// ---------------------------------------------------------------------------
__global__ __launch_bounds__(256, 2)
void dual_gemm_kernel(const float* __restrict__ A1, const float* __restrict__ B1, int K1,
                      const float* __restrict__ A2, const float* __restrict__ B2, int K2,
                      float* __restrict__ C, int N) {
    __shared__ uint32_t As[2][16 * AS_STR];
    __shared__ uint32_t Bs[2][16 * BS_STR];
    int tid = threadIdx.x;
    int lane = tid & 31, warp = tid >> 5;
    int wm = warp >> 1, wn = warp & 1;
    int row0 = blockIdx.y * 128, col0 = blockIdx.x * 128;
    float d[2][8][4] = {};
    float4 ar[2], br[2];
    #pragma unroll
    for (int ph = 0; ph < 2; ph++) {
        const float* A = ph ? A2 : A1;
        const float* B = ph ? B2 : B1;
        int K = ph ? K2 : K1;
        g_load(A, B, K, N, row0, col0, 0, tid, ar, br);
        g_sts(As[0], Bs[0], tid, ar, br);
        __syncthreads();
        for (int k0 = 0; k0 < K; k0 += 16) {
            int cur = (k0 >> 4) & 1;
            if (k0 + 16 < K) g_load(A, B, K, N, row0, col0, k0 + 16, tid, ar, br);
            g_mma(As[cur], Bs[cur], lane, wm, wn, d);
            if (k0 + 16 < K) g_sts(As[cur ^ 1], Bs[cur ^ 1], tid, ar, br);
            __syncthreads();
        }
    }
    g_epilogue(d, C, N, row0, col0, lane, wm, wn);
}

// ---------------------------------------------------------------------------
// RoPE + tf32 convert + column permute. Q pre-scaled into log2 domain.
// ---------------------------------------------------------------------------
#define QSCALE 0.18033688f   // 0.125 * log2(e)

__global__ void rope_kernel(const float* __restrict__ qp, const float* __restrict__ kp,
                            uint32_t* __restrict__ q2, uint32_t* __restrict__ k2) {
    int idx = blockIdx.x * blockDim.x + threadIdx.x;
    const int qtot = Bsz * Sl * Hn * 32;
    const int ktot = Bsz * Sl * HKn * 32;
    const float* src; uint32_t* dst; int nheads; bool isq;
    if (idx < qtot) { src = qp; dst = q2; nheads = Hn; isq = true; }
    else { idx -= qtot; if (idx >= ktot) return; src = kp; dst = k2; nheads = HKn; isq = false; }
    int j = idx & 31;
    int h = (idx >> 5) % nheads;
    int s = ((idx >> 5) / nheads) % Sl;
    int b = idx / (32 * nheads * Sl);
    float inv = powf(500000.0f, -(float)(2 * j) / 64.0f);
    float ang = (float)s * inv;
    float c, sn;
    __sincosf(ang, &sn, &c);
    size_t base = ((size_t)(b * Sl + s) * nheads + h) * 64;
    float u1 = src[base + j], u2 = src[base + j + 32];
    float r1 = u1 * c - u2 * sn;
    float r2 = u2 * c + u1 * sn;
    if (isq) { r1 *= QSCALE; r2 *= QSCALE; }
    dst[base + colperm(j)]      = f2tf(r1);
    dst[base + colperm(j + 32)] = f2tf(r2);
}

// ---------------------------------------------------------------------------
// TF32 flash attention v5 (unchanged from R12 best): no-max softmax,
// sigma-permuted V (QK C-frag == PV A-frag), 128 threads, 2 CTAs/SM.
// ---------------------------------------------------------------------------
#define QST 72
#define KST 72
#define VST 144
#define ATTN_WORDS (128*QST + 2*64*KST + 2*32*VST)
#define ATTN_BYTES (ATTN_WORDS * 4)

__global__ __launch_bounds__(128, 2)
void attn_kernel(const uint32_t* __restrict__ q2, const uint32_t* __restrict__ k2,
                 const uint32_t* __restrict__ v2, float* __restrict__ o) {
    extern __shared__ uint32_t smu[];
    uint32_t* qs = smu;                 // [r:128][d':64] stride 72
    uint32_t* ks = qs + 128 * QST;      // 2 x [c:64][d':64] stride 72
    uint32_t* vs = ks + 2 * 64 * KST;   // 2 x [row':32][2d+slot:128] stride 144

    int qt = (int)gridDim.x - 1 - (int)blockIdx.x;   // longest tiles first
    int bh = blockIdx.y;
    int b = bh >> 4, h = bh & 15, kh = h >> 2;
    int tid = threadIdx.x;
    int lane = tid & 31, w = tid >> 5;
    int g = lane >> 2, c4 = lane & 3;
    int row_base = w * 32 + g;

    size_t qbase = ((size_t)(b * Sl + qt * 128) * Hn + h) * 64;
    size_t kvbase = ((size_t)(b * Sl) * HKn + kh) * 64;
    size_t v2base0 = (size_t)(b * HKn + kh) * (Sl / 2) * 128;
    int ktmax = 2 * qt + 1;

    // ---- prologue: cp.async Q tile + K0 + V0 ----
    {
        unsigned qd = su32(qs);
        #pragma unroll
        for (int i = 0; i < 16; i++) {
            int vec = tid + i * 128;
            int r = vec >> 4, ch = vec & 15;
            CP16(qd + (unsigned)((r * QST + ch * 4) * 4),
                 &q2[qbase + (size_t)r * Hn * 64 + ch * 4]);
        }
        unsigned kd = su32(ks), vd = su32(vs);
        #pragma unroll
        for (int i = 0; i < 8; i++) {
            int vec = tid + i * 128;
            int c = vec >> 4, dq = vec & 15;
            CP16(kd + (unsigned)((c * KST + dq * 4) * 4),
                 &k2[kvbase + (size_t)c * HKn * 64 + dq * 4]);
            int row = vec >> 5, ch = vec & 31;
            CP16(vd + (unsigned)((row * VST + ch * 4) * 4),
                 &v2[v2base0 + (size_t)row * 128 + ch * 4]);
        }
        CPCOMMIT();
    }

    float l[2][2] = {};
    float accO[2][8][4] = {};
    CPWAITALL();
    __syncthreads();

    for (int kt = 0; kt <= ktmax; kt++) {
        const uint32_t* kb = ks + (kt & 1) * 64 * KST;
        const uint32_t* vb = vs + (kt & 1) * 32 * VST;

        if (kt < ktmax) {
            unsigned kd = su32(ks + ((kt + 1) & 1) * 64 * KST);
            unsigned vd = su32(vs + ((kt + 1) & 1) * 32 * VST);
            size_t kbase = kvbase + (size_t)(kt + 1) * 64 * HKn * 64;
            size_t vbase = v2base0 + (size_t)(kt + 1) * 32 * 128;
            #pragma unroll
            for (int i = 0; i < 8; i++) {
                int vec = tid + i * 128;
                int c = vec >> 4, dq = vec & 15;
                CP16(kd + (unsigned)((c * KST + dq * 4) * 4),
                     &k2[kbase + (size_t)c * HKn * 64 + dq * 4]);
                int row = vec >> 5, ch = vec & 31;
                CP16(vd + (unsigned)((row * VST + ch * 4) * 4),
                     &v2[vbase + (size_t)row * 128 + ch * 4]);
            }
            CPCOMMIT();
        }

        // ---- QK^T: 32 q-rows x 64 kv-cols per warp ----
        float sc[2][8][4] = {};
        #pragma unroll
        for (int t8 = 0; t8 < 8; t8++) {
            int pc = t8 * 8 + 2 * c4;
            uint32_t a[2][4];
            #pragma unroll
            for (int mt = 0; mt < 2; mt++) {
                uint2 ua0 = *(const uint2*)&qs[(row_base + mt * 16) * QST + pc];
                uint2 ua1 = *(const uint2*)&qs[(row_base + mt * 16 + 8) * QST + pc];
                a[mt][0] = ua0.x; a[mt][1] = ua1.x; a[mt][2] = ua0.y; a[mt][3] = ua1.y;
            }
            #pragma unroll
            for (int nt = 0; nt < 8; nt++) {
                int n = nt * 8 + g;
                uint2 ub = *(const uint2*)&kb[n * KST + pc];
                uint32_t bb[2] = { ub.x, ub.y };
                mma8(sc[0][nt], a[0], bb);
                mma8(sc[1][nt], a[1], bb);
            }
        }

        // ---- causal mask ----
        if (kt >= 2 * qt) {
            #pragma unroll
            for (int mt = 0; mt < 2; mt++) {
                int rg0 = qt * 128 + row_base + mt * 16, rg1 = rg0 + 8;
                #pragma unroll
                for (int nt = 0; nt < 8; nt++) {
                    int cg = kt * 64 + nt * 8 + 2 * c4;
                    if (cg > rg0)     sc[mt][nt][0] = -1e30f;
                    if (cg + 1 > rg0) sc[mt][nt][1] = -1e30f;
                    if (cg > rg1)     sc[mt][nt][2] = -1e30f;
                    if (cg + 1 > rg1) sc[mt][nt][3] = -1e30f;
                }
            }
        }

        // ---- softmax numerator (log2 domain, no max subtraction) ----
        #pragma unroll
        for (int mt = 0; mt < 2; mt++) {
            #pragma unroll
            for (int nt = 0; nt < 8; nt++) {
                sc[mt][nt][0] = ex2(sc[mt][nt][0]); l[mt][0] += sc[mt][nt][0];
                sc[mt][nt][1] = ex2(sc[mt][nt][1]); l[mt][0] += sc[mt][nt][1];
                sc[mt][nt][2] = ex2(sc[mt][nt][2]); l[mt][1] += sc[mt][nt][2];
                sc[mt][nt][3] = ex2(sc[mt][nt][3]); l[mt][1] += sc[mt][nt][3];
            }
        }

        // ---- P @ V: C-fragment IS the A-fragment under sigma ----
        #pragma unroll
        for (int t = 0; t < 8; t++) {
            uint32_t a[2][4];
            #pragma unroll
            for (int mt = 0; mt < 2; mt++) {
                a[mt][0] = f2tf(sc[mt][t][0]);
                a[mt][1] = f2tf(sc[mt][t][2]);
                a[mt][2] = f2tf(sc[mt][t][1]);
                a[mt][3] = f2tf(sc[mt][t][3]);
            }
            int vrow = t * 4 + c4;
            #pragma unroll
            for (int nt = 0; nt < 8; nt++) {
                int dcol = nt * 8 + g;
                uint2 ub = *(const uint2*)&vb[vrow * VST + 2 * dcol];
                uint32_t bb[2] = { ub.x, ub.y };
                mma8(accO[0][nt], a[0], bb);
                mma8(accO[1][nt], a[1], bb);
            }
        }

        if (kt < ktmax) CPWAITALL();
        __syncthreads();
    }

    // ---- epilogue: reduce l across the 4-lane row group, then scale ----
    #pragma unroll
    for (int mt = 0; mt < 2; mt++) {
        #pragma unroll
        for (int half = 0; half < 2; half++) {
            l[mt][half] += __shfl_xor_sync(0xffffffffu, l[mt][half], 1);
            l[mt][half] += __shfl_xor_sync(0xffffffffu, l[mt][half], 2);
        }
        float il0 = 1.f / l[mt][0], il1 = 1.f / l[mt][1];
        size_t ob0 = ((size_t)(b * Sl + qt * 128 + row_base + mt * 16) * Hn + h) * 64;
        size_t ob1 = ((size_t)(b * Sl + qt * 128 + row_base + mt * 16 + 8) * Hn + h) * 64;
        #pragma unroll
        for (int nt = 0; nt < 8; nt++) {
            int dcol = nt * 8 + 2 * c4;
            *(float2*)&o[ob0 + dcol] = make_float2(accO[mt][nt][0] * il0, accO[mt][nt][1] * il0);
            *(float2*)&o[ob1 + dcol] = make_float2(accO[mt][nt][2] * il1, accO[mt][nt][3] * il1);
        }
    }
}

// ---------------------------------------------------------------------------
// Chunked delta-rule memory scan (side stream).
// ---------------------------------------------------------------------------
__global__ __launch_bounds__(256)
void memscan_kernel(const float* __restrict__ z,
                    const float* __restrict__ M_init,
                    const float* __restrict__ w_eta, const float* __restrict__ b_eta,
                    const float* __restrict__ w_alpha, const float* __restrict__ b_alpha,
                    const float* __restrict__ w_gate, const float* __restrict__ b_gate,
                    float* __restrict__ mem_out) {
    __shared__ float Ms[64][65];
    __shared__ float chs[64][65];
    __shared__ float red2[16][64];
    __shared__ float se[64], sa[64], sg[64], nrm[64];
    __shared__ float kmean[64], vt[64], diffv[64];
    __shared__ float swe[64], swa[64], swg[64];
    __shared__ float redw[8];
    __shared__ float sc_eta, sc_alpha, sc_gate, sc_scale;

    int b = blockIdx.x;
    int tid = threadIdx.x;
    int tx = tid & 15, ty = tid >> 4;
    int lane = tid & 31, warp = tid >> 5;
    int tok = tid >> 2, part = tid & 3;
    float be = b_eta[0], ba = b_alpha[0], bg = b_gate[0];

    if (tid < 64) { swe[tid] = w_eta[tid]; swa[tid] = w_alpha[tid]; swg[tid] = w_gate[tid]; }
    #pragma unroll
    for (int i = 0; i < 16; i++) {
        int idx = tid + i * 256;
        Ms[idx >> 6][idx & 63] = M_init[idx];
    }
    __syncthreads();

    for (int c = 0; c < NCH; c++) {
        #pragma unroll
        for (int i = 0; i < 16; i++) {
            int idx = tid + i * 256;
            chs[idx >> 6][idx & 63] = z[((size_t)b * Sl + c * 64 + (idx >> 6)) * 64 + (idx & 63)];
        }
        __syncthreads();

        float o4[4][4] = {};
        #pragma unroll
        for (int d = 0; d < 64; d++) {
            float a0 = chs[ty*4+0][d], a1 = chs[ty*4+1][d];
            float a2 = chs[ty*4+2][d], a3 = chs[ty*4+3][d];
            float m0 = Ms[tx*4+0][d], m1 = Ms[tx*4+1][d];
            float m2 = Ms[tx*4+2][d], m3 = Ms[tx*4+3][d];
            o4[0][0] += a0*m0; o4[0][1] += a0*m1; o4[0][2] += a0*m2; o4[0][3] += a0*m3;
            o4[1][0] += a1*m0; o4[1][1] += a1*m1; o4[1][2] += a1*m2; o4[1][3] += a1*m3;
            o4[2][0] += a2*m0; o4[2][1] += a2*m1; o4[2][2] += a2*m2; o4[2][3] += a2*m3;
            o4[3][0] += a3*m0; o4[3][1] += a3*m1; o4[3][2] += a3*m2; o4[3][3] += a3*m3;
        }
        #pragma unroll
        for (int i = 0; i < 4; i++)
            #pragma unroll
            for (int j = 0; j < 4; j++)
                mem_out[((size_t)b * Sl + c * 64 + ty * 4 + i) * 64 + tx * 4 + j] = o4[i][j];
        #pragma unroll
        for (int j = 0; j < 4; j++)
            red2[ty][tx * 4 + j] = o4[0][j] + o4[1][j] + o4[2][j] + o4[3][j];
        __syncthreads();

        {
            float de = 0.f, da = 0.f, dg = 0.f, nn = 0.f;
            int d0 = part * 16;
            #pragma unroll
            for (int dd = 0; dd < 16; dd++) {
                float xv = chs[tok][d0 + dd];
                de = fmaf(xv, swe[d0 + dd], de);
                da = fmaf(xv, swa[d0 + dd], da);
                dg = fmaf(xv, swg[d0 + dd], dg);
                nn = fmaf(xv, xv, nn);
            }
            de += __shfl_xor_sync(0xffffffffu, de, 1); de += __shfl_xor_sync(0xffffffffu, de, 2);
            da += __shfl_xor_sync(0xffffffffu, da, 1); da += __shfl_xor_sync(0xffffffffu, da, 2);
            dg += __shfl_xor_sync(0xffffffffu, dg, 1); dg += __shfl_xor_sync(0xffffffffu, dg, 2);
            nn += __shfl_xor_sync(0xffffffffu, nn, 1); nn += __shfl_xor_sync(0xffffffffu, nn, 2);
            if (part == 0) {
                se[tok] = 0.2f / (1.f + __expf(-(de + be)));
                sa[tok] = 0.5f + 0.5f / (1.f + __expf(-(da + ba)));
                sg[tok] = 1.f / (1.f + __expf(-(dg + bg)));
                nrm[tok] = fmaxf(sqrtf(nn), 1e-6f);
            }
        }
        __syncthreads();

        {
            float s = 0.f, s2 = 0.f;
            #pragma unroll
            for (int t = 0; t < 16; t++) s += chs[part * 16 + t][tok] / nrm[part * 16 + t];
            #pragma unroll
            for (int yy = 0; yy < 4; yy++) s2 += red2[part * 4 + yy][tok];
            s  += __shfl_xor_sync(0xffffffffu, s, 1);  s  += __shfl_xor_sync(0xffffffffu, s, 2);
            s2 += __shfl_xor_sync(0xffffffffu, s2, 1); s2 += __shfl_xor_sync(0xffffffffu, s2, 2);
            if (part == 0) { kmean[tok] = s * (1.f / 64.f); vt[tok] = s2 * (1.f / 64.f); }
        }
        __syncthreads();

        if (tid < 32) {
            float e = se[tid] + se[tid + 32];
            float a = sa[tid] + sa[tid + 32];
            float gg = sg[tid] + sg[tid + 32];
            #pragma unroll
            for (int st = 16; st; st >>= 1) {
                e  += __shfl_xor_sync(0xffffffffu, e, st);
                a  += __shfl_xor_sync(0xffffffffu, a, st);
                gg += __shfl_xor_sync(0xffffffffu, gg, st);
            }
            if (tid == 0) {
                sc_eta = e * (1.f / 64.f);
                sc_alpha = a * (1.f / 64.f);
                sc_gate = gg * (1.f / 64.f);
            }
        }
        {
            float s = 0.f;
            int d0 = part * 16;
            #pragma unroll
            for (int dd = 0; dd < 16; dd++)
                s = fmaf(Ms[tok][d0 + dd], kmean[d0 + dd], s);
            s += __shfl_xor_sync(0xffffffffu, s, 1);
            s += __shfl_xor_sync(0xffffffffu, s, 2);
            if (part == 0) diffv[tok] = vt[tok] - s;
        }
        __syncthreads();

        float eg = sc_eta * sc_gate, al = sc_alpha;
        float ss2 = 0.f;
        #pragma unroll
        for (int i = 0; i < 16; i++) {
            int idx = tid + i * 256;
            int vv = idx >> 6, d = idx & 63;
            float mn = al * Ms[vv][d] + eg * diffv[vv] * kmean[d];
            Ms[vv][d] = mn;
            ss2 = fmaf(mn, mn, ss2);
        }
        #pragma unroll
        for (int st = 16; st; st >>= 1) ss2 += __shfl_xor_sync(0xffffffffu, ss2, st);
        if (lane == 0) redw[warp] = ss2;
        __syncthreads();
        if (tid == 0) {
            float fro = sqrtf(redw[0] + redw[1] + redw[2] + redw[3] +
                              redw[4] + redw[5] + redw[6] + redw[7]);
            sc_scale = fminf(1.f, 30.f / fmaxf(fro, 1e-6f));
        }
        __syncthreads();
        #pragma unroll
        for (int i = 0; i < 16; i++) {
            int idx = tid + i * 256;
            Ms[idx >> 6][idx & 63] *= sc_scale;
        }
        __syncthreads();
    }
}

// ---------------------------------------------------------------------------
extern "C" void kernel_launch(void* const* d_in, const int* in_sizes, int n_in,
                              void* d_out, int out_size) {
    const float* x       = (const float*)d_in[0];
    const float* Wq      = (const float*)d_in[1];
    const float* Wk      = (const float*)d_in[2];
    const float* Wv      = (const float*)d_in[3];
    const float* Wo      = (const float*)d_in[4];
    const float* Wmemin  = (const float*)d_in[5];
    const float* Wmemout = (const float*)d_in[6];
    const float* M_init  = (const float*)d_in[7];
    const float* w_eta   = (const float*)d_in[8];
    const float* b_eta   = (const float*)d_in[9];
    const float* w_alpha = (const float*)d_in[10];
    const float* b_alpha = (const float*)d_in[11];
    const float* w_gate  = (const float*)d_in[12];
    const float* b_gate  = (const float*)d_in[13];
    float* out = (float*)d_out;

    float *q, *k, *attn, *z, *mem;
    uint32_t *q2, *k2, *v2;
    cudaGetSymbolAddress((void**)&q, g_q);
    cudaGetSymbolAddress((void**)&k, g_k);
    cudaGetSymbolAddress((void**)&attn, g_attn);
    cudaGetSymbolAddress((void**)&z, g_z);
    cudaGetSymbolAddress((void**)&mem, g_mem);
    cudaGetSymbolAddress((void**)&q2, g_q2);
    cudaGetSymbolAddress((void**)&k2, g_k2);
    cudaGetSymbolAddress((void**)&v2, g_v2);

    static cudaStream_t s2 = nullptr;
    static cudaEvent_t evZ = nullptr, evM = nullptr;
    static int inited = 0;
    if (!inited) {
        cudaStreamCreateWithFlags(&s2, cudaStreamNonBlocking);
        cudaEventCreateWithFlags(&evZ, cudaEventDisableTiming);
        cudaEventCreateWithFlags(&evM, cudaEventDisableTiming);
        cudaFuncSetAttribute(attn_kernel,
                             cudaFuncAttributeMaxDynamicSharedMemorySize, ATTN_BYTES);
        inited = 1;
    }

    // Fused projections (q, k fp32; v tf32 sigma-paired; z fp32)
    proj_kernel<<<dim3(13, 32), 256>>>(x, Wq, Wk, Wv, Wmemin, q, k, v2, z);

    // Fork serial memscan onto side stream (depends on z)
    cudaEventRecord(evZ, 0);
    cudaStreamWaitEvent(s2, evZ, 0);
    memscan_kernel<<<Bsz, 256, 0, s2>>>(z, M_init, w_eta, b_eta, w_alpha, b_alpha,
                                        w_gate, b_gate, mem);
    cudaEventRecord(evM, s2);

    // RoPE + tf32 convert + permute (q scaled)
    {
        int total = Bsz * Sl * (Hn + HKn) * 32;
        rope_kernel<<<(total + 255) / 256, 256>>>(q, k, q2, k2);
    }

    // Attention
    attn_kernel<<<dim3(Sl/128, Bsz*Hn), 128, ATTN_BYTES>>>(q2, k2, v2, attn);

    // Join memscan, then fused output GEMM
    cudaStreamWaitEvent((cudaStream_t)0, evM, 0);
    dual_gemm_kernel<<<dim3(8, 32), 256>>>(attn, Wo, Hn*HDn,
                                           mem, Wmemout, DVn, out, Dm);
}

// round 14
// speedup vs baseline: 1.3170x; 1.0156x over previous
#include <cuda_runtime.h>
#include <math.h>
#include <stdint.h>

#define Bsz 2
#define Sl  2048
#define Dm  1024
#define Hn  16
#define HKn 4
#define HDn 64
#define DKn 64
#define DVn 64
#define NCH 32
#define MS  (Bsz*Sl)

__device__ float    g_q[Bsz*Sl*Hn*HDn];        // fp32 q (pre-rope)
__device__ float    g_k[Bsz*Sl*HKn*HDn];       // fp32 k (pre-rope)
__device__ float    g_z[Bsz*Sl*DKn];           // fp32 z (memscan input)
__device__ uint32_t g_attn2[Bsz*Sl*Hn*HDn];    // tf32 attention output
__device__ uint32_t g_mem2[Bsz*Sl*DVn];        // tf32 memscan output
__device__ uint32_t g_q2[Bsz*Sl*Hn*HDn];       // tf32, col-permuted, scaled
__device__ uint32_t g_k2[Bsz*Sl*HKn*HDn];      // tf32, col-permuted
__device__ uint32_t g_v2[Bsz*HKn*(Sl/2)*128];  // tf32, sigma-permuted row pairs
// tf32 copies of inputs
__device__ uint32_t g_x2[Bsz*Sl*Dm];
__device__ uint32_t g_wq2[Dm*Hn*HDn];
__device__ uint32_t g_wk2[Dm*HKn*HDn];
__device__ uint32_t g_wv2[Dm*HKn*HDn];
__device__ uint32_t g_wz2[Dm*DKn];
__device__ uint32_t g_wo2[Hn*HDn*Dm];
__device__ uint32_t g_wmo2[DVn*Dm];

__device__ __forceinline__ uint32_t f2tf(float x) {
    uint32_t u; asm("cvt.rna.tf32.f32 %0, %1;" : "=r"(u) : "f"(x)); return u;
}
__device__ __forceinline__ float ex2(float x) {
    float y; asm("ex2.approx.f32 %0, %1;" : "=f"(y) : "f"(x)); return y;
}
__device__ __forceinline__ int colperm(int d) {   // per-8 group: 0,4,1,5,2,6,3,7
    return (d & ~7) | ((d & 3) << 1) | ((d >> 2) & 1);
}
__device__ __forceinline__ unsigned su32(const void* p) {
    unsigned a;
    asm("{.reg .u64 t; cvta.to.shared.u64 t, %1; cvt.u32.u64 %0, t;}" : "=r"(a) : "l"(p));
    return a;
}
#define CP16(dst, src) asm volatile("cp.async.ca.shared.global [%0], [%1], 16;" :: "r"(dst), "l"(src))
#define CPCOMMIT()     asm volatile("cp.async.commit_group;")
#define CPWAITALL()    asm volatile("cp.async.wait_group 0;")

// mma.sync m16n8k8 tf32
__device__ __forceinline__ void mma8(float d[4], const uint32_t a[4], const uint32_t b[2]) {
    asm volatile(
        "mma.sync.aligned.m16n8k8.row.col.f32.tf32.tf32.f32 "
        "{%0,%1,%2,%3}, {%4,%5,%6,%7}, {%8,%9}, {%0,%1,%2,%3};"
        : "+f"(d[0]), "+f"(d[1]), "+f"(d[2]), "+f"(d[3])
        : "r"(a[0]), "r"(a[1]), "r"(a[2]), "r"(a[3]), "r"(b[0]), "r"(b[1]));
}

// ---------------------------------------------------------------------------
// One-shot tf32 conversion of all GEMM operands.
// ---------------------------------------------------------------------------
__global__ void cvt_kernel(const float* __restrict__ x,  const float* __restrict__ wq,
                           const float* __restrict__ wk, const float* __restrict__ wv,
                           const float* __restrict__ wz, const float* __restrict__ wo,
                           const float* __restrict__ wmo,
                           uint32_t* __restrict__ x2,  uint32_t* __restrict__ wq2,
                           uint32_t* __restrict__ wk2, uint32_t* __restrict__ wv2,
                           uint32_t* __restrict__ wz2, uint32_t* __restrict__ wo2,
                           uint32_t* __restrict__ wmo2) {
    const int S0 = Bsz*Sl*Dm/4;          // x
    const int S1 = S0 + Dm*Hn*HDn/4;     // wq
    const int S2 = S1 + Dm*HKn*HDn/4;    // wk
    const int S3 = S2 + Dm*HKn*HDn/4;    // wv
    const int S4 = S3 + Dm*DKn/4;        // wz
    const int S5 = S4 + Hn*HDn*Dm/4;     // wo
    const int S6 = S5 + DVn*Dm/4;        // wmo
    int idx = blockIdx.x * blockDim.x + threadIdx.x;
    if (idx >= S6) return;
    const float* src; uint32_t* dst; int off;
    if (idx < S0)      { src = x;   dst = x2;   off = idx; }
    else if (idx < S1) { src = wq;  dst = wq2;  off = idx - S0; }
    else if (idx < S2) { src = wk;  dst = wk2;  off = idx - S1; }
    else if (idx < S3) { src = wv;  dst = wv2;  off = idx - S2; }
    else if (idx < S4) { src = wz;  dst = wz2;  off = idx - S3; }
    else if (idx < S5) { src = wo;  dst = wo2;  off = idx - S4; }
    else               { src = wmo; dst = wmo2; off = idx - S5; }
    float4 t = *(const float4*)&src[off * 4];
    uint4 u;
    u.x = f2tf(t.x); u.y = f2tf(t.y); u.z = f2tf(t.z); u.w = f2tf(t.w);
    *(uint4*)&dst[off * 4] = u;
}

// ===========================================================================
// TF32 GEMM core v3: BM=128, BN=128, BK=16, 256 thr (8 warps, 4x2),
// warp tile 32x64. Pure cp.async smem fill (operands pre-converted tf32).
// As [m:128][k:16] stride 36 (banks 4g+c4); Bs [k:16][n:128] stride 136
// (banks 8c4+g). Dynamic smem, double-buffered, 1 sync per BK step.
// ===========================================================================
#define AXS 36
#define BXS 136
#define GEMM_SM_WORDS (2*128*AXS + 2*16*BXS)
#define GEMM_SM_BYTES (GEMM_SM_WORDS * 4)

__device__ __forceinline__ void g_issue(const uint32_t* __restrict__ A,
                                        const uint32_t* __restrict__ B,
                                        int K, int N, int row0, int col0, int k0,
                                        int tid, unsigned Asd, unsigned Bsd) {
    #pragma unroll
    for (int i = 0; i < 2; i++) {
        int vec = tid + i * 256;
        int m = vec >> 2, kq = vec & 3;
        CP16(Asd + (unsigned)((m * AXS + kq * 4) * 4),
             &A[(size_t)(row0 + m) * K + k0 + kq * 4]);
        int kk = vec >> 5, nq = vec & 31;
        int col = col0 + nq * 4;
        if (col < N)
            CP16(Bsd + (unsigned)((kk * BXS + nq * 4) * 4),
                 &B[(size_t)(k0 + kk) * N + col]);
    }
}

__device__ __forceinline__ void g_mma(const uint32_t* As, const uint32_t* Bs,
                                      int lane, int wm, int wn, float d[2][8][4]) {
    #pragma unroll
    for (int ks = 0; ks < 16; ks += 8) {
        int kc = ks + (lane & 3);
        uint32_t a[2][4], b[8][2];
        #pragma unroll
        for (int mt = 0; mt < 2; mt++) {
            int r = wm * 32 + mt * 16 + (lane >> 2);
            a[mt][0] = As[r * AXS + kc];
            a[mt][1] = As[(r + 8) * AXS + kc];
            a[mt][2] = As[r * AXS + kc + 4];
            a[mt][3] = As[(r + 8) * AXS + kc + 4];
        }
        #pragma unroll
        for (int nt = 0; nt < 8; nt++) {
            int n = wn * 64 + nt * 8 + (lane >> 2);
            b[nt][0] = Bs[kc * BXS + n];
            b[nt][1] = Bs[(kc + 4) * BXS + n];
        }
        #pragma unroll
        for (int mt = 0; mt < 2; mt++)
            #pragma unroll
            for (int nt = 0; nt < 8; nt++)
                mma8(d[mt][nt], a[mt], b[nt]);
    }
}

__device__ __forceinline__ void g_epilogue(float d[2][8][4], float* __restrict__ C,
                                           int N, int row0, int col0,
                                           int lane, int wm, int wn) {
    #pragma unroll
    for (int mt = 0; mt < 2; mt++) {
        #pragma unroll
        for (int nt = 0; nt < 8; nt++) {
            int r = row0 + wm * 32 + mt * 16 + (lane >> 2);
            int cc = col0 + wn * 64 + nt * 8 + 2 * (lane & 3);
            if (cc < N) {
                *(float2*)&C[(size_t)r * N + cc]       = make_float2(d[mt][nt][0], d[mt][nt][1]);
                *(float2*)&C[(size_t)(r + 8) * N + cc] = make_float2(d[mt][nt][2], d[mt][nt][3]);
            }
        }
    }
}

// V store into sigma-paired tf32 layout:
// V'[(b,kh)][ (s>>3)*4 + ((s>>1)&3) ][ 2d + (s&1) ]
__device__ __forceinline__ void v2store(uint32_t* __restrict__ v2, int r, int cc, float val) {
    int s = r & (Sl - 1), b = r >> 11;
    int kh = cc >> 6, d = cc & 63;
    size_t idx = ((size_t)(b * HKn + kh) * (Sl / 2) + (s >> 3) * 4 + ((s >> 1) & 3)) * 128
               + 2 * d + (s & 1);
    v2[idx] = f2tf(val);
}

// ---------------------------------------------------------------------------
// Fused projection GEMM (tf32 inputs): grid=(13,32), block=256, dyn smem.
// ---------------------------------------------------------------------------
__global__ __launch_bounds__(256, 2)
void proj_kernel(const uint32_t* __restrict__ x,
                 const uint32_t* __restrict__ Wq, const uint32_t* __restrict__ Wk,
                 const uint32_t* __restrict__ Wv, const uint32_t* __restrict__ Wz,
                 float* __restrict__ q, float* __restrict__ kout,
                 uint32_t* __restrict__ v2, float* __restrict__ z) {
    extern __shared__ uint32_t gsm[];
    uint32_t* As = gsm;                    // 2 x 128 x AXS
    uint32_t* Bs = gsm + 2 * 128 * AXS;    // 2 x 16 x BXS
    int tid = threadIdx.x;
    int lane = tid & 31, warp = tid >> 5;
    int wm = warp >> 1, wn = warp & 1;
    int ct = blockIdx.x;
    int row0 = blockIdx.y * 128;
    const uint32_t* B; float* C; int N, col0; bool isV = false;
    if (ct < 8)       { B = Wq; C = q;    N = 1024; col0 = ct * 128; }
    else if (ct < 10) { B = Wk; C = kout; N = 256;  col0 = (ct - 8) * 128; }
    else if (ct < 12) { B = Wv; C = nullptr; N = 256; col0 = (ct - 10) * 128; isV = true; }
    else              { B = Wz; C = z;    N = 64;   col0 = 0; }

    float d[2][8][4] = {};
    unsigned Asd = su32(As), Bsd = su32(Bs);
    g_issue(x, B, 1024, N, row0, col0, 0, tid, Asd, Bsd);
    CPCOMMIT(); CPWAITALL();
    __syncthreads();
    for (int k0 = 0; k0 < 1024; k0 += 16) {
        int cur = (k0 >> 4) & 1;
        if (k0 + 16 < 1024) {
            g_issue(x, B, 1024, N, row0, col0, k0 + 16, tid,
                    Asd + (unsigned)((cur ^ 1) * 128 * AXS * 4),
                    Bsd + (unsigned)((cur ^ 1) * 16 * BXS * 4));
            CPCOMMIT();
        }
        g_mma(As + cur * 128 * AXS, Bs + cur * 16 * BXS, lane, wm, wn, d);
        if (k0 + 16 < 1024) CPWAITALL();
        __syncthreads();
    }
    if (!isV) {
        g_epilogue(d, C, N, row0, col0, lane, wm, wn);
    } else {
        #pragma unroll
        for (int mt = 0; mt < 2; mt++) {
            #pragma unroll
            for (int nt = 0; nt < 8; nt++) {
                int r = row0 + wm * 32 + mt * 16 + (lane >> 2);
                int cc = col0 + wn * 64 + nt * 8 + 2 * (lane & 3);
                v2store(v2, r,     cc,     d[mt][nt][0]);
                v2store(v2, r,     cc + 1, d[mt][nt][1]);
                v2store(v2, r + 8, cc,     d[mt][nt][2]);
                v2store(v2, r + 8, cc + 1, d[mt][nt][3]);
            }
        }
    }
}

// ---------------------------------------------------------------------------
// Dual GEMM (tf32 inputs): C = A1@B1 + A2@B2. grid=(8,32), block=256.
// ---------------------------------------------------------------------------
__global__ __launch_bounds__(256, 2)
void dual_gemm_kernel(const uint32_t* __restrict__ A1, const uint32_t* __restrict__ B1, int K1,
                      const uint32_t* __restrict__ A2, const uint32_t* __restrict__ B2, int K2,
                      float* __restrict__ C, int N) {
    extern __shared__ uint32_t gsm[];
    uint32_t* As = gsm;
    uint32_t* Bs = gsm + 2 * 128 * AXS;
    int tid = threadIdx.x;
    int lane = tid & 31, warp = tid >> 5;
    int wm = warp >> 1, wn = warp & 1;
    int row0 = blockIdx.y * 128, col0 = blockIdx.x * 128;
    float d[2][8][4] = {};
    unsigned Asd = su32(As), Bsd = su32(Bs);
    #pragma unroll
    for (int ph = 0; ph < 2; ph++) {
        const uint32_t* A = ph ? A2 : A1;
        const uint32_t* B = ph ? B2 : B1;
        int K = ph ? K2 : K1;
        g_issue(A, B, K, N, row0, col0, 0, tid, Asd, Bsd);
        CPCOMMIT(); CPWAITALL();
        __syncthreads();
        for (int k0 = 0; k0 < K; k0 += 16) {
            int cur = (k0 >> 4) & 1;
            if (k0 + 16 < K) {
                g_issue(A, B, K, N, row0, col0, k0 + 16, tid,
                        Asd + (unsigned)((cur ^ 1) * 128 * AXS * 4),
                        Bsd + (unsigned)((cur ^ 1) * 16 * BXS * 4));
                CPCOMMIT();
            }
            g_mma(As + cur * 128 * AXS, Bs + cur * 16 * BXS, lane, wm, wn, d);
            if (k0 + 16 < K) CPWAITALL();
            __syncthreads();
        }
    }
    g_epilogue(d, C, N, row0, col0, lane, wm, wn);
}

// ---------------------------------------------------------------------------
// RoPE + tf32 convert + column permute. Q pre-scaled into log2 domain.
// ---------------------------------------------------------------------------
#define QSCALE 0.18033688f   // 0.125 * log2(e)

__global__ void rope_kernel(const float* __restrict__ qp, const float* __restrict__ kp,
                            uint32_t* __restrict__ q2, uint32_t* __restrict__ k2) {
    int idx = blockIdx.x * blockDim.x + threadIdx.x;
    const int qtot = Bsz * Sl * Hn * 32;
    const int ktot = Bsz * Sl * HKn * 32;
    const float* src; uint32_t* dst; int nheads; bool isq;
    if (idx < qtot) { src = qp; dst = q2; nheads = Hn; isq = true; }
    else { idx -= qtot; if (idx >= ktot) return; src = kp; dst = k2; nheads = HKn; isq = false; }
    int j = idx & 31;
    int h = (idx >> 5) % nheads;
    int s = ((idx >> 5) / nheads) % Sl;
    int b = idx / (32 * nheads * Sl);
    float inv = powf(500000.0f, -(float)(2 * j) / 64.0f);
    float ang = (float)s * inv;
    float c, sn;
    __sincosf(ang, &sn, &c);
    size_t base = ((size_t)(b * Sl + s) * nheads + h) * 64;
    float u1 = src[base + j], u2 = src[base + j + 32];
    float r1 = u1 * c - u2 * sn;
    float r2 = u2 * c + u1 * sn;
    if (isq) { r1 *= QSCALE; r2 *= QSCALE; }
    dst[base + colperm(j)]      = f2tf(r1);
    dst[base + colperm(j + 32)] = f2tf(r2);
}

// ---------------------------------------------------------------------------
// TF32 flash attention v5 (R12/R13 best), epilogue now writes tf32.
// ---------------------------------------------------------------------------
#define QST 72
#define KST 72
#define VST 144
#define ATTN_WORDS (128*QST + 2*64*KST + 2*32*VST)
#define ATTN_BYTES (ATTN_WORDS * 4)

__global__ __launch_bounds__(128, 2)
void attn_kernel(const uint32_t* __restrict__ q2, const uint32_t* __restrict__ k2,
                 const uint32_t* __restrict__ v2, uint32_t* __restrict__ o2) {
    extern __shared__ uint32_t smu[];
    uint32_t* qs = smu;
    uint32_t* ks = qs + 128 * QST;
    uint32_t* vs = ks + 2 * 64 * KST;

    int qt = (int)gridDim.x - 1 - (int)blockIdx.x;
    int bh = blockIdx.y;
    int b = bh >> 4, h = bh & 15, kh = h >> 2;
    int tid = threadIdx.x;
    int lane = tid & 31, w = tid >> 5;
    int g = lane >> 2, c4 = lane & 3;
    int row_base = w * 32 + g;

    size_t qbase = ((size_t)(b * Sl + qt * 128) * Hn + h) * 64;
    size_t kvbase = ((size_t)(b * Sl) * HKn + kh) * 64;
    size_t v2base0 = (size_t)(b * HKn + kh) * (Sl / 2) * 128;
    int ktmax = 2 * qt + 1;

    {
        unsigned qd = su32(qs);
        #pragma unroll
        for (int i = 0; i < 16; i++) {
            int vec = tid + i * 128;
            int r = vec >> 4, ch = vec & 15;
            CP16(qd + (unsigned)((r * QST + ch * 4) * 4),
                 &q2[qbase + (size_t)r * Hn * 64 + ch * 4]);
        }
        unsigned kd = su32(ks), vd = su32(vs);
        #pragma unroll
        for (int i = 0; i < 8; i++) {
            int vec = tid + i * 128;
            int c = vec >> 4, dq = vec & 15;
            CP16(kd + (unsigned)((c * KST + dq * 4) * 4),
                 &k2[kvbase + (size_t)c * HKn * 64 + dq * 4]);
            int row = vec >> 5, ch = vec & 31;
            CP16(vd + (unsigned)((row * VST + ch * 4) * 4),
                 &v2[v2base0 + (size_t)row * 128 + ch * 4]);
        }
        CPCOMMIT();
    }

    float l[2][2] = {};
    float accO[2][8][4] = {};
    CPWAITALL();
    __syncthreads();

    for (int kt = 0; kt <= ktmax; kt++) {
        const uint32_t* kb = ks + (kt & 1) * 64 * KST;
        const uint32_t* vb = vs + (kt & 1) * 32 * VST;

        if (kt < ktmax) {
            unsigned kd = su32(ks + ((kt + 1) & 1) * 64 * KST);
            unsigned vd = su32(vs + ((kt + 1) & 1) * 32 * VST);
            size_t kbase = kvbase + (size_t)(kt + 1) * 64 * HKn * 64;
            size_t vbase = v2base0 + (size_t)(kt + 1) * 32 * 128;
            #pragma unroll
            for (int i = 0; i < 8; i++) {
                int vec = tid + i * 128;
                int c = vec >> 4, dq = vec & 15;
                CP16(kd + (unsigned)((c * KST + dq * 4) * 4),
                     &k2[kbase + (size_t)c * HKn * 64 + dq * 4]);
                int row = vec >> 5, ch = vec & 31;
                CP16(vd + (unsigned)((row * VST + ch * 4) * 4),
                     &v2[vbase + (size_t)row * 128 + ch * 4]);
            }
            CPCOMMIT();
        }

        // ---- QK^T ----
        float sc[2][8][4] = {};
        #pragma unroll
        for (int t8 = 0; t8 < 8; t8++) {
            int pc = t8 * 8 + 2 * c4;
            uint32_t a[2][4];
            #pragma unroll
            for (int mt = 0; mt < 2; mt++) {
                uint2 ua0 = *(const uint2*)&qs[(row_base + mt * 16) * QST + pc];
                uint2 ua1 = *(const uint2*)&qs[(row_base + mt * 16 + 8) * QST + pc];
                a[mt][0] = ua0.x; a[mt][1] = ua1.x; a[mt][2] = ua0.y; a[mt][3] = ua1.y;
            }
            #pragma unroll
            for (int nt = 0; nt < 8; nt++) {
                int n = nt * 8 + g;
                uint2 ub = *(const uint2*)&kb[n * KST + pc];
                uint32_t bb[2] = { ub.x, ub.y };
                mma8(sc[0][nt], a[0], bb);
                mma8(sc[1][nt], a[1], bb);
            }
        }

        // ---- causal mask ----
        if (kt >= 2 * qt) {
            #pragma unroll
            for (int mt = 0; mt < 2; mt++) {
                int rg0 = qt * 128 + row_base + mt * 16, rg1 = rg0 + 8;
                #pragma unroll
                for (int nt = 0; nt < 8; nt++) {
                    int cg = kt * 64 + nt * 8 + 2 * c4;
                    if (cg > rg0)     sc[mt][nt][0] = -1e30f;
                    if (cg + 1 > rg0) sc[mt][nt][1] = -1e30f;
                    if (cg > rg1)     sc[mt][nt][2] = -1e30f;
                    if (cg + 1 > rg1) sc[mt][nt][3] = -1e30f;
                }
            }
        }

        // ---- softmax numerator (log2 domain, no max subtraction) ----
        #pragma unroll
        for (int mt = 0; mt < 2; mt++) {
            #pragma unroll
            for (int nt = 0; nt < 8; nt++) {
                sc[mt][nt][0] = ex2(sc[mt][nt][0]); l[mt][0] += sc[mt][nt][0];
                sc[mt][nt][1] = ex2(sc[mt][nt][1]); l[mt][0] += sc[mt][nt][1];
                sc[mt][nt][2] = ex2(sc[mt][nt][2]); l[mt][1] += sc[mt][nt][2];
                sc[mt][nt][3] = ex2(sc[mt][nt][3]); l[mt][1] += sc[mt][nt][3];
            }
        }

        // ---- P @ V ----
        #pragma unroll
        for (int t = 0; t < 8; t++) {
            uint32_t a[2][4];
            #pragma unroll
            for (int mt = 0; mt < 2; mt++) {
                a[mt][0] = f2tf(sc[mt][t][0]);
                a[mt][1] = f2tf(sc[mt][t][2]);
                a[mt][2] = f2tf(sc[mt][t][1]);
                a[mt][3] = f2tf(sc[mt][t][3]);
            }
            int vrow = t * 4 + c4;
            #pragma unroll
            for (int nt = 0; nt < 8; nt++) {
                int dcol = nt * 8 + g;
                uint2 ub = *(const uint2*)&vb[vrow * VST + 2 * dcol];
                uint32_t bb[2] = { ub.x, ub.y };
                mma8(accO[0][nt], a[0], bb);
                mma8(accO[1][nt], a[1], bb);
            }
        }

        if (kt < ktmax) CPWAITALL();
        __syncthreads();
    }

    // ---- epilogue: reduce l, normalize, write tf32 ----
    #pragma unroll
    for (int mt = 0; mt < 2; mt++) {
        #pragma unroll
        for (int half = 0; half < 2; half++) {
            l[mt][half] += __shfl_xor_sync(0xffffffffu, l[mt][half], 1);
            l[mt][half] += __shfl_xor_sync(0xffffffffu, l[mt][half], 2);
        }
        float il0 = 1.f / l[mt][0], il1 = 1.f / l[mt][1];
        size_t ob0 = ((size_t)(b * Sl + qt * 128 + row_base + mt * 16) * Hn + h) * 64;
        size_t ob1 = ((size_t)(b * Sl + qt * 128 + row_base + mt * 16 + 8) * Hn + h) * 64;
        #pragma unroll
        for (int nt = 0; nt < 8; nt++) {
            int dcol = nt * 8 + 2 * c4;
            uint2 u0, u1;
            u0.x = f2tf(accO[mt][nt][0] * il0); u0.y = f2tf(accO[mt][nt][1] * il0);
            u1.x = f2tf(accO[mt][nt][2] * il1); u1.y = f2tf(accO[mt][nt][3] * il1);
            *(uint2*)&o2[ob0 + dcol] = u0;
            *(uint2*)&o2[ob1 + dcol] = u1;
        }
    }
}

// ---------------------------------------------------------------------------
// Chunked delta-rule memory scan (side stream). Output written as tf32.
// ---------------------------------------------------------------------------
__global__ __launch_bounds__(256)
void memscan_kernel(const float* __restrict__ z,
                    const float* __restrict__ M_init,
                    const float* __restrict__ w_eta, const float* __restrict__ b_eta,
                    const float* __restrict__ w_alpha, const float* __restrict__ b_alpha,
                    const float* __restrict__ w_gate, const float* __restrict__ b_gate,
                    uint32_t* __restrict__ mem_out) {
    __shared__ float Ms[64][65];
    __shared__ float chs[64][65];
    __shared__ float red2[16][64];
    __shared__ float se[64], sa[64], sg[64], nrm[64];
    __shared__ float kmean[64], vt[64], diffv[64];
    __shared__ float swe[64], swa[64], swg[64];
    __shared__ float redw[8];
    __shared__ float sc_eta, sc_alpha, sc_gate, sc_scale;

    int b = blockIdx.x;
    int tid = threadIdx.x;
    int tx = tid & 15, ty = tid >> 4;
    int lane = tid & 31, warp = tid >> 5;
    int tok = tid >> 2, part = tid & 3;
    float be = b_eta[0], ba = b_alpha[0], bg = b_gate[0];

    if (tid < 64) { swe[tid] = w_eta[tid]; swa[tid] = w_alpha[tid]; swg[tid] = w_gate[tid]; }
    #pragma unroll
    for (int i = 0; i < 16; i++) {
        int idx = tid + i * 256;
        Ms[idx >> 6][idx & 63] = M_init[idx];
    }
    __syncthreads();

    for (int c = 0; c < NCH; c++) {
        #pragma unroll
        for (int i = 0; i < 16; i++) {
            int idx = tid + i * 256;
            chs[idx >> 6][idx & 63] = z[((size_t)b * Sl + c * 64 + (idx >> 6)) * 64 + (idx & 63)];
        }
        __syncthreads();

        float o4[4][4] = {};
        #pragma unroll
        for (int d = 0; d < 64; d++) {
            float a0 = chs[ty*4+0][d], a1 = chs[ty*4+1][d];
            float a2 = chs[ty*4+2][d], a3 = chs[ty*4+3][d];
            float m0 = Ms[tx*4+0][d], m1 = Ms[tx*4+1][d];
            float m2 = Ms[tx*4+2][d], m3 = Ms[tx*4+3][d];
            o4[0][0] += a0*m0; o4[0][1] += a0*m1; o4[0][2] += a0*m2; o4[0][3] += a0*m3;
            o4[1][0] += a1*m0; o4[1][1] += a1*m1; o4[1][2] += a1*m2; o4[1][3] += a1*m3;
            o4[2][0] += a2*m0; o4[2][1] += a2*m1; o4[2][2] += a2*m2; o4[2][3] += a2*m3;
            o4[3][0] += a3*m0; o4[3][1] += a3*m1; o4[3][2] += a3*m2; o4[3][3] += a3*m3;
        }
        #pragma unroll
        for (int i = 0; i < 4; i++)
            #pragma unroll
            for (int j = 0; j < 4; j++)
                mem_out[((size_t)b * Sl + c * 64 + ty * 4 + i) * 64 + tx * 4 + j] = f2tf(o4[i][j]);
        #pragma unroll
        for (int j = 0; j < 4; j++)
            red2[ty][tx * 4 + j] = o4[0][j] + o4[1][j] + o4[2][j] + o4[3][j];
        __syncthreads();

        {
            float de = 0.f, da = 0.f, dg = 0.f, nn = 0.f;
            int d0 = part * 16;
            #pragma unroll
            for (int dd = 0; dd < 16; dd++) {
                float xv = chs[tok][d0 + dd];
                de = fmaf(xv, swe[d0 + dd], de);
                da = fmaf(xv, swa[d0 + dd], da);
                dg = fmaf(xv, swg[d0 + dd], dg);
                nn = fmaf(xv, xv, nn);
            }
            de += __shfl_xor_sync(0xffffffffu, de, 1); de += __shfl_xor_sync(0xffffffffu, de, 2);
            da += __shfl_xor_sync(0xffffffffu, da, 1); da += __shfl_xor_sync(0xffffffffu, da, 2);
            dg += __shfl_xor_sync(0xffffffffu, dg, 1); dg += __shfl_xor_sync(0xffffffffu, dg, 2);
            nn += __shfl_xor_sync(0xffffffffu, nn, 1); nn += __shfl_xor_sync(0xffffffffu, nn, 2);
            if (part == 0) {
                se[tok] = 0.2f / (1.f + __expf(-(de + be)));
                sa[tok] = 0.5f + 0.5f / (1.f + __expf(-(da + ba)));
                sg[tok] = 1.f / (1.f + __expf(-(dg + bg)));
                nrm[tok] = fmaxf(sqrtf(nn), 1e-6f);
            }
        }
        __syncthreads();

        {
            float s = 0.f, s2 = 0.f;
            #pragma unroll
            for (int t = 0; t < 16; t++) s += chs[part * 16 + t][tok] / nrm[part * 16 + t];
            #pragma unroll
            for (int yy = 0; yy < 4; yy++) s2 += red2[part * 4 + yy][tok];
            s  += __shfl_xor_sync(0xffffffffu, s, 1);  s  += __shfl_xor_sync(0xffffffffu, s, 2);
            s2 += __shfl_xor_sync(0xffffffffu, s2, 1); s2 += __shfl_xor_sync(0xffffffffu, s2, 2);
            if (part == 0) { kmean[tok] = s * (1.f / 64.f); vt[tok] = s2 * (1.f / 64.f); }
        }
        __syncthreads();

        if (tid < 32) {
            float e = se[tid] + se[tid + 32];
            float a = sa[tid] + sa[tid + 32];
            float gg = sg[tid] + sg[tid + 32];
            #pragma unroll
            for (int st = 16; st; st >>= 1) {
                e  += __shfl_xor_sync(0xffffffffu, e, st);
                a  += __shfl_xor_sync(0xffffffffu, a, st);
                gg += __shfl_xor_sync(0xffffffffu, gg, st);
            }
            if (tid == 0) {
                sc_eta = e * (1.f / 64.f);
                sc_alpha = a * (1.f / 64.f);
                sc_gate = gg * (1.f / 64.f);
            }
        }
        {
            float s = 0.f;
            int d0 = part * 16;
            #pragma unroll
            for (int dd = 0; dd < 16; dd++)
                s = fmaf(Ms[tok][d0 + dd], kmean[d0 + dd], s);
            s += __shfl_xor_sync(0xffffffffu, s, 1);
            s += __shfl_xor_sync(0xffffffffu, s, 2);
            if (part == 0) diffv[tok] = vt[tok] - s;
        }
        __syncthreads();

        float eg = sc_eta * sc_gate, al = sc_alpha;
        float ss2 = 0.f;
        #pragma unroll
        for (int i = 0; i < 16; i++) {
            int idx = tid + i * 256;
            int vv = idx >> 6, d = idx & 63;
            float mn = al * Ms[vv][d] + eg * diffv[vv] * kmean[d];
            Ms[vv][d] = mn;
            ss2 = fmaf(mn, mn, ss2);
        }
        #pragma unroll
        for (int st = 16; st; st >>= 1) ss2 += __shfl_xor_sync(0xffffffffu, ss2, st);
        if (lane == 0) redw[warp] = ss2;
        __syncthreads();
        if (tid == 0) {
            float fro = sqrtf(redw[0] + redw[1] + redw[2] + redw[3] +
                              redw[4] + redw[5] + redw[6] + redw[7]);
            sc_scale = fminf(1.f, 30.f / fmaxf(fro, 1e-6f));
        }
        __syncthreads();
        #pragma unroll
        for (int i = 0; i < 16; i++) {
            int idx = tid + i * 256;
            Ms[idx >> 6][idx & 63] *= sc_scale;
        }
        __syncthreads();
    }
}

// ---------------------------------------------------------------------------
extern "C" void kernel_launch(void* const* d_in, const int* in_sizes, int n_in,
                              void* d_out, int out_size) {
    const float* x       = (const float*)d_in[0];
    const float* Wq      = (const float*)d_in[1];
    const float* Wk      = (const float*)d_in[2];
    const float* Wv      = (const float*)d_in[3];
    const float* Wo      = (const float*)d_in[4];
    const float* Wmemin  = (const float*)d_in[5];
    const float* Wmemout = (const float*)d_in[6];
    const float* M_init  = (const float*)d_in[7];
    const float* w_eta   = (const float*)d_in[8];
    const float* b_eta   = (const float*)d_in[9];
    const float* w_alpha = (const float*)d_in[10];
    const float* b_alpha = (const float*)d_in[11];
    const float* w_gate  = (const float*)d_in[12];
    const float* b_gate  = (const float*)d_in[13];
    float* out = (float*)d_out;

    float *q, *k, *z;
    uint32_t *attn2, *mem2, *q2, *k2, *v2;
    uint32_t *x2, *wq2, *wk2, *wv2, *wz2, *wo2, *wmo2;
    cudaGetSymbolAddress((void**)&q, g_q);
    cudaGetSymbolAddress((void**)&k, g_k);
    cudaGetSymbolAddress((void**)&z, g_z);
    cudaGetSymbolAddress((void**)&attn2, g_attn2);
    cudaGetSymbolAddress((void**)&mem2, g_mem2);
    cudaGetSymbolAddress((void**)&q2, g_q2);
    cudaGetSymbolAddress((void**)&k2, g_k2);
    cudaGetSymbolAddress((void**)&v2, g_v2);
    cudaGetSymbolAddress((void**)&x2, g_x2);
    cudaGetSymbolAddress((void**)&wq2, g_wq2);
    cudaGetSymbolAddress((void**)&wk2, g_wk2);
    cudaGetSymbolAddress((void**)&wv2, g_wv2);
    cudaGetSymbolAddress((void**)&wz2, g_wz2);
    cudaGetSymbolAddress((void**)&wo2, g_wo2);
    cudaGetSymbolAddress((void**)&wmo2, g_wmo2);

    static cudaStream_t s2 = nullptr;
    static cudaEvent_t evZ = nullptr, evM = nullptr;
    static int inited = 0;
    if (!inited) {
        cudaStreamCreateWithFlags(&s2, cudaStreamNonBlocking);
        cudaEventCreateWithFlags(&evZ, cudaEventDisableTiming);
        cudaEventCreateWithFlags(&evM, cudaEventDisableTiming);
        cudaFuncSetAttribute(attn_kernel,
                             cudaFuncAttributeMaxDynamicSharedMemorySize, ATTN_BYTES);
        cudaFuncSetAttribute(proj_kernel,
                             cudaFuncAttributeMaxDynamicSharedMemorySize, GEMM_SM_BYTES);
        cudaFuncSetAttribute(dual_gemm_kernel,
                             cudaFuncAttributeMaxDynamicSharedMemorySize, GEMM_SM_BYTES);
        inited = 1;
    }

    // One-shot tf32 conversion of GEMM operands
    {
        int total4 = (Bsz*Sl*Dm + Dm*Hn*HDn + 2*Dm*HKn*HDn + Dm*DKn
                      + Hn*HDn*Dm + DVn*Dm) / 4;
        cvt_kernel<<<(total4 + 255) / 256, 256>>>(x, Wq, Wk, Wv, Wmemin, Wo, Wmemout,
                                                  x2, wq2, wk2, wv2, wz2, wo2, wmo2);
    }

    // Fused projections (q, k fp32; v tf32 sigma-paired; z fp32)
    proj_kernel<<<dim3(13, 32), 256, GEMM_SM_BYTES>>>(x2, wq2, wk2, wv2, wz2,
                                                      q, k, v2, z);

    // Fork serial memscan onto side stream (depends on z)
    cudaEventRecord(evZ, 0);
    cudaStreamWaitEvent(s2, evZ, 0);
    memscan_kernel<<<Bsz, 256, 0, s2>>>(z, M_init, w_eta, b_eta, w_alpha, b_alpha,
                                        w_gate, b_gate, mem2);
    cudaEventRecord(evM, s2);

    // RoPE + tf32 convert + permute (q scaled)
    {
        int total = Bsz * Sl * (Hn + HKn) * 32;
        rope_kernel<<<(total + 255) / 256, 256>>>(q, k, q2, k2);
    }

    // Attention (writes tf32)
    attn_kernel<<<dim3(Sl/128, Bsz*Hn), 128, ATTN_BYTES>>>(q2, k2, v2, attn2);

    // Join memscan, then fused output GEMM
    cudaStreamWaitEvent((cudaStream_t)0, evM, 0);
    dual_gemm_kernel<<<dim3(8, 32), 256, GEMM_SM_BYTES>>>(attn2, wo2, Hn*HDn,
                                                          mem2, wmo2, DVn, out, Dm);
}

// round 15
// speedup vs baseline: 1.3284x; 1.0087x over previous
#include <cuda_runtime.h>
#include <math.h>
#include <stdint.h>

#define Bsz 2
#define Sl  2048
#define Dm  1024
#define Hn  16
#define HKn 4
#define HDn 64
#define DKn 64
#define DVn 64
#define NCH 32
#define MS  (Bsz*Sl)

__device__ float    g_q[Bsz*Sl*Hn*HDn];
__device__ float    g_k[Bsz*Sl*HKn*HDn];
__device__ float    g_z[Bsz*Sl*DKn];
__device__ uint32_t g_attn2[Bsz*Sl*Hn*HDn];
__device__ uint32_t g_mem2[Bsz*Sl*DVn];
__device__ uint32_t g_q2[Bsz*Sl*Hn*HDn];
__device__ uint32_t g_k2[Bsz*Sl*HKn*HDn];
__device__ uint32_t g_v2[Bsz*HKn*(Sl/2)*128];
__device__ uint32_t g_x2[Bsz*Sl*Dm];
__device__ uint32_t g_wq2[Dm*Hn*HDn];
__device__ uint32_t g_wk2[Dm*HKn*HDn];
__device__ uint32_t g_wv2[Dm*HKn*HDn];
__device__ uint32_t g_wz2[Dm*DKn];
__device__ uint32_t g_wo2[Hn*HDn*Dm];
__device__ uint32_t g_wmo2[DVn*Dm];

__device__ __forceinline__ uint32_t f2tf(float x) {
    uint32_t u; asm("cvt.rna.tf32.f32 %0, %1;" : "=r"(u) : "f"(x)); return u;
}
__device__ __forceinline__ float ex2(float x) {
    float y; asm("ex2.approx.f32 %0, %1;" : "=f"(y) : "f"(x)); return y;
}
__device__ __forceinline__ int colperm(int d) {
    return (d & ~7) | ((d & 3) << 1) | ((d >> 2) & 1);
}
__device__ __forceinline__ unsigned su32(const void* p) {
    unsigned a;
    asm("{.reg .u64 t; cvta.to.shared.u64 t, %1; cvt.u32.u64 %0, t;}" : "=r"(a) : "l"(p));
    return a;
}
#define CP16(dst, src) asm volatile("cp.async.ca.shared.global [%0], [%1], 16;" :: "r"(dst), "l"(src))
#define CPCOMMIT()     asm volatile("cp.async.commit_group;")
#define CPWAITALL()    asm volatile("cp.async.wait_group 0;")

__device__ __forceinline__ void mma8(float d[4], const uint32_t a[4], const uint32_t b[2]) {
    asm volatile(
        "mma.sync.aligned.m16n8k8.row.col.f32.tf32.tf32.f32 "
        "{%0,%1,%2,%3}, {%4,%5,%6,%7}, {%8,%9}, {%0,%1,%2,%3};"
        : "+f"(d[0]), "+f"(d[1]), "+f"(d[2]), "+f"(d[3])
        : "r"(a[0]), "r"(a[1]), "r"(a[2]), "r"(a[3]), "r"(b[0]), "r"(b[1]));
}

// ---------------------------------------------------------------------------
// tf32 conversion kernels: A = critical path (x + proj weights), B = side.
// ---------------------------------------------------------------------------
__global__ void cvtA_kernel(const float* __restrict__ x,  const float* __restrict__ wq,
                            const float* __restrict__ wk, const float* __restrict__ wv,
                            const float* __restrict__ wz,
                            uint32_t* __restrict__ x2,  uint32_t* __restrict__ wq2,
                            uint32_t* __restrict__ wk2, uint32_t* __restrict__ wv2,
                            uint32_t* __restrict__ wz2) {
    const int S0 = Bsz*Sl*Dm/4;
    const int S1 = S0 + Dm*Hn*HDn/4;
    const int S2 = S1 + Dm*HKn*HDn/4;
    const int S3 = S2 + Dm*HKn*HDn/4;
    const int S4 = S3 + Dm*DKn/4;
    int idx = blockIdx.x * blockDim.x + threadIdx.x;
    if (idx >= S4) return;
    const float* src; uint32_t* dst; int off;
    if (idx < S0)      { src = x;  dst = x2;  off = idx; }
    else if (idx < S1) { src = wq; dst = wq2; off = idx - S0; }
    else if (idx < S2) { src = wk; dst = wk2; off = idx - S1; }
    else if (idx < S3) { src = wv; dst = wv2; off = idx - S2; }
    else               { src = wz; dst = wz2; off = idx - S3; }
    float4 t = *(const float4*)&src[off * 4];
    uint4 u;
    u.x = f2tf(t.x); u.y = f2tf(t.y); u.z = f2tf(t.z); u.w = f2tf(t.w);
    *(uint4*)&dst[off * 4] = u;
}

__global__ void cvtB_kernel(const float* __restrict__ wo, const float* __restrict__ wmo,
                            uint32_t* __restrict__ wo2, uint32_t* __restrict__ wmo2) {
    const int S0 = Hn*HDn*Dm/4;
    const int S1 = S0 + DVn*Dm/4;
    int idx = blockIdx.x * blockDim.x + threadIdx.x;
    if (idx >= S1) return;
    const float* src; uint32_t* dst; int off;
    if (idx < S0) { src = wo;  dst = wo2;  off = idx; }
    else          { src = wmo; dst = wmo2; off = idx - S0; }
    float4 t = *(const float4*)&src[off * 4];
    uint4 u;
    u.x = f2tf(t.x); u.y = f2tf(t.y); u.z = f2tf(t.z); u.w = f2tf(t.w);
    *(uint4*)&dst[off * 4] = u;
}

// ===========================================================================
// TF32 GEMM core v3 (unchanged from R14): BM=128, BN=128, BK=16, 256 thr.
// ===========================================================================
#define AXS 36
#define BXS 136
#define GEMM_SM_WORDS (2*128*AXS + 2*16*BXS)
#define GEMM_SM_BYTES (GEMM_SM_WORDS * 4)

__device__ __forceinline__ void g_issue(const uint32_t* __restrict__ A,
                                        const uint32_t* __restrict__ B,
                                        int K, int N, int row0, int col0, int k0,
                                        int tid, unsigned Asd, unsigned Bsd) {
    #pragma unroll
    for (int i = 0; i < 2; i++) {
        int vec = tid + i * 256;
        int m = vec >> 2, kq = vec & 3;
        CP16(Asd + (unsigned)((m * AXS + kq * 4) * 4),
             &A[(size_t)(row0 + m) * K + k0 + kq * 4]);
        int kk = vec >> 5, nq = vec & 31;
        int col = col0 + nq * 4;
        if (col < N)
            CP16(Bsd + (unsigned)((kk * BXS + nq * 4) * 4),
                 &B[(size_t)(k0 + kk) * N + col]);
    }
}

__device__ __forceinline__ void g_mma(const uint32_t* As, const uint32_t* Bs,
                                      int lane, int wm, int wn, float d[2][8][4]) {
    #pragma unroll
    for (int ks = 0; ks < 16; ks += 8) {
        int kc = ks + (lane & 3);
        uint32_t a[2][4], b[8][2];
        #pragma unroll
        for (int mt = 0; mt < 2; mt++) {
            int r = wm * 32 + mt * 16 + (lane >> 2);
            a[mt][0] = As[r * AXS + kc];
            a[mt][1] = As[(r + 8) * AXS + kc];
            a[mt][2] = As[r * AXS + kc + 4];
            a[mt][3] = As[(r + 8) * AXS + kc + 4];
        }
        #pragma unroll
        for (int nt = 0; nt < 8; nt++) {
            int n = wn * 64 + nt * 8 + (lane >> 2);
            b[nt][0] = Bs[kc * BXS + n];
            b[nt][1] = Bs[(kc + 4) * BXS + n];
        }
        #pragma unroll
        for (int mt = 0; mt < 2; mt++)
            #pragma unroll
            for (int nt = 0; nt < 8; nt++)
                mma8(d[mt][nt], a[mt], b[nt]);
    }
}

__device__ __forceinline__ void g_epilogue(float d[2][8][4], float* __restrict__ C,
                                           int N, int row0, int col0,
                                           int lane, int wm, int wn) {
    #pragma unroll
    for (int mt = 0; mt < 2; mt++) {
        #pragma unroll
        for (int nt = 0; nt < 8; nt++) {
            int r = row0 + wm * 32 + mt * 16 + (lane >> 2);
            int cc = col0 + wn * 64 + nt * 8 + 2 * (lane & 3);
            if (cc < N) {
                *(float2*)&C[(size_t)r * N + cc]       = make_float2(d[mt][nt][0], d[mt][nt][1]);
                *(float2*)&C[(size_t)(r + 8) * N + cc] = make_float2(d[mt][nt][2], d[mt][nt][3]);
            }
        }
    }
}

__device__ __forceinline__ void v2store(uint32_t* __restrict__ v2, int r, int cc, float val) {
    int s = r & (Sl - 1), b = r >> 11;
    int kh = cc >> 6, d = cc & 63;
    size_t idx = ((size_t)(b * HKn + kh) * (Sl / 2) + (s >> 3) * 4 + ((s >> 1) & 3)) * 128
               + 2 * d + (s & 1);
    v2[idx] = f2tf(val);
}

// ---------------------------------------------------------------------------
// Fused projection GEMM (tf32 inputs): grid=(13,32), block=256, dyn smem.
// ---------------------------------------------------------------------------
__global__ __launch_bounds__(256, 2)
void proj_kernel(const uint32_t* __restrict__ x,
                 const uint32_t* __restrict__ Wq, const uint32_t* __restrict__ Wk,
                 const uint32_t* __restrict__ Wv, const uint32_t* __restrict__ Wz,
                 float* __restrict__ q, float* __restrict__ kout,
                 uint32_t* __restrict__ v2, float* __restrict__ z) {
    extern __shared__ uint32_t gsm[];
    uint32_t* As = gsm;
    uint32_t* Bs = gsm + 2 * 128 * AXS;
    int tid = threadIdx.x;
    int lane = tid & 31, warp = tid >> 5;
    int wm = warp >> 1, wn = warp & 1;
    int ct = blockIdx.x;
    int row0 = blockIdx.y * 128;
    const uint32_t* B; float* C; int N, col0; bool isV = false;
    if (ct < 8)       { B = Wq; C = q;    N = 1024; col0 = ct * 128; }
    else if (ct < 10) { B = Wk; C = kout; N = 256;  col0 = (ct - 8) * 128; }
    else if (ct < 12) { B = Wv; C = nullptr; N = 256; col0 = (ct - 10) * 128; isV = true; }
    else              { B = Wz; C = z;    N = 64;   col0 = 0; }

    float d[2][8][4] = {};
    unsigned Asd = su32(As), Bsd = su32(Bs);
    g_issue(x, B, 1024, N, row0, col0, 0, tid, Asd, Bsd);
    CPCOMMIT(); CPWAITALL();
    __syncthreads();
    for (int k0 = 0; k0 < 1024; k0 += 16) {
        int cur = (k0 >> 4) & 1;
        if (k0 + 16 < 1024) {
            g_issue(x, B, 1024, N, row0, col0, k0 + 16, tid,
                    Asd + (unsigned)((cur ^ 1) * 128 * AXS * 4),
                    Bsd + (unsigned)((cur ^ 1) * 16 * BXS * 4));
            CPCOMMIT();
        }
        g_mma(As + cur * 128 * AXS, Bs + cur * 16 * BXS, lane, wm, wn, d);
        if (k0 + 16 < 1024) CPWAITALL();
        __syncthreads();
    }
    if (!isV) {
        g_epilogue(d, C, N, row0, col0, lane, wm, wn);
    } else {
        #pragma unroll
        for (int mt = 0; mt < 2; mt++) {
            #pragma unroll
            for (int nt = 0; nt < 8; nt++) {
                int r = row0 + wm * 32 + mt * 16 + (lane >> 2);
                int cc = col0 + wn * 64 + nt * 8 + 2 * (lane & 3);
                v2store(v2, r,     cc,     d[mt][nt][0]);
                v2store(v2, r,     cc + 1, d[mt][nt][1]);
                v2store(v2, r + 8, cc,     d[mt][nt][2]);
                v2store(v2, r + 8, cc + 1, d[mt][nt][3]);
            }
        }
    }
}

// ---------------------------------------------------------------------------
// Dual GEMM (tf32 inputs): grid=(8,32), block=256.
// ---------------------------------------------------------------------------
__global__ __launch_bounds__(256, 2)
void dual_gemm_kernel(const uint32_t* __restrict__ A1, const uint32_t* __restrict__ B1, int K1,
                      const uint32_t* __restrict__ A2, const uint32_t* __restrict__ B2, int K2,
                      float* __restrict__ C, int N) {
    extern __shared__ uint32_t gsm[];
    uint32_t* As = gsm;
    uint32_t* Bs = gsm + 2 * 128 * AXS;
    int tid = threadIdx.x;
    int lane = tid & 31, warp = tid >> 5;
    int wm = warp >> 1, wn = warp & 1;
    int row0 = blockIdx.y * 128, col0 = blockIdx.x * 128;
    float d[2][8][4] = {};
    unsigned Asd = su32(As), Bsd = su32(Bs);
    #pragma unroll
    for (int ph = 0; ph < 2; ph++) {
        const uint32_t* A = ph ? A2 : A1;
        const uint32_t* B = ph ? B2 : B1;
        int K = ph ? K2 : K1;
        g_issue(A, B, K, N, row0, col0, 0, tid, Asd, Bsd);
        CPCOMMIT(); CPWAITALL();
        __syncthreads();
        for (int k0 = 0; k0 < K; k0 += 16) {
            int cur = (k0 >> 4) & 1;
            if (k0 + 16 < K) {
                g_issue(A, B, K, N, row0, col0, k0 + 16, tid,
                        Asd + (unsigned)((cur ^ 1) * 128 * AXS * 4),
                        Bsd + (unsigned)((cur ^ 1) * 16 * BXS * 4));
                CPCOMMIT();
            }
            g_mma(As + cur * 128 * AXS, Bs + cur * 16 * BXS, lane, wm, wn, d);
            if (k0 + 16 < K) CPWAITALL();
            __syncthreads();
        }
    }
    g_epilogue(d, C, N, row0, col0, lane, wm, wn);
}

// ---------------------------------------------------------------------------
// RoPE: inv-freq table computed once per block in smem (kills per-thread powf).
// ---------------------------------------------------------------------------
#define QSCALE 0.18033688f   // 0.125 * log2(e)

__global__ void rope_kernel(const float* __restrict__ qp, const float* __restrict__ kp,
                            uint32_t* __restrict__ q2, uint32_t* __restrict__ k2) {
    __shared__ float sinv[32];
    if (threadIdx.x < 32)
        sinv[threadIdx.x] = powf(500000.0f, -(float)(2 * threadIdx.x) / 64.0f);
    __syncthreads();
    int idx = blockIdx.x * blockDim.x + threadIdx.x;
    const int qtot = Bsz * Sl * Hn * 32;
    const int ktot = Bsz * Sl * HKn * 32;
    const float* src; uint32_t* dst; int nheads; bool isq;
    if (idx < qtot) { src = qp; dst = q2; nheads = Hn; isq = true; }
    else { idx -= qtot; if (idx >= ktot) return; src = kp; dst = k2; nheads = HKn; isq = false; }
    int j = idx & 31;
    int h = (idx >> 5) % nheads;
    int s = ((idx >> 5) / nheads) % Sl;
    int b = idx / (32 * nheads * Sl);
    float ang = (float)s * sinv[j];
    float c, sn;
    __sincosf(ang, &sn, &c);
    size_t base = ((size_t)(b * Sl + s) * nheads + h) * 64;
    float u1 = src[base + j], u2 = src[base + j + 32];
    float r1 = u1 * c - u2 * sn;
    float r2 = u2 * c + u1 * sn;
    if (isq) { r1 *= QSCALE; r2 *= QSCALE; }
    dst[base + colperm(j)]      = f2tf(r1);
    dst[base + colperm(j + 32)] = f2tf(r2);
}

// ---------------------------------------------------------------------------
// TF32 flash attention v6: P fed as raw fp32 bits (tf32 truncation); l via
// ones-column mma (constant B fragment) — no FADD chain, no epilogue shfl.
// ---------------------------------------------------------------------------
#define QST 72
#define KST 72
#define VST 144
#define ATTN_WORDS (128*QST + 2*64*KST + 2*32*VST)
#define ATTN_BYTES (ATTN_WORDS * 4)
#define TF_ONE 0x3F800000u

__global__ __launch_bounds__(128, 2)
void attn_kernel(const uint32_t* __restrict__ q2, const uint32_t* __restrict__ k2,
                 const uint32_t* __restrict__ v2, uint32_t* __restrict__ o2) {
    extern __shared__ uint32_t smu[];
    uint32_t* qs = smu;
    uint32_t* ks = qs + 128 * QST;
    uint32_t* vs = ks + 2 * 64 * KST;

    int qt = (int)gridDim.x - 1 - (int)blockIdx.x;
    int bh = blockIdx.y;
    int b = bh >> 4, h = bh & 15, kh = h >> 2;
    int tid = threadIdx.x;
    int lane = tid & 31, w = tid >> 5;
    int g = lane >> 2, c4 = lane & 3;
    int row_base = w * 32 + g;

    size_t qbase = ((size_t)(b * Sl + qt * 128) * Hn + h) * 64;
    size_t kvbase = ((size_t)(b * Sl) * HKn + kh) * 64;
    size_t v2base0 = (size_t)(b * HKn + kh) * (Sl / 2) * 128;
    int ktmax = 2 * qt + 1;

    {
        unsigned qd = su32(qs);
        #pragma unroll
        for (int i = 0; i < 16; i++) {
            int vec = tid + i * 128;
            int r = vec >> 4, ch = vec & 15;
            CP16(qd + (unsigned)((r * QST + ch * 4) * 4),
                 &q2[qbase + (size_t)r * Hn * 64 + ch * 4]);
        }
        unsigned kd = su32(ks), vd = su32(vs);
        #pragma unroll
        for (int i = 0; i < 8; i++) {
            int vec = tid + i * 128;
            int c = vec >> 4, dq = vec & 15;
            CP16(kd + (unsigned)((c * KST + dq * 4) * 4),
                 &k2[kvbase + (size_t)c * HKn * 64 + dq * 4]);
            int row = vec >> 5, ch = vec & 31;
            CP16(vd + (unsigned)((row * VST + ch * 4) * 4),
                 &v2[v2base0 + (size_t)row * 128 + ch * 4]);
        }
        CPCOMMIT();
    }

    float accL[2][4] = {};     // l via ones-mma; [0]==[1] row g, [2]==[3] row g+8
    float accO[2][8][4] = {};
    const uint32_t bones[2] = { TF_ONE, TF_ONE };
    CPWAITALL();
    __syncthreads();

    for (int kt = 0; kt <= ktmax; kt++) {
        const uint32_t* kb = ks + (kt & 1) * 64 * KST;
        const uint32_t* vb = vs + (kt & 1) * 32 * VST;

        if (kt < ktmax) {
            unsigned kd = su32(ks + ((kt + 1) & 1) * 64 * KST);
            unsigned vd = su32(vs + ((kt + 1) & 1) * 32 * VST);
            size_t kbase = kvbase + (size_t)(kt + 1) * 64 * HKn * 64;
            size_t vbase = v2base0 + (size_t)(kt + 1) * 32 * 128;
            #pragma unroll
            for (int i = 0; i < 8; i++) {
                int vec = tid + i * 128;
                int c = vec >> 4, dq = vec & 15;
                CP16(kd + (unsigned)((c * KST + dq * 4) * 4),
                     &k2[kbase + (size_t)c * HKn * 64 + dq * 4]);
                int row = vec >> 5, ch = vec & 31;
                CP16(vd + (unsigned)((row * VST + ch * 4) * 4),
                     &v2[vbase + (size_t)row * 128 + ch * 4]);
            }
            CPCOMMIT();
        }

        // ---- QK^T ----
        float sc[2][8][4] = {};
        #pragma unroll
        for (int t8 = 0; t8 < 8; t8++) {
            int pc = t8 * 8 + 2 * c4;
            uint32_t a[2][4];
            #pragma unroll
            for (int mt = 0; mt < 2; mt++) {
                uint2 ua0 = *(const uint2*)&qs[(row_base + mt * 16) * QST + pc];
                uint2 ua1 = *(const uint2*)&qs[(row_base + mt * 16 + 8) * QST + pc];
                a[mt][0] = ua0.x; a[mt][1] = ua1.x; a[mt][2] = ua0.y; a[mt][3] = ua1.y;
            }
            #pragma unroll
            for (int nt = 0; nt < 8; nt++) {
                int n = nt * 8 + g;
                uint2 ub = *(const uint2*)&kb[n * KST + pc];
                uint32_t bb[2] = { ub.x, ub.y };
                mma8(sc[0][nt], a[0], bb);
                mma8(sc[1][nt], a[1], bb);
            }
        }

        // ---- causal mask ----
        if (kt >= 2 * qt) {
            #pragma unroll
            for (int mt = 0; mt < 2; mt++) {
                int rg0 = qt * 128 + row_base + mt * 16, rg1 = rg0 + 8;
                #pragma unroll
                for (int nt = 0; nt < 8; nt++) {
                    int cg = kt * 64 + nt * 8 + 2 * c4;
                    if (cg > rg0)     sc[mt][nt][0] = -1e30f;
                    if (cg + 1 > rg0) sc[mt][nt][1] = -1e30f;
                    if (cg > rg1)     sc[mt][nt][2] = -1e30f;
                    if (cg + 1 > rg1) sc[mt][nt][3] = -1e30f;
                }
            }
        }

        // ---- softmax numerator (log2 domain, no max, no sum chain) ----
        #pragma unroll
        for (int mt = 0; mt < 2; mt++)
            #pragma unroll
            for (int nt = 0; nt < 8; nt++) {
                sc[mt][nt][0] = ex2(sc[mt][nt][0]);
                sc[mt][nt][1] = ex2(sc[mt][nt][1]);
                sc[mt][nt][2] = ex2(sc[mt][nt][2]);
                sc[mt][nt][3] = ex2(sc[mt][nt][3]);
            }

        // ---- P @ V + l via ones-mma; P fed as raw fp32 bits (tf32 trunc) ----
        #pragma unroll
        for (int t = 0; t < 8; t++) {
            uint32_t a[2][4];
            #pragma unroll
            for (int mt = 0; mt < 2; mt++) {
                a[mt][0] = __float_as_uint(sc[mt][t][0]);
                a[mt][1] = __float_as_uint(sc[mt][t][2]);
                a[mt][2] = __float_as_uint(sc[mt][t][1]);
                a[mt][3] = __float_as_uint(sc[mt][t][3]);
            }
            int vrow = t * 4 + c4;
            #pragma unroll
            for (int nt = 0; nt < 8; nt++) {
                int dcol = nt * 8 + g;
                uint2 ub = *(const uint2*)&vb[vrow * VST + 2 * dcol];
                uint32_t bb[2] = { ub.x, ub.y };
                mma8(accO[0][nt], a[0], bb);
                mma8(accO[1][nt], a[1], bb);
            }
            mma8(accL[0], a[0], bones);
            mma8(accL[1], a[1], bones);
        }

        if (kt < ktmax) CPWAITALL();
        __syncthreads();
    }

    // ---- epilogue: l already fully reduced per row in accL ----
    #pragma unroll
    for (int mt = 0; mt < 2; mt++) {
        float il0 = 1.f / accL[mt][0];
        float il1 = 1.f / accL[mt][2];
        size_t ob0 = ((size_t)(b * Sl + qt * 128 + row_base + mt * 16) * Hn + h) * 64;
        size_t ob1 = ((size_t)(b * Sl + qt * 128 + row_base + mt * 16 + 8) * Hn + h) * 64;
        #pragma unroll
        for (int nt = 0; nt < 8; nt++) {
            int dcol = nt * 8 + 2 * c4;
            uint2 u0, u1;
            u0.x = f2tf(accO[mt][nt][0] * il0); u0.y = f2tf(accO[mt][nt][1] * il0);
            u1.x = f2tf(accO[mt][nt][2] * il1); u1.y = f2tf(accO[mt][nt][3] * il1);
            *(uint2*)&o2[ob0 + dcol] = u0;
            *(uint2*)&o2[ob1 + dcol] = u1;
        }
    }
}

// ---------------------------------------------------------------------------
// Chunked delta-rule memory scan (side stream). Output written as tf32.
// ---------------------------------------------------------------------------
__global__ __launch_bounds__(256)
void memscan_kernel(const float* __restrict__ z,
                    const float* __restrict__ M_init,
                    const float* __restrict__ w_eta, const float* __restrict__ b_eta,
                    const float* __restrict__ w_alpha, const float* __restrict__ b_alpha,
                    const float* __restrict__ w_gate, const float* __restrict__ b_gate,
                    uint32_t* __restrict__ mem_out) {
    __shared__ float Ms[64][65];
    __shared__ float chs[64][65];
    __shared__ float red2[16][64];
    __shared__ float se[64], sa[64], sg[64], nrm[64];
    __shared__ float kmean[64], vt[64], diffv[64];
    __shared__ float swe[64], swa[64], swg[64];
    __shared__ float redw[8];
    __shared__ float sc_eta, sc_alpha, sc_gate, sc_scale;

    int b = blockIdx.x;
    int tid = threadIdx.x;
    int tx = tid & 15, ty = tid >> 4;
    int lane = tid & 31, warp = tid >> 5;
    int tok = tid >> 2, part = tid & 3;
    float be = b_eta[0], ba = b_alpha[0], bg = b_gate[0];

    if (tid < 64) { swe[tid] = w_eta[tid]; swa[tid] = w_alpha[tid]; swg[tid] = w_gate[tid]; }
    #pragma unroll
    for (int i = 0; i < 16; i++) {
        int idx = tid + i * 256;
        Ms[idx >> 6][idx & 63] = M_init[idx];
    }
    __syncthreads();

    for (int c = 0; c < NCH; c++) {
        #pragma unroll
        for (int i = 0; i < 16; i++) {
            int idx = tid + i * 256;
            chs[idx >> 6][idx & 63] = z[((size_t)b * Sl + c * 64 + (idx >> 6)) * 64 + (idx & 63)];
        }
        __syncthreads();

        float o4[4][4] = {};
        #pragma unroll
        for (int d = 0; d < 64; d++) {
            float a0 = chs[ty*4+0][d], a1 = chs[ty*4+1][d];
            float a2 = chs[ty*4+2][d], a3 = chs[ty*4+3][d];
            float m0 = Ms[tx*4+0][d], m1 = Ms[tx*4+1][d];
            float m2 = Ms[tx*4+2][d], m3 = Ms[tx*4+3][d];
            o4[0][0] += a0*m0; o4[0][1] += a0*m1; o4[0][2] += a0*m2; o4[0][3] += a0*m3;
            o4[1][0] += a1*m0; o4[1][1] += a1*m1; o4[1][2] += a1*m2; o4[1][3] += a1*m3;
            o4[2][0] += a2*m0; o4[2][1] += a2*m1; o4[2][2] += a2*m2; o4[2][3] += a2*m3;
            o4[3][0] += a3*m0; o4[3][1] += a3*m1; o4[3][2] += a3*m2; o4[3][3] += a3*m3;
        }
        #pragma unroll
        for (int i = 0; i < 4; i++)
            #pragma unroll
            for (int j = 0; j < 4; j++)
                mem_out[((size_t)b * Sl + c * 64 + ty * 4 + i) * 64 + tx * 4 + j] = f2tf(o4[i][j]);
        #pragma unroll
        for (int j = 0; j < 4; j++)
            red2[ty][tx * 4 + j] = o4[0][j] + o4[1][j] + o4[2][j] + o4[3][j];
        __syncthreads();

        {
            float de = 0.f, da = 0.f, dg = 0.f, nn = 0.f;
            int d0 = part * 16;
            #pragma unroll
            for (int dd = 0; dd < 16; dd++) {
                float xv = chs[tok][d0 + dd];
                de = fmaf(xv, swe[d0 + dd], de);
                da = fmaf(xv, swa[d0 + dd], da);
                dg = fmaf(xv, swg[d0 + dd], dg);
                nn = fmaf(xv, xv, nn);
            }
            de += __shfl_xor_sync(0xffffffffu, de, 1); de += __shfl_xor_sync(0xffffffffu, de, 2);
            da += __shfl_xor_sync(0xffffffffu, da, 1); da += __shfl_xor_sync(0xffffffffu, da, 2);
            dg += __shfl_xor_sync(0xffffffffu, dg, 1); dg += __shfl_xor_sync(0xffffffffu, dg, 2);
            nn += __shfl_xor_sync(0xffffffffu, nn, 1); nn += __shfl_xor_sync(0xffffffffu, nn, 2);
            if (part == 0) {
                se[tok] = 0.2f / (1.f + __expf(-(de + be)));
                sa[tok] = 0.5f + 0.5f / (1.f + __expf(-(da + ba)));
                sg[tok] = 1.f / (1.f + __expf(-(dg + bg)));
                nrm[tok] = fmaxf(sqrtf(nn), 1e-6f);
            }
        }
        __syncthreads();

        {
            float s = 0.f, s2 = 0.f;
            #pragma unroll
            for (int t = 0; t < 16; t++) s += chs[part * 16 + t][tok] / nrm[part * 16 + t];
            #pragma unroll
            for (int yy = 0; yy < 4; yy++) s2 += red2[part * 4 + yy][tok];
            s  += __shfl_xor_sync(0xffffffffu, s, 1);  s  += __shfl_xor_sync(0xffffffffu, s, 2);
            s2 += __shfl_xor_sync(0xffffffffu, s2, 1); s2 += __shfl_xor_sync(0xffffffffu, s2, 2);
            if (part == 0) { kmean[tok] = s * (1.f / 64.f); vt[tok] = s2 * (1.f / 64.f); }
        }
        __syncthreads();

        if (tid < 32) {
            float e = se[tid] + se[tid + 32];
            float a = sa[tid] + sa[tid + 32];
            float gg = sg[tid] + sg[tid + 32];
            #pragma unroll
            for (int st = 16; st; st >>= 1) {
                e  += __shfl_xor_sync(0xffffffffu, e, st);
                a  += __shfl_xor_sync(0xffffffffu, a, st);
                gg += __shfl_xor_sync(0xffffffffu, gg, st);
            }
            if (tid == 0) {
                sc_eta = e * (1.f / 64.f);
                sc_alpha = a * (1.f / 64.f);
                sc_gate = gg * (1.f / 64.f);
            }
        }
        {
            float s = 0.f;
            int d0 = part * 16;
            #pragma unroll
            for (int dd = 0; dd < 16; dd++)
                s = fmaf(Ms[tok][d0 + dd], kmean[d0 + dd], s);
            s += __shfl_xor_sync(0xffffffffu, s, 1);
            s += __shfl_xor_sync(0xffffffffu, s, 2);
            if (part == 0) diffv[tok] = vt[tok] - s;
        }
        __syncthreads();

        float eg = sc_eta * sc_gate, al = sc_alpha;
        float ss2 = 0.f;
        #pragma unroll
        for (int i = 0; i < 16; i++) {
            int idx = tid + i * 256;
            int vv = idx >> 6, d = idx & 63;
            float mn = al * Ms[vv][d] + eg * diffv[vv] * kmean[d];
            Ms[vv][d] = mn;
            ss2 = fmaf(mn, mn, ss2);
        }
        #pragma unroll
        for (int st = 16; st; st >>= 1) ss2 += __shfl_xor_sync(0xffffffffu, ss2, st);
        if (lane == 0) redw[warp] = ss2;
        __syncthreads();
        if (tid == 0) {
            float fro = sqrtf(redw[0] + redw[1] + redw[2] + redw[3] +
                              redw[4] + redw[5] + redw[6] + redw[7]);
            sc_scale = fminf(1.f, 30.f / fmaxf(fro, 1e-6f));
        }
        __syncthreads();
        #pragma unroll
        for (int i = 0; i < 16; i++) {
            int idx = tid + i * 256;
            Ms[idx >> 6][idx & 63] *= sc_scale;
        }
        __syncthreads();
    }
}

// ---------------------------------------------------------------------------
extern "C" void kernel_launch(void* const* d_in, const int* in_sizes, int n_in,
                              void* d_out, int out_size) {
    const float* x       = (const float*)d_in[0];
    const float* Wq      = (const float*)d_in[1];
    const float* Wk      = (const float*)d_in[2];
    const float* Wv      = (const float*)d_in[3];
    const float* Wo      = (const float*)d_in[4];
    const float* Wmemin  = (const float*)d_in[5];
    const float* Wmemout = (const float*)d_in[6];
    const float* M_init  = (const float*)d_in[7];
    const float* w_eta   = (const float*)d_in[8];
    const float* b_eta   = (const float*)d_in[9];
    const float* w_alpha = (const float*)d_in[10];
    const float* b_alpha = (const float*)d_in[11];
    const float* w_gate  = (const float*)d_in[12];
    const float* b_gate  = (const float*)d_in[13];
    float* out = (float*)d_out;

    float *q, *k, *z;
    uint32_t *attn2, *mem2, *q2, *k2, *v2;
    uint32_t *x2, *wq2, *wk2, *wv2, *wz2, *wo2, *wmo2;
    cudaGetSymbolAddress((void**)&q, g_q);
    cudaGetSymbolAddress((void**)&k, g_k);
    cudaGetSymbolAddress((void**)&z, g_z);
    cudaGetSymbolAddress((void**)&attn2, g_attn2);
    cudaGetSymbolAddress((void**)&mem2, g_mem2);
    cudaGetSymbolAddress((void**)&q2, g_q2);
    cudaGetSymbolAddress((void**)&k2, g_k2);
    cudaGetSymbolAddress((void**)&v2, g_v2);
    cudaGetSymbolAddress((void**)&x2, g_x2);
    cudaGetSymbolAddress((void**)&wq2, g_wq2);
    cudaGetSymbolAddress((void**)&wk2, g_wk2);
    cudaGetSymbolAddress((void**)&wv2, g_wv2);
    cudaGetSymbolAddress((void**)&wz2, g_wz2);
    cudaGetSymbolAddress((void**)&wo2, g_wo2);
    cudaGetSymbolAddress((void**)&wmo2, g_wmo2);

    static cudaStream_t s2 = nullptr;
    static cudaEvent_t evZ = nullptr, evM = nullptr;
    static int inited = 0;
    if (!inited) {
        cudaStreamCreateWithFlags(&s2, cudaStreamNonBlocking);
        cudaEventCreateWithFlags(&evZ, cudaEventDisableTiming);
        cudaEventCreateWithFlags(&evM, cudaEventDisableTiming);
        cudaFuncSetAttribute(attn_kernel,
                             cudaFuncAttributeMaxDynamicSharedMemorySize, ATTN_BYTES);
        cudaFuncSetAttribute(proj_kernel,
                             cudaFuncAttributeMaxDynamicSharedMemorySize, GEMM_SM_BYTES);
        cudaFuncSetAttribute(dual_gemm_kernel,
                             cudaFuncAttributeMaxDynamicSharedMemorySize, GEMM_SM_BYTES);
        inited = 1;
    }

    // Side stream: convert output-GEMM weights (off critical path).
    {
        int total4 = (Hn*HDn*Dm + DVn*Dm) / 4;
        cvtB_kernel<<<(total4 + 255) / 256, 256, 0, s2>>>(Wo, Wmemout, wo2, wmo2);
    }
    // Critical path: convert x + projection weights.
    {
        int total4 = (Bsz*Sl*Dm + Dm*Hn*HDn + 2*Dm*HKn*HDn + Dm*DKn) / 4;
        cvtA_kernel<<<(total4 + 255) / 256, 256>>>(x, Wq, Wk, Wv, Wmemin,
                                                   x2, wq2, wk2, wv2, wz2);
    }

    // Fused projections
    proj_kernel<<<dim3(13, 32), 256, GEMM_SM_BYTES>>>(x2, wq2, wk2, wv2, wz2,
                                                      q, k, v2, z);

    // Fork serial memscan onto side stream (depends on z; also after cvtB on s2)
    cudaEventRecord(evZ, 0);
    cudaStreamWaitEvent(s2, evZ, 0);
    memscan_kernel<<<Bsz, 256, 0, s2>>>(z, M_init, w_eta, b_eta, w_alpha, b_alpha,
                                        w_gate, b_gate, mem2);
    cudaEventRecord(evM, s2);

    // RoPE + tf32 convert + permute
    {
        int total = Bsz * Sl * (Hn + HKn) * 32;
        rope_kernel<<<(total + 255) / 256, 256>>>(q, k, q2, k2);
    }

    // Attention
    attn_kernel<<<dim3(Sl/128, Bsz*Hn), 128, ATTN_BYTES>>>(q2, k2, v2, attn2);

    // Join memscan (and cvtB), then fused output GEMM
    cudaStreamWaitEvent((cudaStream_t)0, evM, 0);
    dual_gemm_kernel<<<dim3(8, 32), 256, GEMM_SM_BYTES>>>(attn2, wo2, Hn*HDn,
                                                          mem2, wmo2, DVn, out, Dm);
}